// round 9
// baseline (speedup 1.0000x reference)
#include <cuda_runtime.h>
#include <cuda_bf16.h>
#include <cstdint>

using bf16 = __nv_bfloat16;

// Problem constants
#define BSZ 4
#define LSEQ 2048
#define DDIM 512
#define EDIM 1024
#define NST 16
#define RRANK 32
#define NTOK (BSZ * LSEQ)          // 8192

// ---------------- scratch (device globals) ----------------
__device__ bf16  g_xzb[NTOK * 2 * EDIM];
__device__ float g_dtT[NTOK * EDIM];
__device__ float g_xsT[NTOK * EDIM];
__device__ bf16  g_zT [NTOK * EDIM];
__device__ bf16  g_nrmb[NTOK * DDIM];
__device__ bf16  g_xsb [NTOK * EDIM];
__device__ bf16  g_dblb[NTOK * 64];
__device__ bf16  g_bcb [NTOK * 32];
__device__ bf16  g_yb  [NTOK * EDIM];
__device__ bf16  g_winb [DDIM * 2 * EDIM];
__device__ bf16  g_wxb  [EDIM * 64];
__device__ bf16  g_wdtb [RRANK * EDIM];
__device__ bf16  g_woutb[EDIM * DDIM];

// ---------------- PTX helpers ----------------
__device__ __forceinline__ uint32_t smem_u32(const void* p) {
    return (uint32_t)__cvta_generic_to_shared(p);
}
__device__ __forceinline__ void cp_async16(void* s, const void* g) {
    asm volatile("cp.async.cg.shared.global [%0], [%1], 16;\n"
                 :: "r"(smem_u32(s)), "l"(g));
}
__device__ __forceinline__ void cp_commit() { asm volatile("cp.async.commit_group;\n"); }
template <int N> __device__ __forceinline__ void cp_wait() {
    asm volatile("cp.async.wait_group %0;\n" :: "n"(N));
}
__device__ __forceinline__ void ldsm_x4(uint32_t& r0, uint32_t& r1, uint32_t& r2, uint32_t& r3,
                                        uint32_t a) {
    asm volatile("ldmatrix.sync.aligned.m8n8.x4.shared.b16 {%0,%1,%2,%3}, [%4];\n"
                 : "=r"(r0), "=r"(r1), "=r"(r2), "=r"(r3) : "r"(a));
}
__device__ __forceinline__ void ldsm_x4_t(uint32_t& r0, uint32_t& r1, uint32_t& r2, uint32_t& r3,
                                          uint32_t a) {
    asm volatile("ldmatrix.sync.aligned.m8n8.x4.trans.shared.b16 {%0,%1,%2,%3}, [%4];\n"
                 : "=r"(r0), "=r"(r1), "=r"(r2), "=r"(r3) : "r"(a));
}
__device__ __forceinline__ void mma_bf16(float& d0, float& d1, float& d2, float& d3,
                                         uint32_t a0, uint32_t a1, uint32_t a2, uint32_t a3,
                                         uint32_t b0, uint32_t b1) {
    asm volatile("mma.sync.aligned.m16n8k16.row.col.f32.bf16.bf16.f32 "
                 "{%0,%1,%2,%3}, {%4,%5,%6,%7}, {%8,%9}, {%0,%1,%2,%3};\n"
                 : "+f"(d0), "+f"(d1), "+f"(d2), "+f"(d3)
                 : "r"(a0), "r"(a1), "r"(a2), "r"(a3), "r"(b0), "r"(b1));
}
__device__ __forceinline__ float softplus_f(float v) {
    return (v > 20.0f) ? v : log1pf(expf(v));
}
__device__ __forceinline__ void unpack8(uint4 v, float* f) {
    uint32_t u[4] = {v.x, v.y, v.z, v.w};
    #pragma unroll
    for (int j = 0; j < 4; j++) {
        f[2 * j]     = __uint_as_float(u[j] << 16);
        f[2 * j + 1] = __uint_as_float(u[j] & 0xffff0000u);
    }
}
// dA[n] = exp(dtv * Acoef[n]); fast path when Acoef[n] == -(n+1).
__device__ __forceinline__ void compute_dA(float dtv, const float* Acoef,
                                           bool structured, float* dA) {
    if (structured) {
        const float r1 = __expf(-dtv);
        const float r2 = r1 * r1;
        const float r4 = r2 * r2;
        const float r8 = r4 * r4;
        dA[0] = r1;       dA[1] = r2;       dA[2] = r2 * r1;  dA[3] = r4;
        dA[4] = r4 * r1;  dA[5] = r4 * r2;  dA[6] = r4 * dA[2]; dA[7] = r8;
        dA[8]  = r8 * r1;   dA[9]  = r8 * r2;   dA[10] = r8 * dA[2]; dA[11] = r8 * r4;
        dA[12] = r8 * dA[4]; dA[13] = r8 * dA[5]; dA[14] = r8 * dA[6]; dA[15] = r8 * r8;
    } else {
        #pragma unroll
        for (int n = 0; n < NST; n++) dA[n] = __expf(dtv * Acoef[n]);
    }
}

// ---------------- fused weight conversion (all 4 weights, one launch) ----------------
#define N_WIN  (DDIM * 2 * EDIM)      // 1048576
#define N_WX   (EDIM * 64)            // 65536
#define N_WDT  (RRANK * EDIM)         // 32768
#define N_WOUT (EDIM * DDIM)          // 524288
__global__ void wconv_kernel(const float* __restrict__ w_in,  bf16* __restrict__ o_in,
                             const float* __restrict__ w_x,   bf16* __restrict__ o_x,
                             const float* __restrict__ w_dt,  bf16* __restrict__ o_dt,
                             const float* __restrict__ w_out, bf16* __restrict__ o_out) {
    int i = (blockIdx.x * blockDim.x + threadIdx.x) * 4;
    const float* src; bf16* dst; int off;
    if (i < N_WIN)                      { src = w_in;  dst = o_in;  off = i; }
    else if (i < N_WIN + N_WX)          { src = w_x;   dst = o_x;   off = i - N_WIN; }
    else if (i < N_WIN + N_WX + N_WDT)  { src = w_dt;  dst = o_dt;  off = i - N_WIN - N_WX; }
    else if (i < N_WIN + N_WX + N_WDT + N_WOUT)
                                        { src = w_out; dst = o_out; off = i - N_WIN - N_WX - N_WDT; }
    else return;
    float4 v = *(const float4*)(src + off);
    bf16 o[4] = {__float2bfloat16(v.x), __float2bfloat16(v.y),
                 __float2bfloat16(v.z), __float2bfloat16(v.w)};
    *(uint64_t*)(dst + off) = *(uint64_t*)o;
}

// ---------------- RMSNorm -> bf16 ----------------
__global__ void rmsnorm_kernel(const float* __restrict__ x,
                               const float* __restrict__ w,
                               bf16* __restrict__ out) {
    int row = blockIdx.x;
    int tid = threadIdx.x;
    float4 v = ((const float4*)(x + (size_t)row * DDIM))[tid];
    float ss = v.x * v.x + v.y * v.y + v.z * v.z + v.w * v.w;
    #pragma unroll
    for (int o = 16; o > 0; o >>= 1) ss += __shfl_xor_sync(0xffffffffu, ss, o);
    __shared__ float sred[4];
    if ((tid & 31) == 0) sred[tid >> 5] = ss;
    __syncthreads();
    float tot = sred[0] + sred[1] + sred[2] + sred[3];
    float scale = rsqrtf(tot * (1.0f / DDIM) + 1e-6f);
    float4 wv = ((const float4*)w)[tid];
    bf16 o[4] = {__float2bfloat16(v.x * scale * wv.x),
                 __float2bfloat16(v.y * scale * wv.y),
                 __float2bfloat16(v.z * scale * wv.z),
                 __float2bfloat16(v.w * scale * wv.w)};
    *(uint64_t*)(out + (size_t)row * DDIM + tid * 4) = *(uint64_t*)o;
}

// ---------------- bf16 tensor-core GEMM ----------------
// EPI: 2 fp32 + resid | 5 bf16 C2 only | 6 bf16 C2 + compact bf16 C3 (cols>=32)
template <int BM, int BN, int WGM, int WGN, int EPI>
__global__ void __launch_bounds__(WGM * WGN * 32)
gemm_bf16(const bf16* __restrict__ A, int lda,
          const bf16* __restrict__ B, int ldb,
          float* __restrict__ C, int ldc,
          int M, int N, int K,
          const float* __restrict__ resid,
          bf16* __restrict__ C2,
          bf16* __restrict__ C3) {
    constexpr int BK = 32;
    constexpr int NTHR = WGM * WGN * 32;
    constexpr int WM = BM / WGM;
    constexpr int WN = BN / WGN;
    constexpr int MT = WM / 16;
    constexpr int NT = WN / 8;
    static_assert(NT % 2 == 0, "NT even");

    __shared__ __align__(16) bf16 As[2][BM][BK + 8];
    __shared__ __align__(16) bf16 Bs[2][BK][BN + 8];

    const int tid = threadIdx.x;
    const int warp = tid >> 5, lane = tid & 31;
    const int wm = (warp % WGM) * WM;
    const int wn = (warp / WGM) * WN;
    const int rowBase = blockIdx.y * BM;
    const int colBase = blockIdx.x * BN;

    float acc[MT][NT][4];
    #pragma unroll
    for (int i = 0; i < MT; i++)
        #pragma unroll
        for (int j = 0; j < NT; j++)
            #pragma unroll
            for (int q = 0; q < 4; q++) acc[i][j][q] = 0.0f;

    constexpr int A_CHUNKS = BM * BK / 8;
    constexpr int B_CHUNKS = BK * BN / 8;

    auto load_tile = [&](int buf, int k0) {
        #pragma unroll
        for (int c = tid; c < A_CHUNKS; c += NTHR) {
            int row = c / (BK / 8);
            int col = (c % (BK / 8)) * 8;
            cp_async16(&As[buf][row][col],
                       &A[(size_t)(rowBase + row) * lda + k0 + col]);
        }
        #pragma unroll
        for (int c = tid; c < B_CHUNKS; c += NTHR) {
            int row = c / (BN / 8);
            int col = (c % (BN / 8)) * 8;
            cp_async16(&Bs[buf][row][col],
                       &B[(size_t)(k0 + row) * ldb + colBase + col]);
        }
        cp_commit();
    };

    const int KT = K / BK;
    load_tile(0, 0);

    const int arow = lane & 15, acol = (lane >> 4) * 8;
    const int bq = lane >> 3, bl = lane & 7;
    const int bk = (bq & 1) * 8 + bl, bn = (bq >> 1) * 8;

    for (int kt = 0; kt < KT; kt++) {
        const int buf = kt & 1;
        if (kt + 1 < KT) {
            load_tile(buf ^ 1, (kt + 1) * BK);
            cp_wait<1>();
        } else {
            cp_wait<0>();
        }
        __syncthreads();

        #pragma unroll
        for (int ks = 0; ks < 2; ks++) {
            uint32_t a[MT][4];
            #pragma unroll
            for (int mt = 0; mt < MT; mt++)
                ldsm_x4(a[mt][0], a[mt][1], a[mt][2], a[mt][3],
                        smem_u32(&As[buf][wm + mt * 16 + arow][ks * 16 + acol]));
            uint32_t b[NT][2];
            #pragma unroll
            for (int nt2 = 0; nt2 < NT / 2; nt2++) {
                uint32_t r0, r1, r2, r3;
                ldsm_x4_t(r0, r1, r2, r3,
                          smem_u32(&Bs[buf][ks * 16 + bk][wn + nt2 * 16 + bn]));
                b[2 * nt2][0] = r0; b[2 * nt2][1] = r1;
                b[2 * nt2 + 1][0] = r2; b[2 * nt2 + 1][1] = r3;
            }
            #pragma unroll
            for (int mt = 0; mt < MT; mt++)
                #pragma unroll
                for (int nt = 0; nt < NT; nt++)
                    mma_bf16(acc[mt][nt][0], acc[mt][nt][1], acc[mt][nt][2], acc[mt][nt][3],
                             a[mt][0], a[mt][1], a[mt][2], a[mt][3],
                             b[nt][0], b[nt][1]);
        }
        __syncthreads();
    }

    #pragma unroll
    for (int mt = 0; mt < MT; mt++) {
        #pragma unroll
        for (int nt = 0; nt < NT; nt++) {
            int col = colBase + wn + nt * 8 + (lane & 3) * 2;
            #pragma unroll
            for (int h = 0; h < 2; h++) {
                int row = rowBase + wm + mt * 16 + (lane >> 2) + h * 8;
                float v0 = acc[mt][nt][2 * h + 0];
                float v1 = acc[mt][nt][2 * h + 1];
                if (EPI == 2) {
                    const float2 r = *(const float2*)&resid[(size_t)row * ldc + col];
                    v0 += r.x; v1 += r.y;
                    *(float2*)&C[(size_t)row * ldc + col] = make_float2(v0, v1);
                }
                if (EPI == 5 || EPI == 6) {
                    bf16 o[2] = {__float2bfloat16(v0), __float2bfloat16(v1)};
                    *(uint32_t*)&C2[(size_t)row * ldc + col] = *(uint32_t*)o;
                    if (EPI == 6 && col >= RRANK)
                        *(uint32_t*)&C3[(size_t)row * 32 + col - RRANK] = *(uint32_t*)o;
                }
            }
        }
    }
}

// ---------------- dedicated dt GEMM ----------------
__global__ void __launch_bounds__(256)
dtgemm_kernel(const bf16* __restrict__ A,
              const bf16* __restrict__ B,
              const float* __restrict__ bias,
              float* __restrict__ dtT) {
    __shared__ __align__(16) bf16 As[128][40];
    __shared__ __align__(16) bf16 Bs[32][136];
    __shared__ float sbuf[32][129];

    const int tid = threadIdx.x, warp = tid >> 5, lane = tid & 31;
    const int wm = (warp & 1) * 64;
    const int wn = (warp >> 1) * 32;
    const int rowBase = blockIdx.y * 128;
    const int colBase = blockIdx.x * 128;

    #pragma unroll
    for (int c = tid; c < 512; c += 256) {
        int r = c >> 2, q = (c & 3) * 8;
        cp_async16(&As[r][q], &A[(size_t)(rowBase + r) * 64 + q]);
    }
    #pragma unroll
    for (int c = tid; c < 512; c += 256) {
        int r = c >> 4, q = (c & 15) * 8;
        cp_async16(&Bs[r][q], &B[(size_t)r * EDIM + colBase + q]);
    }
    cp_commit(); cp_wait<0>(); __syncthreads();

    float acc[4][4][4];
    #pragma unroll
    for (int i = 0; i < 4; i++)
        #pragma unroll
        for (int j = 0; j < 4; j++)
            #pragma unroll
            for (int q = 0; q < 4; q++) acc[i][j][q] = 0.0f;

    const int arow = lane & 15, acol = (lane >> 4) * 8;
    const int bq = lane >> 3, bl = lane & 7;
    const int bk = (bq & 1) * 8 + bl, bn = (bq >> 1) * 8;

    #pragma unroll
    for (int ks = 0; ks < 2; ks++) {
        uint32_t a[4][4];
        #pragma unroll
        for (int mt = 0; mt < 4; mt++)
            ldsm_x4(a[mt][0], a[mt][1], a[mt][2], a[mt][3],
                    smem_u32(&As[wm + mt * 16 + arow][ks * 16 + acol]));
        uint32_t b[4][2];
        #pragma unroll
        for (int nt2 = 0; nt2 < 2; nt2++) {
            uint32_t r0, r1, r2, r3;
            ldsm_x4_t(r0, r1, r2, r3,
                      smem_u32(&Bs[ks * 16 + bk][wn + nt2 * 16 + bn]));
            b[2 * nt2][0] = r0; b[2 * nt2][1] = r1;
            b[2 * nt2 + 1][0] = r2; b[2 * nt2 + 1][1] = r3;
        }
        #pragma unroll
        for (int mt = 0; mt < 4; mt++)
            #pragma unroll
            for (int nt = 0; nt < 4; nt++)
                mma_bf16(acc[mt][nt][0], acc[mt][nt][1], acc[mt][nt][2], acc[mt][nt][3],
                         a[mt][0], a[mt][1], a[mt][2], a[mt][3],
                         b[nt][0], b[nt][1]);
    }

    const int bb = rowBase >> 11;
    const int tb = rowBase & 2047;
    #pragma unroll
    for (int cc = 0; cc < 4; cc++) {
        __syncthreads();
        if (wn == cc * 32) {
            #pragma unroll
            for (int mt = 0; mt < 4; mt++)
                #pragma unroll
                for (int nt = 0; nt < 4; nt++) {
                    int c = nt * 8 + (lane & 3) * 2;
                    int col = colBase + wn + c;
                    #pragma unroll
                    for (int h = 0; h < 2; h++) {
                        int r = wm + mt * 16 + (lane >> 2) + h * 8;
                        sbuf[c][r]     = softplus_f(acc[mt][nt][2 * h]     + bias[col]);
                        sbuf[c + 1][r] = softplus_f(acc[mt][nt][2 * h + 1] + bias[col + 1]);
                    }
                }
        }
        __syncthreads();
        for (int j = tid; j < 32 * 128; j += 256) {
            int c = j >> 7, r = j & 127;
            dtT[((size_t)bb * EDIM + colBase + cc * 32 + c) * LSEQ + tb + r] = sbuf[c][r];
        }
    }
}

// ---------------- fused conv+silu+transposes ----------------
__global__ void __launch_bounds__(256)
conv_fused_kernel(const bf16* __restrict__ xzb,
                  const float* __restrict__ conv_w,
                  const float* __restrict__ conv_b,
                  bf16* __restrict__ xsb,
                  float* __restrict__ xsT,
                  bf16* __restrict__ zT) {
    __shared__ float xt[35][65];
    __shared__ float st[32][65];
    __shared__ bf16  zt[32][66];

    const int e0 = blockIdx.x * 64;
    const int t0 = blockIdx.y * 32;
    const int b  = blockIdx.z;
    const int tx = threadIdx.x & 31, ty = threadIdx.x >> 5;

    for (int i = ty; i < 35; i += 8) {
        int t = t0 - 3 + i;
        uint32_t pv = 0;
        if (t >= 0)
            pv = *(const uint32_t*)&xzb[((size_t)(b * LSEQ + t)) * (2 * EDIM) + e0 + 2 * tx];
        bf16 p[2]; *(uint32_t*)p = pv;
        xt[i][2 * tx]     = __bfloat162float(p[0]);
        xt[i][2 * tx + 1] = __bfloat162float(p[1]);
    }
    for (int i = ty; i < 32; i += 8) {
        uint32_t pv = *(const uint32_t*)&xzb[((size_t)(b * LSEQ + t0 + i)) * (2 * EDIM) + EDIM + e0 + 2 * tx];
        *(uint32_t*)&zt[i][2 * tx] = pv;
    }
    __syncthreads();

    const int ea = e0 + 2 * tx, ebx = ea + 1;
    const float w0a = conv_w[ea * 4 + 0], w1a = conv_w[ea * 4 + 1],
                w2a = conv_w[ea * 4 + 2], w3a = conv_w[ea * 4 + 3], bba = conv_b[ea];
    const float w0b = conv_w[ebx * 4 + 0], w1b = conv_w[ebx * 4 + 1],
                w2b = conv_w[ebx * 4 + 2], w3b = conv_w[ebx * 4 + 3], bbb = conv_b[ebx];

    for (int i = ty; i < 32; i += 8) {
        float a0 = bba + w0a * xt[i][2*tx] + w1a * xt[i+1][2*tx]
                       + w2a * xt[i+2][2*tx] + w3a * xt[i+3][2*tx];
        float a1 = bbb + w0b * xt[i][2*tx+1] + w1b * xt[i+1][2*tx+1]
                       + w2b * xt[i+2][2*tx+1] + w3b * xt[i+3][2*tx+1];
        float s0 = a0 / (1.0f + __expf(-a0));
        float s1 = a1 / (1.0f + __expf(-a1));
        st[i][2*tx] = s0; st[i][2*tx+1] = s1;
        bf16 o[2] = {__float2bfloat16(s0), __float2bfloat16(s1)};
        *(uint32_t*)&xsb[((size_t)(b * LSEQ + t0 + i)) * EDIM + e0 + 2 * tx] = *(uint32_t*)o;
    }
    __syncthreads();

    for (int i = ty; i < 64; i += 8) {
        xsT[((size_t)b * EDIM + e0 + i) * LSEQ + t0 + tx] = st[tx][i];
        zT [((size_t)b * EDIM + e0 + i) * LSEQ + t0 + tx] = zt[tx][i];
    }
}

// ---------------- chunked parallel selective scan (32 warps/block, shared B/C) ----------------
#define CHUNK 64
#define BC_SMEM_BYTES 131072
#define YROW 2112                       // 2048 + 2*32 padding (u32-aligned swizzle)
#define YSTAGE_BYTES (8 * YROW * 2)
#define SCAN_SMEM (BC_SMEM_BYTES + YSTAGE_BYTES)

__device__ __forceinline__ const uint4* bc_addr(const char* bcs, int t, int c) {
    int slot = ((t & 1) * 4 + c) ^ ((t >> 6) & 7);
    return (const uint4*)(bcs + (t >> 1) * 128 + slot * 16);
}

__global__ void __launch_bounds__(1024)
scan_kernel(const float* __restrict__ dtT,
            const float* __restrict__ xsT,
            const bf16*  __restrict__ zT,
            const bf16*  __restrict__ bcb,
            const float* __restrict__ A_log,
            const float* __restrict__ D_skip,
            bf16* __restrict__ y) {
    extern __shared__ __align__(16) char dyn[];
    char* bcs = dyn;
    bf16 (*ystage)[YROW] = (bf16 (*)[YROW])(dyn + BC_SMEM_BYTES);

    const int b    = blockIdx.y;
    const int warp = threadIdx.x >> 5;
    const int lane = threadIdx.x & 31;
    const int e    = blockIdx.x * 32 + warp;

    // ---- stage B/C (shared by all 32 warps) ----
    {
        const bf16* src = bcb + (size_t)b * LSEQ * 32;
        for (int k = threadIdx.x; k < 8192; k += 1024) {
            int t = k >> 2, c = k & 3;
            int slot = ((t & 1) * 4 + c) ^ ((t >> 6) & 7);
            cp_async16(bcs + (t >> 1) * 128 + slot * 16, src + k * 8);
        }
        cp_commit(); cp_wait<0>();
    }
    __syncthreads();

    float Acoef[NST];
    bool structured = true;
    #pragma unroll
    for (int n = 0; n < NST; n++) {
        Acoef[n] = -__expf(A_log[e * NST + n]);
        structured &= fabsf(Acoef[n] + (float)(n + 1)) < 1e-4f * (float)(n + 1);
    }
    const float dsk = D_skip[e];

    const float* dtp = dtT + ((size_t)b * EDIM + e) * LSEQ;
    const float* xsp = xsT + ((size_t)b * EDIM + e) * LSEQ;
    const bf16*  zp  = zT  + ((size_t)b * EDIM + e) * LSEQ;

    const int t0 = lane * CHUNK;

    // ---- pass 1: per-chunk affine summary (P, q) ----
    float P[NST], q[NST];
    #pragma unroll
    for (int n = 0; n < NST; n++) { P[n] = 1.0f; q[n] = 0.0f; }

    for (int s4 = 0; s4 < CHUNK; s4 += 4) {
        float4 d4 = *(const float4*)&dtp[t0 + s4];
        float4 x4 = *(const float4*)&xsp[t0 + s4];
        float dv[4] = {d4.x, d4.y, d4.z, d4.w};
        float xv[4] = {x4.x, x4.y, x4.z, x4.w};
        #pragma unroll
        for (int u = 0; u < 4; u++) {
            const int t = t0 + s4 + u;
            float Bv[NST];
            unpack8(*bc_addr(bcs, t, 0), Bv);
            unpack8(*bc_addr(bcs, t, 1), Bv + 8);
            float dA[NST];
            compute_dA(dv[u], Acoef, structured, dA);
            const float dx = dv[u] * xv[u];
            #pragma unroll
            for (int n = 0; n < NST; n++) {
                q[n] = fmaf(dA[n], q[n], dx * Bv[n]);
                P[n] *= dA[n];
            }
        }
    }

    // ---- warp inclusive scan of affine maps over lanes ----
    #pragma unroll
    for (int d = 1; d < 32; d <<= 1) {
        #pragma unroll
        for (int n = 0; n < NST; n++) {
            float Pp = __shfl_up_sync(0xffffffffu, P[n], d);
            float qp = __shfl_up_sync(0xffffffffu, q[n], d);
            if (lane >= d) {
                q[n] = fmaf(P[n], qp, q[n]);
                P[n] *= Pp;
            }
        }
    }
    float h[NST];
    #pragma unroll
    for (int n = 0; n < NST; n++) {
        float v = __shfl_up_sync(0xffffffffu, q[n], 1);
        h[n] = (lane == 0) ? 0.0f : v;
    }

    // ---- pass 2: replay with true h0; accumulate y in registers (packed bf16) ----
    uint32_t yreg[32];
    for (int s8 = 0; s8 < CHUNK; s8 += 8) {
        float4 d4a = *(const float4*)&dtp[t0 + s8];
        float4 d4b = *(const float4*)&dtp[t0 + s8 + 4];
        float4 x4a = *(const float4*)&xsp[t0 + s8];
        float4 x4b = *(const float4*)&xsp[t0 + s8 + 4];
        uint4  zv8 = *(const uint4*)&zp[t0 + s8];
        float dv[8] = {d4a.x, d4a.y, d4a.z, d4a.w, d4b.x, d4b.y, d4b.z, d4b.w};
        float xv[8] = {x4a.x, x4a.y, x4a.z, x4a.w, x4b.x, x4b.y, x4b.z, x4b.w};
        float zv[8];
        unpack8(zv8, zv);
        uint32_t pklo = 0;
        #pragma unroll
        for (int u = 0; u < 8; u++) {
            const int t = t0 + s8 + u;
            float Bv[NST], Cv[NST];
            unpack8(*bc_addr(bcs, t, 0), Bv);
            unpack8(*bc_addr(bcs, t, 1), Bv + 8);
            unpack8(*bc_addr(bcs, t, 2), Cv);
            unpack8(*bc_addr(bcs, t, 3), Cv + 8);
            float dA[NST];
            compute_dA(dv[u], Acoef, structured, dA);
            const float dx = dv[u] * xv[u];
            float yacc0 = 0.0f, yacc1 = 0.0f;
            #pragma unroll
            for (int n = 0; n < NST; n += 2) {
                h[n]     = fmaf(dA[n],     h[n],     dx * Bv[n]);
                h[n + 1] = fmaf(dA[n + 1], h[n + 1], dx * Bv[n + 1]);
                yacc0 = fmaf(h[n],     Cv[n],     yacc0);
                yacc1 = fmaf(h[n + 1], Cv[n + 1], yacc1);
            }
            const float zz  = zv[u];
            const float sig = 1.0f / (1.0f + __expf(-zz));
            const float out = ((yacc0 + yacc1) + xv[u] * dsk) * (zz * sig);
            const uint32_t ob = (uint32_t)__bfloat16_as_ushort(__float2bfloat16(out));
            if (u & 1) yreg[(s8 + u) >> 1] = pklo | (ob << 16);
            else       pklo = ob;
        }
    }
    __syncthreads();

    // ---- grouped y staging + coalesced store (4 rounds of 8 warps) ----
    const int grp  = warp >> 3;
    const int wrow = warp & 7;
    #pragma unroll
    for (int g = 0; g < 4; g++) {
        if (grp == g) {
            #pragma unroll
            for (int i = 0; i < 32; i++) {
                int t = t0 + i * 2;
                *(uint32_t*)&ystage[wrow][t + 2 * (t >> 6)] = yreg[i];
            }
        }
        __syncthreads();
        const int e0 = blockIdx.x * 32 + g * 8;
        for (int t = threadIdx.x; t < LSEQ; t += 1024) {
            bf16 v[8];
            #pragma unroll
            for (int w = 0; w < 8; w++) v[w] = ystage[w][t + 2 * (t >> 6)];
            *(uint4*)&y[((size_t)(b * LSEQ + t)) * EDIM + e0] = *(uint4*)v;
        }
        __syncthreads();
    }
}

// ---------------- launcher ----------------
extern "C" void kernel_launch(void* const* d_in, const int* in_sizes, int n_in,
                              void* d_out, int out_size) {
    const float* hidden = (const float*)d_in[0];
    const float* norm_w = (const float*)d_in[1];
    const float* W_in   = (const float*)d_in[2];
    const float* conv_w = (const float*)d_in[3];
    const float* conv_b = (const float*)d_in[4];
    const float* W_x    = (const float*)d_in[5];
    const float* W_dt   = (const float*)d_in[6];
    const float* b_dt   = (const float*)d_in[7];
    const float* A_log  = (const float*)d_in[8];
    const float* D_skip = (const float*)d_in[9];
    const float* W_out  = (const float*)d_in[10];
    float* out = (float*)d_out;

    float *p_dtT, *p_xsT;
    bf16 *p_xzb, *p_zT, *p_nrmb, *p_xsb, *p_dblb, *p_bcb, *p_yb;
    bf16 *p_winb, *p_wxb, *p_wdtb, *p_woutb;
    cudaGetSymbolAddress((void**)&p_xzb,  g_xzb);
    cudaGetSymbolAddress((void**)&p_dtT,  g_dtT);
    cudaGetSymbolAddress((void**)&p_xsT,  g_xsT);
    cudaGetSymbolAddress((void**)&p_zT,   g_zT);
    cudaGetSymbolAddress((void**)&p_nrmb, g_nrmb);
    cudaGetSymbolAddress((void**)&p_xsb,  g_xsb);
    cudaGetSymbolAddress((void**)&p_dblb, g_dblb);
    cudaGetSymbolAddress((void**)&p_bcb,  g_bcb);
    cudaGetSymbolAddress((void**)&p_yb,   g_yb);
    cudaGetSymbolAddress((void**)&p_winb, g_winb);
    cudaGetSymbolAddress((void**)&p_wxb,  g_wxb);
    cudaGetSymbolAddress((void**)&p_wdtb, g_wdtb);
    cudaGetSymbolAddress((void**)&p_woutb, g_woutb);

    cudaFuncSetAttribute(scan_kernel, cudaFuncAttributeMaxDynamicSharedMemorySize, SCAN_SMEM);

    // 0) fused weight conversion
    {
        int total = (N_WIN + N_WX + N_WDT + N_WOUT) / 4;
        wconv_kernel<<<(total + 255) / 256, 256>>>(W_in, p_winb, W_x, p_wxb,
                                                   W_dt, p_wdtb, W_out, p_woutb);
    }

    // 1) RMSNorm -> bf16
    rmsnorm_kernel<<<NTOK, 128>>>(hidden, norm_w, p_nrmb);

    // 2) xz = nrm @ W_in -> bf16 only
    gemm_bf16<128, 128, 2, 4, 5><<<dim3(2 * EDIM / 128, NTOK / 128), 256>>>(
        p_nrmb, DDIM, p_winb, 2 * EDIM, nullptr, 2 * EDIM,
        NTOK, 2 * EDIM, DDIM, nullptr, p_xzb, nullptr);

    // 3) fused conv + silu + transposes
    conv_fused_kernel<<<dim3(EDIM / 64, LSEQ / 32, BSZ), 256>>>(
        p_xzb, conv_w, conv_b, p_xsb, p_xsT, p_zT);

    // 4) dbl = xs @ W_x -> bf16 full + bf16 compact BC
    gemm_bf16<64, 64, 4, 2, 6><<<dim3(1, NTOK / 64), 256>>>(
        p_xsb, EDIM, p_wxb, 64, nullptr, 64,
        NTOK, 64, EDIM, nullptr, p_dblb, p_bcb);

    // 5) dtT = softplus(dbl[:, :32] @ W_dt + b_dt), transposed write
    dtgemm_kernel<<<dim3(EDIM / 128, NTOK / 128), 256>>>(p_dblb, p_wdtb, b_dt, p_dtT);

    // 6) chunked parallel scan (32 warps/block, shared B/C) -> bf16 y
    scan_kernel<<<dim3(EDIM / 32, BSZ), 1024, SCAN_SMEM>>>(
        p_dtT, p_xsT, p_zT, p_bcb, A_log, D_skip, p_yb);

    // 7) out = y @ W_out + hidden -> fp32
    gemm_bf16<128, 128, 2, 4, 2><<<dim3(DDIM / 128, NTOK / 128), 256>>>(
        p_yb, EDIM, p_woutb, DDIM, out, DDIM,
        NTOK, DDIM, EDIM, hidden, nullptr, nullptr);
}

// round 10
// speedup vs baseline: 1.0873x; 1.0873x over previous
#include <cuda_runtime.h>
#include <cuda_bf16.h>
#include <cstdint>

using bf16 = __nv_bfloat16;

// Problem constants
#define BSZ 4
#define LSEQ 2048
#define DDIM 512
#define EDIM 1024
#define NST 16
#define RRANK 32
#define NTOK (BSZ * LSEQ)          // 8192

// ---------------- scratch (device globals) ----------------
__device__ bf16  g_xzb[NTOK * 2 * EDIM];
__device__ float g_dtT[NTOK * EDIM];
__device__ float g_xsT[NTOK * EDIM];
__device__ bf16  g_zT [NTOK * EDIM];
__device__ bf16  g_nrmb[NTOK * DDIM];
__device__ bf16  g_xsb [NTOK * EDIM];
__device__ bf16  g_dblb[NTOK * 64];
__device__ bf16  g_bcb [NTOK * 32];
__device__ bf16  g_yb  [NTOK * EDIM];
__device__ bf16  g_winb [DDIM * 2 * EDIM];
__device__ bf16  g_wxb  [EDIM * 64];
__device__ bf16  g_wdtb [RRANK * EDIM];
__device__ bf16  g_woutb[EDIM * DDIM];

// ---------------- PTX helpers ----------------
__device__ __forceinline__ uint32_t smem_u32(const void* p) {
    return (uint32_t)__cvta_generic_to_shared(p);
}
__device__ __forceinline__ void cp_async16(void* s, const void* g) {
    asm volatile("cp.async.cg.shared.global [%0], [%1], 16;\n"
                 :: "r"(smem_u32(s)), "l"(g));
}
__device__ __forceinline__ void cp_commit() { asm volatile("cp.async.commit_group;\n"); }
template <int N> __device__ __forceinline__ void cp_wait() {
    asm volatile("cp.async.wait_group %0;\n" :: "n"(N));
}
__device__ __forceinline__ void ldsm_x4(uint32_t& r0, uint32_t& r1, uint32_t& r2, uint32_t& r3,
                                        uint32_t a) {
    asm volatile("ldmatrix.sync.aligned.m8n8.x4.shared.b16 {%0,%1,%2,%3}, [%4];\n"
                 : "=r"(r0), "=r"(r1), "=r"(r2), "=r"(r3) : "r"(a));
}
__device__ __forceinline__ void ldsm_x4_t(uint32_t& r0, uint32_t& r1, uint32_t& r2, uint32_t& r3,
                                          uint32_t a) {
    asm volatile("ldmatrix.sync.aligned.m8n8.x4.trans.shared.b16 {%0,%1,%2,%3}, [%4];\n"
                 : "=r"(r0), "=r"(r1), "=r"(r2), "=r"(r3) : "r"(a));
}
__device__ __forceinline__ void mma_bf16(float& d0, float& d1, float& d2, float& d3,
                                         uint32_t a0, uint32_t a1, uint32_t a2, uint32_t a3,
                                         uint32_t b0, uint32_t b1) {
    asm volatile("mma.sync.aligned.m16n8k16.row.col.f32.bf16.bf16.f32 "
                 "{%0,%1,%2,%3}, {%4,%5,%6,%7}, {%8,%9}, {%0,%1,%2,%3};\n"
                 : "+f"(d0), "+f"(d1), "+f"(d2), "+f"(d3)
                 : "r"(a0), "r"(a1), "r"(a2), "r"(a3), "r"(b0), "r"(b1));
}
__device__ __forceinline__ float softplus_f(float v) {
    return (v > 20.0f) ? v : log1pf(expf(v));
}
__device__ __forceinline__ void unpack8(uint4 v, float* f) {
    uint32_t u[4] = {v.x, v.y, v.z, v.w};
    #pragma unroll
    for (int j = 0; j < 4; j++) {
        f[2 * j]     = __uint_as_float(u[j] << 16);
        f[2 * j + 1] = __uint_as_float(u[j] & 0xffff0000u);
    }
}
// dA[n] = exp(dtv * Acoef[n]); fast path when Acoef[n] == -(n+1).
__device__ __forceinline__ void compute_dA(float dtv, const float* Acoef,
                                           bool structured, float* dA) {
    if (structured) {
        const float r1 = __expf(-dtv);
        const float r2 = r1 * r1;
        const float r4 = r2 * r2;
        const float r8 = r4 * r4;
        dA[0] = r1;       dA[1] = r2;       dA[2] = r2 * r1;  dA[3] = r4;
        dA[4] = r4 * r1;  dA[5] = r4 * r2;  dA[6] = r4 * dA[2]; dA[7] = r8;
        dA[8]  = r8 * r1;   dA[9]  = r8 * r2;   dA[10] = r8 * dA[2]; dA[11] = r8 * r4;
        dA[12] = r8 * dA[4]; dA[13] = r8 * dA[5]; dA[14] = r8 * dA[6]; dA[15] = r8 * r8;
    } else {
        #pragma unroll
        for (int n = 0; n < NST; n++) dA[n] = __expf(dtv * Acoef[n]);
    }
}

// ---------------- fused weight conversion ----------------
#define N_WIN  (DDIM * 2 * EDIM)
#define N_WX   (EDIM * 64)
#define N_WDT  (RRANK * EDIM)
#define N_WOUT (EDIM * DDIM)
__global__ void wconv_kernel(const float* __restrict__ w_in,  bf16* __restrict__ o_in,
                             const float* __restrict__ w_x,   bf16* __restrict__ o_x,
                             const float* __restrict__ w_dt,  bf16* __restrict__ o_dt,
                             const float* __restrict__ w_out, bf16* __restrict__ o_out) {
    int i = (blockIdx.x * blockDim.x + threadIdx.x) * 4;
    const float* src; bf16* dst; int off;
    if (i < N_WIN)                      { src = w_in;  dst = o_in;  off = i; }
    else if (i < N_WIN + N_WX)          { src = w_x;   dst = o_x;   off = i - N_WIN; }
    else if (i < N_WIN + N_WX + N_WDT)  { src = w_dt;  dst = o_dt;  off = i - N_WIN - N_WX; }
    else if (i < N_WIN + N_WX + N_WDT + N_WOUT)
                                        { src = w_out; dst = o_out; off = i - N_WIN - N_WX - N_WDT; }
    else return;
    float4 v = *(const float4*)(src + off);
    bf16 o[4] = {__float2bfloat16(v.x), __float2bfloat16(v.y),
                 __float2bfloat16(v.z), __float2bfloat16(v.w)};
    *(uint64_t*)(dst + off) = *(uint64_t*)o;
}

// ---------------- RMSNorm -> bf16 ----------------
__global__ void rmsnorm_kernel(const float* __restrict__ x,
                               const float* __restrict__ w,
                               bf16* __restrict__ out) {
    int row = blockIdx.x;
    int tid = threadIdx.x;
    float4 v = ((const float4*)(x + (size_t)row * DDIM))[tid];
    float ss = v.x * v.x + v.y * v.y + v.z * v.z + v.w * v.w;
    #pragma unroll
    for (int o = 16; o > 0; o >>= 1) ss += __shfl_xor_sync(0xffffffffu, ss, o);
    __shared__ float sred[4];
    if ((tid & 31) == 0) sred[tid >> 5] = ss;
    __syncthreads();
    float tot = sred[0] + sred[1] + sred[2] + sred[3];
    float scale = rsqrtf(tot * (1.0f / DDIM) + 1e-6f);
    float4 wv = ((const float4*)w)[tid];
    bf16 o[4] = {__float2bfloat16(v.x * scale * wv.x),
                 __float2bfloat16(v.y * scale * wv.y),
                 __float2bfloat16(v.z * scale * wv.z),
                 __float2bfloat16(v.w * scale * wv.w)};
    *(uint64_t*)(out + (size_t)row * DDIM + tid * 4) = *(uint64_t*)o;
}

// ---------------- bf16 tensor-core GEMM, 3-stage cp.async pipeline ----------------
// EPI: 2 fp32 + resid | 5 bf16 C2 only | 6 bf16 C2 + compact bf16 C3 (cols>=32)
template <int BM, int BN, int WGM, int WGN, int EPI>
__global__ void __launch_bounds__(WGM * WGN * 32)
gemm_bf16(const bf16* __restrict__ A, int lda,
          const bf16* __restrict__ B, int ldb,
          float* __restrict__ C, int ldc,
          int M, int N, int K,
          const float* __restrict__ resid,
          bf16* __restrict__ C2,
          bf16* __restrict__ C3) {
    constexpr int BK = 32;
    constexpr int NTHR = WGM * WGN * 32;
    constexpr int WM = BM / WGM;
    constexpr int WN = BN / WGN;
    constexpr int MT = WM / 16;
    constexpr int NT = WN / 8;
    static_assert(NT % 2 == 0, "NT even");
    constexpr int LDAS = BK + 8;
    constexpr int LDBS = BN + 8;
    constexpr int SA_ELEM = BM * LDAS;
    constexpr int SB_ELEM = BK * LDBS;
    constexpr int STAGE = SA_ELEM + SB_ELEM;

    extern __shared__ __align__(16) bf16 smem[];

    const int tid = threadIdx.x;
    const int warp = tid >> 5, lane = tid & 31;
    const int wm = (warp % WGM) * WM;
    const int wn = (warp / WGM) * WN;
    const int rowBase = blockIdx.y * BM;
    const int colBase = blockIdx.x * BN;

    float acc[MT][NT][4];
    #pragma unroll
    for (int i = 0; i < MT; i++)
        #pragma unroll
        for (int j = 0; j < NT; j++)
            #pragma unroll
            for (int q = 0; q < 4; q++) acc[i][j][q] = 0.0f;

    constexpr int A_CHUNKS = BM * BK / 8;
    constexpr int B_CHUNKS = BK * BN / 8;

    auto load_tile = [&](int s, int k0) {
        bf16* As = smem + s * STAGE;
        bf16* Bs = As + SA_ELEM;
        #pragma unroll
        for (int c = tid; c < A_CHUNKS; c += NTHR) {
            int row = c / (BK / 8);
            int col = (c % (BK / 8)) * 8;
            cp_async16(&As[row * LDAS + col],
                       &A[(size_t)(rowBase + row) * lda + k0 + col]);
        }
        #pragma unroll
        for (int c = tid; c < B_CHUNKS; c += NTHR) {
            int row = c / (BN / 8);
            int col = (c % (BN / 8)) * 8;
            cp_async16(&Bs[row * LDBS + col],
                       &B[(size_t)(k0 + row) * ldb + colBase + col]);
        }
        cp_commit();
    };

    const int KT = K / BK;
    load_tile(0, 0);
    if (KT > 1) load_tile(1, BK);

    const int arow = lane & 15, acol = (lane >> 4) * 8;
    const int bq = lane >> 3, bl = lane & 7;
    const int bk = (bq & 1) * 8 + bl, bn = (bq >> 1) * 8;

    int sbuf = 0;
    for (int kt = 0; kt < KT; kt++) {
        if (kt + 2 < KT) cp_wait<1>(); else cp_wait<0>();
        __syncthreads();
        if (kt + 2 < KT) {
            int s2 = sbuf + 2; if (s2 >= 3) s2 -= 3;
            load_tile(s2, (kt + 2) * BK);
        }
        const bf16* As = smem + sbuf * STAGE;
        const bf16* Bs = As + SA_ELEM;

        #pragma unroll
        for (int ks = 0; ks < 2; ks++) {
            uint32_t a[MT][4];
            #pragma unroll
            for (int mt = 0; mt < MT; mt++)
                ldsm_x4(a[mt][0], a[mt][1], a[mt][2], a[mt][3],
                        smem_u32(&As[(wm + mt * 16 + arow) * LDAS + ks * 16 + acol]));
            uint32_t b[NT][2];
            #pragma unroll
            for (int nt2 = 0; nt2 < NT / 2; nt2++) {
                uint32_t r0, r1, r2, r3;
                ldsm_x4_t(r0, r1, r2, r3,
                          smem_u32(&Bs[(ks * 16 + bk) * LDBS + wn + nt2 * 16 + bn]));
                b[2 * nt2][0] = r0; b[2 * nt2][1] = r1;
                b[2 * nt2 + 1][0] = r2; b[2 * nt2 + 1][1] = r3;
            }
            #pragma unroll
            for (int mt = 0; mt < MT; mt++)
                #pragma unroll
                for (int nt = 0; nt < NT; nt++)
                    mma_bf16(acc[mt][nt][0], acc[mt][nt][1], acc[mt][nt][2], acc[mt][nt][3],
                             a[mt][0], a[mt][1], a[mt][2], a[mt][3],
                             b[nt][0], b[nt][1]);
        }
        if (++sbuf == 3) sbuf = 0;
    }

    #pragma unroll
    for (int mt = 0; mt < MT; mt++) {
        #pragma unroll
        for (int nt = 0; nt < NT; nt++) {
            int col = colBase + wn + nt * 8 + (lane & 3) * 2;
            #pragma unroll
            for (int h = 0; h < 2; h++) {
                int row = rowBase + wm + mt * 16 + (lane >> 2) + h * 8;
                float v0 = acc[mt][nt][2 * h + 0];
                float v1 = acc[mt][nt][2 * h + 1];
                if (EPI == 2) {
                    const float2 r = *(const float2*)&resid[(size_t)row * ldc + col];
                    v0 += r.x; v1 += r.y;
                    *(float2*)&C[(size_t)row * ldc + col] = make_float2(v0, v1);
                }
                if (EPI == 5 || EPI == 6) {
                    bf16 o[2] = {__float2bfloat16(v0), __float2bfloat16(v1)};
                    *(uint32_t*)&C2[(size_t)row * ldc + col] = *(uint32_t*)o;
                    if (EPI == 6 && col >= RRANK)
                        *(uint32_t*)&C3[(size_t)row * 32 + col - RRANK] = *(uint32_t*)o;
                }
            }
        }
    }
}
#define GEMM_BIG_SMEM  (3 * (128 * 40 + 32 * 136) * 2)   // 56832
#define GEMM_DBL_SMEM  (3 * (64 * 40 + 32 * 72) * 2)     // 29184

// ---------------- dedicated dt GEMM ----------------
__global__ void __launch_bounds__(256)
dtgemm_kernel(const bf16* __restrict__ A,
              const bf16* __restrict__ B,
              const float* __restrict__ bias,
              float* __restrict__ dtT) {
    __shared__ __align__(16) bf16 As[128][40];
    __shared__ __align__(16) bf16 Bs[32][136];
    __shared__ float sbuf[32][129];

    const int tid = threadIdx.x, warp = tid >> 5, lane = tid & 31;
    const int wm = (warp & 1) * 64;
    const int wn = (warp >> 1) * 32;
    const int rowBase = blockIdx.y * 128;
    const int colBase = blockIdx.x * 128;

    #pragma unroll
    for (int c = tid; c < 512; c += 256) {
        int r = c >> 2, q = (c & 3) * 8;
        cp_async16(&As[r][q], &A[(size_t)(rowBase + r) * 64 + q]);
    }
    #pragma unroll
    for (int c = tid; c < 512; c += 256) {
        int r = c >> 4, q = (c & 15) * 8;
        cp_async16(&Bs[r][q], &B[(size_t)r * EDIM + colBase + q]);
    }
    cp_commit(); cp_wait<0>(); __syncthreads();

    float acc[4][4][4];
    #pragma unroll
    for (int i = 0; i < 4; i++)
        #pragma unroll
        for (int j = 0; j < 4; j++)
            #pragma unroll
            for (int q = 0; q < 4; q++) acc[i][j][q] = 0.0f;

    const int arow = lane & 15, acol = (lane >> 4) * 8;
    const int bq = lane >> 3, bl = lane & 7;
    const int bk = (bq & 1) * 8 + bl, bn = (bq >> 1) * 8;

    #pragma unroll
    for (int ks = 0; ks < 2; ks++) {
        uint32_t a[4][4];
        #pragma unroll
        for (int mt = 0; mt < 4; mt++)
            ldsm_x4(a[mt][0], a[mt][1], a[mt][2], a[mt][3],
                    smem_u32(&As[wm + mt * 16 + arow][ks * 16 + acol]));
        uint32_t b[4][2];
        #pragma unroll
        for (int nt2 = 0; nt2 < 2; nt2++) {
            uint32_t r0, r1, r2, r3;
            ldsm_x4_t(r0, r1, r2, r3,
                      smem_u32(&Bs[ks * 16 + bk][wn + nt2 * 16 + bn]));
            b[2 * nt2][0] = r0; b[2 * nt2][1] = r1;
            b[2 * nt2 + 1][0] = r2; b[2 * nt2 + 1][1] = r3;
        }
        #pragma unroll
        for (int mt = 0; mt < 4; mt++)
            #pragma unroll
            for (int nt = 0; nt < 4; nt++)
                mma_bf16(acc[mt][nt][0], acc[mt][nt][1], acc[mt][nt][2], acc[mt][nt][3],
                         a[mt][0], a[mt][1], a[mt][2], a[mt][3],
                         b[nt][0], b[nt][1]);
    }

    const int bb = rowBase >> 11;
    const int tb = rowBase & 2047;
    #pragma unroll
    for (int cc = 0; cc < 4; cc++) {
        __syncthreads();
        if (wn == cc * 32) {
            #pragma unroll
            for (int mt = 0; mt < 4; mt++)
                #pragma unroll
                for (int nt = 0; nt < 4; nt++) {
                    int c = nt * 8 + (lane & 3) * 2;
                    int col = colBase + wn + c;
                    #pragma unroll
                    for (int h = 0; h < 2; h++) {
                        int r = wm + mt * 16 + (lane >> 2) + h * 8;
                        sbuf[c][r]     = softplus_f(acc[mt][nt][2 * h]     + bias[col]);
                        sbuf[c + 1][r] = softplus_f(acc[mt][nt][2 * h + 1] + bias[col + 1]);
                    }
                }
        }
        __syncthreads();
        for (int j = tid; j < 32 * 128; j += 256) {
            int c = j >> 7, r = j & 127;
            dtT[((size_t)bb * EDIM + colBase + cc * 32 + c) * LSEQ + tb + r] = sbuf[c][r];
        }
    }
}

// ---------------- fused conv+silu+transposes (float2 smem accesses) ----------------
__global__ void __launch_bounds__(256)
conv_fused_kernel(const bf16* __restrict__ xzb,
                  const float* __restrict__ conv_w,
                  const float* __restrict__ conv_b,
                  bf16* __restrict__ xsb,
                  float* __restrict__ xsT,
                  bf16* __restrict__ zT) {
    __shared__ __align__(8) float xt[35][66];
    __shared__ __align__(8) float st[32][66];
    __shared__ bf16  zt[32][66];

    const int e0 = blockIdx.x * 64;
    const int t0 = blockIdx.y * 32;
    const int b  = blockIdx.z;
    const int tx = threadIdx.x & 31, ty = threadIdx.x >> 5;

    for (int i = ty; i < 35; i += 8) {
        int t = t0 - 3 + i;
        uint32_t pv = 0;
        if (t >= 0)
            pv = *(const uint32_t*)&xzb[((size_t)(b * LSEQ + t)) * (2 * EDIM) + e0 + 2 * tx];
        bf16 p[2]; *(uint32_t*)p = pv;
        *(float2*)&xt[i][2 * tx] = make_float2(__bfloat162float(p[0]), __bfloat162float(p[1]));
    }
    for (int i = ty; i < 32; i += 8) {
        uint32_t pv = *(const uint32_t*)&xzb[((size_t)(b * LSEQ + t0 + i)) * (2 * EDIM) + EDIM + e0 + 2 * tx];
        *(uint32_t*)&zt[i][2 * tx] = pv;
    }
    __syncthreads();

    const int ea = e0 + 2 * tx, ebx = ea + 1;
    const float w0a = conv_w[ea * 4 + 0], w1a = conv_w[ea * 4 + 1],
                w2a = conv_w[ea * 4 + 2], w3a = conv_w[ea * 4 + 3], bba = conv_b[ea];
    const float w0b = conv_w[ebx * 4 + 0], w1b = conv_w[ebx * 4 + 1],
                w2b = conv_w[ebx * 4 + 2], w3b = conv_w[ebx * 4 + 3], bbb = conv_b[ebx];

    for (int i = ty; i < 32; i += 8) {
        float2 v0 = *(const float2*)&xt[i][2 * tx];
        float2 v1 = *(const float2*)&xt[i + 1][2 * tx];
        float2 v2 = *(const float2*)&xt[i + 2][2 * tx];
        float2 v3 = *(const float2*)&xt[i + 3][2 * tx];
        float a0 = bba + w0a * v0.x + w1a * v1.x + w2a * v2.x + w3a * v3.x;
        float a1 = bbb + w0b * v0.y + w1b * v1.y + w2b * v2.y + w3b * v3.y;
        float s0 = a0 / (1.0f + __expf(-a0));
        float s1 = a1 / (1.0f + __expf(-a1));
        *(float2*)&st[i][2 * tx] = make_float2(s0, s1);
        bf16 o[2] = {__float2bfloat16(s0), __float2bfloat16(s1)};
        *(uint32_t*)&xsb[((size_t)(b * LSEQ + t0 + i)) * EDIM + e0 + 2 * tx] = *(uint32_t*)o;
    }
    __syncthreads();

    for (int i = ty; i < 64; i += 8) {
        xsT[((size_t)b * EDIM + e0 + i) * LSEQ + t0 + tx] = st[tx][i];
        zT [((size_t)b * EDIM + e0 + i) * LSEQ + t0 + tx] = zt[tx][i];
    }
}

// ---------------- chunked parallel selective scan (R8 version: 8 warps/block) ----------------
#define CHUNK 64
#define BC_SMEM_BYTES 131072
#define YSTAGE_BYTES  (8 * (LSEQ + 32) * 2)
#define SCAN_SMEM (BC_SMEM_BYTES + YSTAGE_BYTES)

__device__ __forceinline__ const uint4* bc_addr(const char* bcs, int t, int c) {
    int slot = ((t & 1) * 4 + c) ^ ((t >> 6) & 7);
    return (const uint4*)(bcs + (t >> 1) * 128 + slot * 16);
}

__global__ void __launch_bounds__(256)
scan_kernel(const float* __restrict__ dtT,
            const float* __restrict__ xsT,
            const bf16*  __restrict__ zT,
            const bf16*  __restrict__ bcb,
            const float* __restrict__ A_log,
            const float* __restrict__ D_skip,
            bf16* __restrict__ y) {
    extern __shared__ __align__(16) char dyn[];
    char* bcs = dyn;
    bf16 (*ystage)[LSEQ + 32] = (bf16 (*)[LSEQ + 32])(dyn + BC_SMEM_BYTES);

    const int b    = blockIdx.y;
    const int warp = threadIdx.x >> 5;
    const int lane = threadIdx.x & 31;
    const int e    = blockIdx.x * 8 + warp;

    {
        const bf16* src = bcb + (size_t)b * LSEQ * 32;
        for (int k = threadIdx.x; k < 8192; k += 256) {
            int t = k >> 2, c = k & 3;
            int slot = ((t & 1) * 4 + c) ^ ((t >> 6) & 7);
            cp_async16(bcs + (t >> 1) * 128 + slot * 16, src + k * 8);
        }
        cp_commit(); cp_wait<0>();
    }
    __syncthreads();

    float Acoef[NST];
    bool structured = true;
    #pragma unroll
    for (int n = 0; n < NST; n++) {
        Acoef[n] = -__expf(A_log[e * NST + n]);
        structured &= fabsf(Acoef[n] + (float)(n + 1)) < 1e-4f * (float)(n + 1);
    }
    const float dsk = D_skip[e];

    const float* dtp = dtT + ((size_t)b * EDIM + e) * LSEQ;
    const float* xsp = xsT + ((size_t)b * EDIM + e) * LSEQ;
    const bf16*  zp  = zT  + ((size_t)b * EDIM + e) * LSEQ;

    const int t0 = lane * CHUNK;

    float P[NST], q[NST];
    #pragma unroll
    for (int n = 0; n < NST; n++) { P[n] = 1.0f; q[n] = 0.0f; }

    for (int s4 = 0; s4 < CHUNK; s4 += 4) {
        float4 d4 = *(const float4*)&dtp[t0 + s4];
        float4 x4 = *(const float4*)&xsp[t0 + s4];
        float dv[4] = {d4.x, d4.y, d4.z, d4.w};
        float xv[4] = {x4.x, x4.y, x4.z, x4.w};
        #pragma unroll
        for (int u = 0; u < 4; u++) {
            const int t = t0 + s4 + u;
            float Bv[NST];
            unpack8(*bc_addr(bcs, t, 0), Bv);
            unpack8(*bc_addr(bcs, t, 1), Bv + 8);
            float dA[NST];
            compute_dA(dv[u], Acoef, structured, dA);
            const float dx = dv[u] * xv[u];
            #pragma unroll
            for (int n = 0; n < NST; n++) {
                q[n] = fmaf(dA[n], q[n], dx * Bv[n]);
                P[n] *= dA[n];
            }
        }
    }

    #pragma unroll
    for (int d = 1; d < 32; d <<= 1) {
        #pragma unroll
        for (int n = 0; n < NST; n++) {
            float Pp = __shfl_up_sync(0xffffffffu, P[n], d);
            float qp = __shfl_up_sync(0xffffffffu, q[n], d);
            if (lane >= d) {
                q[n] = fmaf(P[n], qp, q[n]);
                P[n] *= Pp;
            }
        }
    }
    float h[NST];
    #pragma unroll
    for (int n = 0; n < NST; n++) {
        float v = __shfl_up_sync(0xffffffffu, q[n], 1);
        h[n] = (lane == 0) ? 0.0f : v;
    }

    for (int s8 = 0; s8 < CHUNK; s8 += 8) {
        float4 d4a = *(const float4*)&dtp[t0 + s8];
        float4 d4b = *(const float4*)&dtp[t0 + s8 + 4];
        float4 x4a = *(const float4*)&xsp[t0 + s8];
        float4 x4b = *(const float4*)&xsp[t0 + s8 + 4];
        uint4  zv8 = *(const uint4*)&zp[t0 + s8];
        float dv[8] = {d4a.x, d4a.y, d4a.z, d4a.w, d4b.x, d4b.y, d4b.z, d4b.w};
        float xv[8] = {x4a.x, x4a.y, x4a.z, x4a.w, x4b.x, x4b.y, x4b.z, x4b.w};
        float zv[8];
        unpack8(zv8, zv);
        #pragma unroll
        for (int u = 0; u < 8; u++) {
            const int t = t0 + s8 + u;
            float Bv[NST], Cv[NST];
            unpack8(*bc_addr(bcs, t, 0), Bv);
            unpack8(*bc_addr(bcs, t, 1), Bv + 8);
            unpack8(*bc_addr(bcs, t, 2), Cv);
            unpack8(*bc_addr(bcs, t, 3), Cv + 8);
            float dA[NST];
            compute_dA(dv[u], Acoef, structured, dA);
            const float dx = dv[u] * xv[u];
            float yacc0 = 0.0f, yacc1 = 0.0f;
            #pragma unroll
            for (int n = 0; n < NST; n += 2) {
                h[n]     = fmaf(dA[n],     h[n],     dx * Bv[n]);
                h[n + 1] = fmaf(dA[n + 1], h[n + 1], dx * Bv[n + 1]);
                yacc0 = fmaf(h[n],     Cv[n],     yacc0);
                yacc1 = fmaf(h[n + 1], Cv[n + 1], yacc1);
            }
            const float zz  = zv[u];
            const float sig = 1.0f / (1.0f + __expf(-zz));
            const float out = ((yacc0 + yacc1) + xv[u] * dsk) * (zz * sig);
            ystage[warp][t + (t >> 6)] = __float2bfloat16(out);
        }
    }
    __syncthreads();

    const int e0 = blockIdx.x * 8;
    for (int t = threadIdx.x; t < LSEQ; t += 256) {
        bf16 v[8];
        #pragma unroll
        for (int w = 0; w < 8; w++) v[w] = ystage[w][t + (t >> 6)];
        *(uint4*)&y[((size_t)(b * LSEQ + t)) * EDIM + e0] = *(uint4*)v;
    }
}

// ---------------- launcher ----------------
extern "C" void kernel_launch(void* const* d_in, const int* in_sizes, int n_in,
                              void* d_out, int out_size) {
    const float* hidden = (const float*)d_in[0];
    const float* norm_w = (const float*)d_in[1];
    const float* W_in   = (const float*)d_in[2];
    const float* conv_w = (const float*)d_in[3];
    const float* conv_b = (const float*)d_in[4];
    const float* W_x    = (const float*)d_in[5];
    const float* W_dt   = (const float*)d_in[6];
    const float* b_dt   = (const float*)d_in[7];
    const float* A_log  = (const float*)d_in[8];
    const float* D_skip = (const float*)d_in[9];
    const float* W_out  = (const float*)d_in[10];
    float* out = (float*)d_out;

    float *p_dtT, *p_xsT;
    bf16 *p_xzb, *p_zT, *p_nrmb, *p_xsb, *p_dblb, *p_bcb, *p_yb;
    bf16 *p_winb, *p_wxb, *p_wdtb, *p_woutb;
    cudaGetSymbolAddress((void**)&p_xzb,  g_xzb);
    cudaGetSymbolAddress((void**)&p_dtT,  g_dtT);
    cudaGetSymbolAddress((void**)&p_xsT,  g_xsT);
    cudaGetSymbolAddress((void**)&p_zT,   g_zT);
    cudaGetSymbolAddress((void**)&p_nrmb, g_nrmb);
    cudaGetSymbolAddress((void**)&p_xsb,  g_xsb);
    cudaGetSymbolAddress((void**)&p_dblb, g_dblb);
    cudaGetSymbolAddress((void**)&p_bcb,  g_bcb);
    cudaGetSymbolAddress((void**)&p_yb,   g_yb);
    cudaGetSymbolAddress((void**)&p_winb, g_winb);
    cudaGetSymbolAddress((void**)&p_wxb,  g_wxb);
    cudaGetSymbolAddress((void**)&p_wdtb, g_wdtb);
    cudaGetSymbolAddress((void**)&p_woutb, g_woutb);

    cudaFuncSetAttribute(scan_kernel, cudaFuncAttributeMaxDynamicSharedMemorySize, SCAN_SMEM);
    cudaFuncSetAttribute(gemm_bf16<128, 128, 2, 4, 5>,
                         cudaFuncAttributeMaxDynamicSharedMemorySize, GEMM_BIG_SMEM);
    cudaFuncSetAttribute(gemm_bf16<128, 128, 2, 4, 2>,
                         cudaFuncAttributeMaxDynamicSharedMemorySize, GEMM_BIG_SMEM);
    cudaFuncSetAttribute(gemm_bf16<64, 64, 4, 2, 6>,
                         cudaFuncAttributeMaxDynamicSharedMemorySize, GEMM_DBL_SMEM);

    // 0) fused weight conversion
    {
        int total = (N_WIN + N_WX + N_WDT + N_WOUT) / 4;
        wconv_kernel<<<(total + 255) / 256, 256>>>(W_in, p_winb, W_x, p_wxb,
                                                   W_dt, p_wdtb, W_out, p_woutb);
    }

    // 1) RMSNorm -> bf16
    rmsnorm_kernel<<<NTOK, 128>>>(hidden, norm_w, p_nrmb);

    // 2) xz = nrm @ W_in -> bf16 only
    gemm_bf16<128, 128, 2, 4, 5><<<dim3(2 * EDIM / 128, NTOK / 128), 256, GEMM_BIG_SMEM>>>(
        p_nrmb, DDIM, p_winb, 2 * EDIM, nullptr, 2 * EDIM,
        NTOK, 2 * EDIM, DDIM, nullptr, p_xzb, nullptr);

    // 3) fused conv + silu + transposes
    conv_fused_kernel<<<dim3(EDIM / 64, LSEQ / 32, BSZ), 256>>>(
        p_xzb, conv_w, conv_b, p_xsb, p_xsT, p_zT);

    // 4) dbl = xs @ W_x -> bf16 full + bf16 compact BC
    gemm_bf16<64, 64, 4, 2, 6><<<dim3(1, NTOK / 64), 256, GEMM_DBL_SMEM>>>(
        p_xsb, EDIM, p_wxb, 64, nullptr, 64,
        NTOK, 64, EDIM, nullptr, p_dblb, p_bcb);

    // 5) dtT = softplus(dbl[:, :32] @ W_dt + b_dt), transposed write
    dtgemm_kernel<<<dim3(EDIM / 128, NTOK / 128), 256>>>(p_dblb, p_wdtb, b_dt, p_dtT);

    // 6) chunked parallel scan (smem B/C) + gate -> bf16 y
    scan_kernel<<<dim3(EDIM / 8, BSZ), 256, SCAN_SMEM>>>(
        p_dtT, p_xsT, p_zT, p_bcb, A_log, D_skip, p_yb);

    // 7) out = y @ W_out + hidden -> fp32
    gemm_bf16<128, 128, 2, 4, 2><<<dim3(DDIM / 128, NTOK / 128), 256, GEMM_BIG_SMEM>>>(
        p_yb, EDIM, p_woutb, DDIM, out, DDIM,
        NTOK, DDIM, EDIM, hidden, nullptr, nullptr);
}

// round 12
// speedup vs baseline: 1.2037x; 1.1071x over previous
#include <cuda_runtime.h>
#include <cuda_bf16.h>
#include <cstdint>

using bf16 = __nv_bfloat16;

// Problem constants
#define BSZ 4
#define LSEQ 2048
#define DDIM 512
#define EDIM 1024
#define NST 16
#define RRANK 32
#define NTOK (BSZ * LSEQ)          // 8192

// ---------------- scratch (device globals) ----------------
__device__ bf16  g_xzb[NTOK * 2 * EDIM];
__device__ float g_dtT[NTOK * EDIM];
__device__ float g_xsT[NTOK * EDIM];
__device__ bf16  g_zT [NTOK * EDIM];
__device__ bf16  g_nrmb[NTOK * DDIM];
__device__ bf16  g_xsb [NTOK * EDIM];
__device__ bf16  g_dblb[NTOK * 64];
__device__ bf16  g_bcb [NTOK * 32];
__device__ bf16  g_yb  [NTOK * EDIM];
__device__ bf16  g_winb [DDIM * 2 * EDIM];
__device__ bf16  g_wxb  [EDIM * 64];
__device__ bf16  g_wdtb [RRANK * EDIM];
__device__ bf16  g_woutb[EDIM * DDIM];

// ---------------- PTX helpers ----------------
__device__ __forceinline__ uint32_t smem_u32(const void* p) {
    return (uint32_t)__cvta_generic_to_shared(p);
}
__device__ __forceinline__ void cp_async16(void* s, const void* g) {
    asm volatile("cp.async.cg.shared.global [%0], [%1], 16;\n"
                 :: "r"(smem_u32(s)), "l"(g));
}
__device__ __forceinline__ void cp_commit() { asm volatile("cp.async.commit_group;\n"); }
template <int N> __device__ __forceinline__ void cp_wait() {
    asm volatile("cp.async.wait_group %0;\n" :: "n"(N));
}
__device__ __forceinline__ void ldsm_x4(uint32_t& r0, uint32_t& r1, uint32_t& r2, uint32_t& r3,
                                        uint32_t a) {
    asm volatile("ldmatrix.sync.aligned.m8n8.x4.shared.b16 {%0,%1,%2,%3}, [%4];\n"
                 : "=r"(r0), "=r"(r1), "=r"(r2), "=r"(r3) : "r"(a));
}
__device__ __forceinline__ void ldsm_x4_t(uint32_t& r0, uint32_t& r1, uint32_t& r2, uint32_t& r3,
                                          uint32_t a) {
    asm volatile("ldmatrix.sync.aligned.m8n8.x4.trans.shared.b16 {%0,%1,%2,%3}, [%4];\n"
                 : "=r"(r0), "=r"(r1), "=r"(r2), "=r"(r3) : "r"(a));
}
__device__ __forceinline__ void mma_bf16(float& d0, float& d1, float& d2, float& d3,
                                         uint32_t a0, uint32_t a1, uint32_t a2, uint32_t a3,
                                         uint32_t b0, uint32_t b1) {
    asm volatile("mma.sync.aligned.m16n8k16.row.col.f32.bf16.bf16.f32 "
                 "{%0,%1,%2,%3}, {%4,%5,%6,%7}, {%8,%9}, {%0,%1,%2,%3};\n"
                 : "+f"(d0), "+f"(d1), "+f"(d2), "+f"(d3)
                 : "r"(a0), "r"(a1), "r"(a2), "r"(a3), "r"(b0), "r"(b1));
}
__device__ __forceinline__ float softplus_f(float v) {
    return (v > 20.0f) ? v : log1pf(expf(v));
}
__device__ __forceinline__ void unpack8(uint4 v, float* f) {
    uint32_t u[4] = {v.x, v.y, v.z, v.w};
    #pragma unroll
    for (int j = 0; j < 4; j++) {
        f[2 * j]     = __uint_as_float(u[j] << 16);
        f[2 * j + 1] = __uint_as_float(u[j] & 0xffff0000u);
    }
}
// dA[n] = exp(dtv * Acoef[n]); fast path when Acoef[n] == -(n+1).
__device__ __forceinline__ void compute_dA(float dtv, const float* Acoef,
                                           bool structured, float* dA) {
    if (structured) {
        const float r1 = __expf(-dtv);
        const float r2 = r1 * r1;
        const float r4 = r2 * r2;
        const float r8 = r4 * r4;
        dA[0] = r1;       dA[1] = r2;       dA[2] = r2 * r1;  dA[3] = r4;
        dA[4] = r4 * r1;  dA[5] = r4 * r2;  dA[6] = r4 * dA[2]; dA[7] = r8;
        dA[8]  = r8 * r1;   dA[9]  = r8 * r2;   dA[10] = r8 * dA[2]; dA[11] = r8 * r4;
        dA[12] = r8 * dA[4]; dA[13] = r8 * dA[5]; dA[14] = r8 * dA[6]; dA[15] = r8 * r8;
    } else {
        #pragma unroll
        for (int n = 0; n < NST; n++) dA[n] = __expf(dtv * Acoef[n]);
    }
}

// ---------------- fused weight conversion ----------------
#define N_WIN  (DDIM * 2 * EDIM)
#define N_WX   (EDIM * 64)
#define N_WDT  (RRANK * EDIM)
#define N_WOUT (EDIM * DDIM)
__global__ void wconv_kernel(const float* __restrict__ w_in,  bf16* __restrict__ o_in,
                             const float* __restrict__ w_x,   bf16* __restrict__ o_x,
                             const float* __restrict__ w_dt,  bf16* __restrict__ o_dt,
                             const float* __restrict__ w_out, bf16* __restrict__ o_out) {
    int i = (blockIdx.x * blockDim.x + threadIdx.x) * 4;
    const float* src; bf16* dst; int off;
    if (i < N_WIN)                      { src = w_in;  dst = o_in;  off = i; }
    else if (i < N_WIN + N_WX)          { src = w_x;   dst = o_x;   off = i - N_WIN; }
    else if (i < N_WIN + N_WX + N_WDT)  { src = w_dt;  dst = o_dt;  off = i - N_WIN - N_WX; }
    else if (i < N_WIN + N_WX + N_WDT + N_WOUT)
                                        { src = w_out; dst = o_out; off = i - N_WIN - N_WX - N_WDT; }
    else return;
    float4 v = *(const float4*)(src + off);
    bf16 o[4] = {__float2bfloat16(v.x), __float2bfloat16(v.y),
                 __float2bfloat16(v.z), __float2bfloat16(v.w)};
    *(uint64_t*)(dst + off) = *(uint64_t*)o;
}

// ---------------- RMSNorm -> bf16 ----------------
__global__ void rmsnorm_kernel(const float* __restrict__ x,
                               const float* __restrict__ w,
                               bf16* __restrict__ out) {
    int row = blockIdx.x;
    int tid = threadIdx.x;
    float4 v = ((const float4*)(x + (size_t)row * DDIM))[tid];
    float ss = v.x * v.x + v.y * v.y + v.z * v.z + v.w * v.w;
    #pragma unroll
    for (int o = 16; o > 0; o >>= 1) ss += __shfl_xor_sync(0xffffffffu, ss, o);
    __shared__ float sred[4];
    if ((tid & 31) == 0) sred[tid >> 5] = ss;
    __syncthreads();
    float tot = sred[0] + sred[1] + sred[2] + sred[3];
    float scale = rsqrtf(tot * (1.0f / DDIM) + 1e-6f);
    float4 wv = ((const float4*)w)[tid];
    bf16 o[4] = {__float2bfloat16(v.x * scale * wv.x),
                 __float2bfloat16(v.y * scale * wv.y),
                 __float2bfloat16(v.z * scale * wv.z),
                 __float2bfloat16(v.w * scale * wv.w)};
    *(uint64_t*)(out + (size_t)row * DDIM + tid * 4) = *(uint64_t*)o;
}

// ---------------- bf16 tensor-core GEMM, 3-stage cp.async pipeline ----------------
// EPI: 2 fp32 + resid | 5 bf16 C2 only | 6 bf16 C2 + compact bf16 C3 (cols>=32)
template <int BM, int BN, int WGM, int WGN, int EPI>
__global__ void __launch_bounds__(WGM * WGN * 32)
gemm_bf16(const bf16* __restrict__ A, int lda,
          const bf16* __restrict__ B, int ldb,
          float* __restrict__ C, int ldc,
          int M, int N, int K,
          const float* __restrict__ resid,
          bf16* __restrict__ C2,
          bf16* __restrict__ C3) {
    constexpr int BK = 32;
    constexpr int NTHR = WGM * WGN * 32;
    constexpr int WM = BM / WGM;
    constexpr int WN = BN / WGN;
    constexpr int MT = WM / 16;
    constexpr int NT = WN / 8;
    static_assert(NT % 2 == 0, "NT even");
    constexpr int LDAS = BK + 8;
    constexpr int LDBS = BN + 8;
    constexpr int SA_ELEM = BM * LDAS;
    constexpr int SB_ELEM = BK * LDBS;
    constexpr int STAGE = SA_ELEM + SB_ELEM;

    extern __shared__ __align__(16) bf16 smem[];

    const int tid = threadIdx.x;
    const int warp = tid >> 5, lane = tid & 31;
    const int wm = (warp % WGM) * WM;
    const int wn = (warp / WGM) * WN;
    const int rowBase = blockIdx.y * BM;
    const int colBase = blockIdx.x * BN;

    float acc[MT][NT][4];
    #pragma unroll
    for (int i = 0; i < MT; i++)
        #pragma unroll
        for (int j = 0; j < NT; j++)
            #pragma unroll
            for (int q = 0; q < 4; q++) acc[i][j][q] = 0.0f;

    constexpr int A_CHUNKS = BM * BK / 8;
    constexpr int B_CHUNKS = BK * BN / 8;

    auto load_tile = [&](int s, int k0) {
        bf16* As = smem + s * STAGE;
        bf16* Bs = As + SA_ELEM;
        #pragma unroll
        for (int c = tid; c < A_CHUNKS; c += NTHR) {
            int row = c / (BK / 8);
            int col = (c % (BK / 8)) * 8;
            cp_async16(&As[row * LDAS + col],
                       &A[(size_t)(rowBase + row) * lda + k0 + col]);
        }
        #pragma unroll
        for (int c = tid; c < B_CHUNKS; c += NTHR) {
            int row = c / (BN / 8);
            int col = (c % (BN / 8)) * 8;
            cp_async16(&Bs[row * LDBS + col],
                       &B[(size_t)(k0 + row) * ldb + colBase + col]);
        }
        cp_commit();
    };

    const int KT = K / BK;
    load_tile(0, 0);
    if (KT > 1) load_tile(1, BK);

    const int arow = lane & 15, acol = (lane >> 4) * 8;
    const int bq = lane >> 3, bl = lane & 7;
    const int bk = (bq & 1) * 8 + bl, bn = (bq >> 1) * 8;

    int sbuf = 0;
    for (int kt = 0; kt < KT; kt++) {
        if (kt + 2 < KT) cp_wait<1>(); else cp_wait<0>();
        __syncthreads();
        if (kt + 2 < KT) {
            int s2 = sbuf + 2; if (s2 >= 3) s2 -= 3;
            load_tile(s2, (kt + 2) * BK);
        }
        const bf16* As = smem + sbuf * STAGE;
        const bf16* Bs = As + SA_ELEM;

        #pragma unroll
        for (int ks = 0; ks < 2; ks++) {
            uint32_t a[MT][4];
            #pragma unroll
            for (int mt = 0; mt < MT; mt++)
                ldsm_x4(a[mt][0], a[mt][1], a[mt][2], a[mt][3],
                        smem_u32(&As[(wm + mt * 16 + arow) * LDAS + ks * 16 + acol]));
            uint32_t b[NT][2];
            #pragma unroll
            for (int nt2 = 0; nt2 < NT / 2; nt2++) {
                uint32_t r0, r1, r2, r3;
                ldsm_x4_t(r0, r1, r2, r3,
                          smem_u32(&Bs[(ks * 16 + bk) * LDBS + wn + nt2 * 16 + bn]));
                b[2 * nt2][0] = r0; b[2 * nt2][1] = r1;
                b[2 * nt2 + 1][0] = r2; b[2 * nt2 + 1][1] = r3;
            }
            #pragma unroll
            for (int mt = 0; mt < MT; mt++)
                #pragma unroll
                for (int nt = 0; nt < NT; nt++)
                    mma_bf16(acc[mt][nt][0], acc[mt][nt][1], acc[mt][nt][2], acc[mt][nt][3],
                             a[mt][0], a[mt][1], a[mt][2], a[mt][3],
                             b[nt][0], b[nt][1]);
        }
        if (++sbuf == 3) sbuf = 0;
    }

    #pragma unroll
    for (int mt = 0; mt < MT; mt++) {
        #pragma unroll
        for (int nt = 0; nt < NT; nt++) {
            int col = colBase + wn + nt * 8 + (lane & 3) * 2;
            #pragma unroll
            for (int h = 0; h < 2; h++) {
                int row = rowBase + wm + mt * 16 + (lane >> 2) + h * 8;
                float v0 = acc[mt][nt][2 * h + 0];
                float v1 = acc[mt][nt][2 * h + 1];
                if (EPI == 2) {
                    const float2 r = *(const float2*)&resid[(size_t)row * ldc + col];
                    v0 += r.x; v1 += r.y;
                    *(float2*)&C[(size_t)row * ldc + col] = make_float2(v0, v1);
                }
                if (EPI == 5 || EPI == 6) {
                    bf16 o[2] = {__float2bfloat16(v0), __float2bfloat16(v1)};
                    *(uint32_t*)&C2[(size_t)row * ldc + col] = *(uint32_t*)o;
                    if (EPI == 6 && col >= RRANK)
                        *(uint32_t*)&C3[(size_t)row * 32 + col - RRANK] = *(uint32_t*)o;
                }
            }
        }
    }
}
#define GEMM_BIG_SMEM  (3 * (128 * 40 + 32 * 136) * 2)   // 56832
#define GEMM_DBL_SMEM  (3 * (64 * 40 + 32 * 72) * 2)     // 29184

// ---------------- dedicated dt GEMM ----------------
__global__ void __launch_bounds__(256)
dtgemm_kernel(const bf16* __restrict__ A,
              const bf16* __restrict__ B,
              const float* __restrict__ bias,
              float* __restrict__ dtT) {
    __shared__ __align__(16) bf16 As[128][40];
    __shared__ __align__(16) bf16 Bs[32][136];
    __shared__ float sbuf[32][129];

    const int tid = threadIdx.x, warp = tid >> 5, lane = tid & 31;
    const int wm = (warp & 1) * 64;
    const int wn = (warp >> 1) * 32;
    const int rowBase = blockIdx.y * 128;
    const int colBase = blockIdx.x * 128;

    #pragma unroll
    for (int c = tid; c < 512; c += 256) {
        int r = c >> 2, q = (c & 3) * 8;
        cp_async16(&As[r][q], &A[(size_t)(rowBase + r) * 64 + q]);
    }
    #pragma unroll
    for (int c = tid; c < 512; c += 256) {
        int r = c >> 4, q = (c & 15) * 8;
        cp_async16(&Bs[r][q], &B[(size_t)r * EDIM + colBase + q]);
    }
    cp_commit(); cp_wait<0>(); __syncthreads();

    float acc[4][4][4];
    #pragma unroll
    for (int i = 0; i < 4; i++)
        #pragma unroll
        for (int j = 0; j < 4; j++)
            #pragma unroll
            for (int q = 0; q < 4; q++) acc[i][j][q] = 0.0f;

    const int arow = lane & 15, acol = (lane >> 4) * 8;
    const int bq = lane >> 3, bl = lane & 7;
    const int bk = (bq & 1) * 8 + bl, bn = (bq >> 1) * 8;

    #pragma unroll
    for (int ks = 0; ks < 2; ks++) {
        uint32_t a[4][4];
        #pragma unroll
        for (int mt = 0; mt < 4; mt++)
            ldsm_x4(a[mt][0], a[mt][1], a[mt][2], a[mt][3],
                    smem_u32(&As[wm + mt * 16 + arow][ks * 16 + acol]));
        uint32_t b[4][2];
        #pragma unroll
        for (int nt2 = 0; nt2 < 2; nt2++) {
            uint32_t r0, r1, r2, r3;
            ldsm_x4_t(r0, r1, r2, r3,
                      smem_u32(&Bs[ks * 16 + bk][wn + nt2 * 16 + bn]));
            b[2 * nt2][0] = r0; b[2 * nt2][1] = r1;
            b[2 * nt2 + 1][0] = r2; b[2 * nt2 + 1][1] = r3;
        }
        #pragma unroll
        for (int mt = 0; mt < 4; mt++)
            #pragma unroll
            for (int nt = 0; nt < 4; nt++)
                mma_bf16(acc[mt][nt][0], acc[mt][nt][1], acc[mt][nt][2], acc[mt][nt][3],
                         a[mt][0], a[mt][1], a[mt][2], a[mt][3],
                         b[nt][0], b[nt][1]);
    }

    const int bb = rowBase >> 11;
    const int tb = rowBase & 2047;
    #pragma unroll
    for (int cc = 0; cc < 4; cc++) {
        __syncthreads();
        if (wn == cc * 32) {
            #pragma unroll
            for (int mt = 0; mt < 4; mt++)
                #pragma unroll
                for (int nt = 0; nt < 4; nt++) {
                    int c = nt * 8 + (lane & 3) * 2;
                    int col = colBase + wn + c;
                    #pragma unroll
                    for (int h = 0; h < 2; h++) {
                        int r = wm + mt * 16 + (lane >> 2) + h * 8;
                        sbuf[c][r]     = softplus_f(acc[mt][nt][2 * h]     + bias[col]);
                        sbuf[c + 1][r] = softplus_f(acc[mt][nt][2 * h + 1] + bias[col + 1]);
                    }
                }
        }
        __syncthreads();
        for (int j = tid; j < 32 * 128; j += 256) {
            int c = j >> 7, r = j & 127;
            dtT[((size_t)bb * EDIM + colBase + cc * 32 + c) * LSEQ + tb + r] = sbuf[c][r];
        }
    }
}

// ---------------- fused conv+silu+transposes (float2 smem accesses) ----------------
__global__ void __launch_bounds__(256)
conv_fused_kernel(const bf16* __restrict__ xzb,
                  const float* __restrict__ conv_w,
                  const float* __restrict__ conv_b,
                  bf16* __restrict__ xsb,
                  float* __restrict__ xsT,
                  bf16* __restrict__ zT) {
    __shared__ __align__(8) float xt[35][66];
    __shared__ __align__(8) float st[32][66];
    __shared__ bf16  zt[32][66];

    const int e0 = blockIdx.x * 64;
    const int t0 = blockIdx.y * 32;
    const int b  = blockIdx.z;
    const int tx = threadIdx.x & 31, ty = threadIdx.x >> 5;

    for (int i = ty; i < 35; i += 8) {
        int t = t0 - 3 + i;
        uint32_t pv = 0;
        if (t >= 0)
            pv = *(const uint32_t*)&xzb[((size_t)(b * LSEQ + t)) * (2 * EDIM) + e0 + 2 * tx];
        bf16 p[2]; *(uint32_t*)p = pv;
        *(float2*)&xt[i][2 * tx] = make_float2(__bfloat162float(p[0]), __bfloat162float(p[1]));
    }
    for (int i = ty; i < 32; i += 8) {
        uint32_t pv = *(const uint32_t*)&xzb[((size_t)(b * LSEQ + t0 + i)) * (2 * EDIM) + EDIM + e0 + 2 * tx];
        *(uint32_t*)&zt[i][2 * tx] = pv;
    }
    __syncthreads();

    const int ea = e0 + 2 * tx, ebx = ea + 1;
    const float w0a = conv_w[ea * 4 + 0], w1a = conv_w[ea * 4 + 1],
                w2a = conv_w[ea * 4 + 2], w3a = conv_w[ea * 4 + 3], bba = conv_b[ea];
    const float w0b = conv_w[ebx * 4 + 0], w1b = conv_w[ebx * 4 + 1],
                w2b = conv_w[ebx * 4 + 2], w3b = conv_w[ebx * 4 + 3], bbb = conv_b[ebx];

    for (int i = ty; i < 32; i += 8) {
        float2 v0 = *(const float2*)&xt[i][2 * tx];
        float2 v1 = *(const float2*)&xt[i + 1][2 * tx];
        float2 v2 = *(const float2*)&xt[i + 2][2 * tx];
        float2 v3 = *(const float2*)&xt[i + 3][2 * tx];
        float a0 = bba + w0a * v0.x + w1a * v1.x + w2a * v2.x + w3a * v3.x;
        float a1 = bbb + w0b * v0.y + w1b * v1.y + w2b * v2.y + w3b * v3.y;
        float s0 = a0 / (1.0f + __expf(-a0));
        float s1 = a1 / (1.0f + __expf(-a1));
        *(float2*)&st[i][2 * tx] = make_float2(s0, s1);
        bf16 o[2] = {__float2bfloat16(s0), __float2bfloat16(s1)};
        *(uint32_t*)&xsb[((size_t)(b * LSEQ + t0 + i)) * EDIM + e0 + 2 * tx] = *(uint32_t*)o;
    }
    __syncthreads();

    for (int i = ty; i < 64; i += 8) {
        xsT[((size_t)b * EDIM + e0 + i) * LSEQ + t0 + tx] = st[tx][i];
        zT [((size_t)b * EDIM + e0 + i) * LSEQ + t0 + tx] = zt[tx][i];
    }
}

// ---------------- chunked parallel selective scan (16 warps/block, shared B/C) ----------------
#define CHUNK 64
#define BC_SMEM_BYTES 131072
#define NWARP_SCAN 16
#define YSTAGE_BYTES  (NWARP_SCAN * (LSEQ + 32) * 2)
#define SCAN_SMEM (BC_SMEM_BYTES + YSTAGE_BYTES)       // 131072 + 66560 = 197632

__device__ __forceinline__ const uint4* bc_addr(const char* bcs, int t, int c) {
    int slot = ((t & 1) * 4 + c) ^ ((t >> 6) & 7);
    return (const uint4*)(bcs + (t >> 1) * 128 + slot * 16);
}

__global__ void __launch_bounds__(NWARP_SCAN * 32)
scan_kernel(const float* __restrict__ dtT,
            const float* __restrict__ xsT,
            const bf16*  __restrict__ zT,
            const bf16*  __restrict__ bcb,
            const float* __restrict__ A_log,
            const float* __restrict__ D_skip,
            bf16* __restrict__ y) {
    extern __shared__ __align__(16) char dyn[];
    char* bcs = dyn;
    bf16 (*ystage)[LSEQ + 32] = (bf16 (*)[LSEQ + 32])(dyn + BC_SMEM_BYTES);

    const int b    = blockIdx.y;
    const int warp = threadIdx.x >> 5;
    const int lane = threadIdx.x & 31;
    const int e    = blockIdx.x * NWARP_SCAN + warp;

    // ---- stage B/C (shared by all warps; depends only on (b,t)) ----
    {
        const bf16* src = bcb + (size_t)b * LSEQ * 32;
        for (int k = threadIdx.x; k < 8192; k += NWARP_SCAN * 32) {
            int t = k >> 2, c = k & 3;
            int slot = ((t & 1) * 4 + c) ^ ((t >> 6) & 7);
            cp_async16(bcs + (t >> 1) * 128 + slot * 16, src + k * 8);
        }
        cp_commit(); cp_wait<0>();
    }
    __syncthreads();

    float Acoef[NST];
    bool structured = true;
    #pragma unroll
    for (int n = 0; n < NST; n++) {
        Acoef[n] = -__expf(A_log[e * NST + n]);
        structured &= fabsf(Acoef[n] + (float)(n + 1)) < 1e-4f * (float)(n + 1);
    }
    const float dsk = D_skip[e];

    const float* dtp = dtT + ((size_t)b * EDIM + e) * LSEQ;
    const float* xsp = xsT + ((size_t)b * EDIM + e) * LSEQ;
    const bf16*  zp  = zT  + ((size_t)b * EDIM + e) * LSEQ;

    const int t0 = lane * CHUNK;

    // ---- pass 1: per-chunk affine summary (P, q) ----
    float P[NST], q[NST];
    #pragma unroll
    for (int n = 0; n < NST; n++) { P[n] = 1.0f; q[n] = 0.0f; }

    for (int s4 = 0; s4 < CHUNK; s4 += 4) {
        float4 d4 = *(const float4*)&dtp[t0 + s4];
        float4 x4 = *(const float4*)&xsp[t0 + s4];
        float dv[4] = {d4.x, d4.y, d4.z, d4.w};
        float xv[4] = {x4.x, x4.y, x4.z, x4.w};
        #pragma unroll
        for (int u = 0; u < 4; u++) {
            const int t = t0 + s4 + u;
            float Bv[NST];
            unpack8(*bc_addr(bcs, t, 0), Bv);
            unpack8(*bc_addr(bcs, t, 1), Bv + 8);
            float dA[NST];
            compute_dA(dv[u], Acoef, structured, dA);
            const float dx = dv[u] * xv[u];
            #pragma unroll
            for (int n = 0; n < NST; n++) {
                q[n] = fmaf(dA[n], q[n], dx * Bv[n]);
                P[n] *= dA[n];
            }
        }
    }

    // ---- warp inclusive scan of affine maps over lanes ----
    #pragma unroll
    for (int d = 1; d < 32; d <<= 1) {
        #pragma unroll
        for (int n = 0; n < NST; n++) {
            float Pp = __shfl_up_sync(0xffffffffu, P[n], d);
            float qp = __shfl_up_sync(0xffffffffu, q[n], d);
            if (lane >= d) {
                q[n] = fmaf(P[n], qp, q[n]);
                P[n] *= Pp;
            }
        }
    }
    float h[NST];
    #pragma unroll
    for (int n = 0; n < NST; n++) {
        float v = __shfl_up_sync(0xffffffffu, q[n], 1);
        h[n] = (lane == 0) ? 0.0f : v;
    }

    // ---- pass 2: replay with true h0, produce gated y -> smem stage ----
    for (int s8 = 0; s8 < CHUNK; s8 += 8) {
        float4 d4a = *(const float4*)&dtp[t0 + s8];
        float4 d4b = *(const float4*)&dtp[t0 + s8 + 4];
        float4 x4a = *(const float4*)&xsp[t0 + s8];
        float4 x4b = *(const float4*)&xsp[t0 + s8 + 4];
        uint4  zv8 = *(const uint4*)&zp[t0 + s8];
        float dv[8] = {d4a.x, d4a.y, d4a.z, d4a.w, d4b.x, d4b.y, d4b.z, d4b.w};
        float xv[8] = {x4a.x, x4a.y, x4a.z, x4a.w, x4b.x, x4b.y, x4b.z, x4b.w};
        float zv[8];
        unpack8(zv8, zv);
        #pragma unroll
        for (int u = 0; u < 8; u++) {
            const int t = t0 + s8 + u;
            float Bv[NST], Cv[NST];
            unpack8(*bc_addr(bcs, t, 0), Bv);
            unpack8(*bc_addr(bcs, t, 1), Bv + 8);
            unpack8(*bc_addr(bcs, t, 2), Cv);
            unpack8(*bc_addr(bcs, t, 3), Cv + 8);
            float dA[NST];
            compute_dA(dv[u], Acoef, structured, dA);
            const float dx = dv[u] * xv[u];
            float yacc0 = 0.0f, yacc1 = 0.0f;
            #pragma unroll
            for (int n = 0; n < NST; n += 2) {
                h[n]     = fmaf(dA[n],     h[n],     dx * Bv[n]);
                h[n + 1] = fmaf(dA[n + 1], h[n + 1], dx * Bv[n + 1]);
                yacc0 = fmaf(h[n],     Cv[n],     yacc0);
                yacc1 = fmaf(h[n + 1], Cv[n + 1], yacc1);
            }
            const float zz  = zv[u];
            const float sig = 1.0f / (1.0f + __expf(-zz));
            const float out = ((yacc0 + yacc1) + xv[u] * dsk) * (zz * sig);
            ystage[warp][t + (t >> 6)] = __float2bfloat16(out);
        }
    }
    __syncthreads();

    // ---- coalesced store: y[b*L+t][e0..e0+15] as 2x uint4 ----
    const int e0 = blockIdx.x * NWARP_SCAN;
    for (int t = threadIdx.x; t < LSEQ; t += NWARP_SCAN * 32) {
        bf16 v[NWARP_SCAN];
        #pragma unroll
        for (int w = 0; w < NWARP_SCAN; w++) v[w] = ystage[w][t + (t >> 6)];
        *(uint4*)&y[((size_t)(b * LSEQ + t)) * EDIM + e0]     = ((uint4*)v)[0];
        *(uint4*)&y[((size_t)(b * LSEQ + t)) * EDIM + e0 + 8] = ((uint4*)v)[1];
    }
}

// ---------------- launcher ----------------
extern "C" void kernel_launch(void* const* d_in, const int* in_sizes, int n_in,
                              void* d_out, int out_size) {
    const float* hidden = (const float*)d_in[0];
    const float* norm_w = (const float*)d_in[1];
    const float* W_in   = (const float*)d_in[2];
    const float* conv_w = (const float*)d_in[3];
    const float* conv_b = (const float*)d_in[4];
    const float* W_x    = (const float*)d_in[5];
    const float* W_dt   = (const float*)d_in[6];
    const float* b_dt   = (const float*)d_in[7];
    const float* A_log  = (const float*)d_in[8];
    const float* D_skip = (const float*)d_in[9];
    const float* W_out  = (const float*)d_in[10];
    float* out = (float*)d_out;

    float *p_dtT, *p_xsT;
    bf16 *p_xzb, *p_zT, *p_nrmb, *p_xsb, *p_dblb, *p_bcb, *p_yb;
    bf16 *p_winb, *p_wxb, *p_wdtb, *p_woutb;
    cudaGetSymbolAddress((void**)&p_xzb,  g_xzb);
    cudaGetSymbolAddress((void**)&p_dtT,  g_dtT);
    cudaGetSymbolAddress((void**)&p_xsT,  g_xsT);
    cudaGetSymbolAddress((void**)&p_zT,   g_zT);
    cudaGetSymbolAddress((void**)&p_nrmb, g_nrmb);
    cudaGetSymbolAddress((void**)&p_xsb,  g_xsb);
    cudaGetSymbolAddress((void**)&p_dblb, g_dblb);
    cudaGetSymbolAddress((void**)&p_bcb,  g_bcb);
    cudaGetSymbolAddress((void**)&p_yb,   g_yb);
    cudaGetSymbolAddress((void**)&p_winb, g_winb);
    cudaGetSymbolAddress((void**)&p_wxb,  g_wxb);
    cudaGetSymbolAddress((void**)&p_wdtb, g_wdtb);
    cudaGetSymbolAddress((void**)&p_woutb, g_woutb);

    cudaFuncSetAttribute(scan_kernel, cudaFuncAttributeMaxDynamicSharedMemorySize, SCAN_SMEM);
    cudaFuncSetAttribute(gemm_bf16<128, 128, 2, 4, 5>,
                         cudaFuncAttributeMaxDynamicSharedMemorySize, GEMM_BIG_SMEM);
    cudaFuncSetAttribute(gemm_bf16<128, 128, 2, 4, 2>,
                         cudaFuncAttributeMaxDynamicSharedMemorySize, GEMM_BIG_SMEM);
    cudaFuncSetAttribute(gemm_bf16<64, 64, 4, 2, 6>,
                         cudaFuncAttributeMaxDynamicSharedMemorySize, GEMM_DBL_SMEM);

    // 0) fused weight conversion
    {
        int total = (N_WIN + N_WX + N_WDT + N_WOUT) / 4;
        wconv_kernel<<<(total + 255) / 256, 256>>>(W_in, p_winb, W_x, p_wxb,
                                                   W_dt, p_wdtb, W_out, p_woutb);
    }

    // 1) RMSNorm -> bf16
    rmsnorm_kernel<<<NTOK, 128>>>(hidden, norm_w, p_nrmb);

    // 2) xz = nrm @ W_in -> bf16 only
    gemm_bf16<128, 128, 2, 4, 5><<<dim3(2 * EDIM / 128, NTOK / 128), 256, GEMM_BIG_SMEM>>>(
        p_nrmb, DDIM, p_winb, 2 * EDIM, nullptr, 2 * EDIM,
        NTOK, 2 * EDIM, DDIM, nullptr, p_xzb, nullptr);

    // 3) fused conv + silu + transposes
    conv_fused_kernel<<<dim3(EDIM / 64, LSEQ / 32, BSZ), 256>>>(
        p_xzb, conv_w, conv_b, p_xsb, p_xsT, p_zT);

    // 4) dbl = xs @ W_x -> bf16 full + bf16 compact BC
    gemm_bf16<64, 64, 4, 2, 6><<<dim3(1, NTOK / 64), 256, GEMM_DBL_SMEM>>>(
        p_xsb, EDIM, p_wxb, 64, nullptr, 64,
        NTOK, 64, EDIM, nullptr, p_dblb, p_bcb);

    // 5) dtT = softplus(dbl[:, :32] @ W_dt + b_dt), transposed write
    dtgemm_kernel<<<dim3(EDIM / 128, NTOK / 128), 256>>>(p_dblb, p_wdtb, b_dt, p_dtT);

    // 6) chunked parallel scan (16 warps/block, shared B/C) -> bf16 y
    scan_kernel<<<dim3(EDIM / NWARP_SCAN, BSZ), NWARP_SCAN * 32, SCAN_SMEM>>>(
        p_dtT, p_xsT, p_zT, p_bcb, A_log, D_skip, p_yb);

    // 7) out = y @ W_out + hidden -> fp32
    gemm_bf16<128, 128, 2, 4, 2><<<dim3(DDIM / 128, NTOK / 128), 256, GEMM_BIG_SMEM>>>(
        p_yb, EDIM, p_woutb, DDIM, out, DDIM,
        NTOK, DDIM, EDIM, hidden, nullptr, nullptr);
}

// round 13
// speedup vs baseline: 1.2220x; 1.0152x over previous
#include <cuda_runtime.h>
#include <cuda_bf16.h>
#include <cstdint>

using bf16 = __nv_bfloat16;
using bf162 = __nv_bfloat162;

// Problem constants
#define BSZ 4
#define LSEQ 2048
#define DDIM 512
#define EDIM 1024
#define NST 16
#define RRANK 32
#define NTOK (BSZ * LSEQ)          // 8192

// ---------------- scratch (device globals) ----------------
__device__ bf16  g_xzb[NTOK * 2 * EDIM];
__device__ float g_dtT[NTOK * EDIM];
__device__ float g_xsT[NTOK * EDIM];
__device__ bf16  g_zT [NTOK * EDIM];
__device__ bf16  g_nrmb[NTOK * DDIM];
__device__ bf16  g_xsb [NTOK * EDIM];
__device__ bf16  g_dblb[NTOK * 64];
__device__ bf16  g_bcb [NTOK * 32];
__device__ bf16  g_yb  [NTOK * EDIM];
__device__ bf16  g_winb [DDIM * 2 * EDIM];
__device__ bf16  g_wxb  [EDIM * 64];
__device__ bf16  g_wdtb [RRANK * EDIM];
__device__ bf16  g_woutb[EDIM * DDIM];

// ---------------- PTX helpers ----------------
__device__ __forceinline__ uint32_t smem_u32(const void* p) {
    return (uint32_t)__cvta_generic_to_shared(p);
}
__device__ __forceinline__ void cp_async16(void* s, const void* g) {
    asm volatile("cp.async.cg.shared.global [%0], [%1], 16;\n"
                 :: "r"(smem_u32(s)), "l"(g));
}
__device__ __forceinline__ void cp_commit() { asm volatile("cp.async.commit_group;\n"); }
template <int N> __device__ __forceinline__ void cp_wait() {
    asm volatile("cp.async.wait_group %0;\n" :: "n"(N));
}
__device__ __forceinline__ void ldsm_x4(uint32_t& r0, uint32_t& r1, uint32_t& r2, uint32_t& r3,
                                        uint32_t a) {
    asm volatile("ldmatrix.sync.aligned.m8n8.x4.shared.b16 {%0,%1,%2,%3}, [%4];\n"
                 : "=r"(r0), "=r"(r1), "=r"(r2), "=r"(r3) : "r"(a));
}
__device__ __forceinline__ void ldsm_x4_t(uint32_t& r0, uint32_t& r1, uint32_t& r2, uint32_t& r3,
                                          uint32_t a) {
    asm volatile("ldmatrix.sync.aligned.m8n8.x4.trans.shared.b16 {%0,%1,%2,%3}, [%4];\n"
                 : "=r"(r0), "=r"(r1), "=r"(r2), "=r"(r3) : "r"(a));
}
__device__ __forceinline__ void mma_bf16(float& d0, float& d1, float& d2, float& d3,
                                         uint32_t a0, uint32_t a1, uint32_t a2, uint32_t a3,
                                         uint32_t b0, uint32_t b1) {
    asm volatile("mma.sync.aligned.m16n8k16.row.col.f32.bf16.bf16.f32 "
                 "{%0,%1,%2,%3}, {%4,%5,%6,%7}, {%8,%9}, {%0,%1,%2,%3};\n"
                 : "+f"(d0), "+f"(d1), "+f"(d2), "+f"(d3)
                 : "r"(a0), "r"(a1), "r"(a2), "r"(a3), "r"(b0), "r"(b1));
}
__device__ __forceinline__ float softplus_f(float v) {
    return (v > 20.0f) ? v : log1pf(expf(v));
}
__device__ __forceinline__ void unpack8(uint4 v, float* f) {
    uint32_t u[4] = {v.x, v.y, v.z, v.w};
    #pragma unroll
    for (int j = 0; j < 4; j++) {
        f[2 * j]     = __uint_as_float(u[j] << 16);
        f[2 * j + 1] = __uint_as_float(u[j] & 0xffff0000u);
    }
}
// dA[n] = exp(dtv * Acoef[n]); fast path when Acoef[n] == -(n+1).
__device__ __forceinline__ void compute_dA(float dtv, const float* Acoef,
                                           bool structured, float* dA) {
    if (structured) {
        const float r1 = __expf(-dtv);
        const float r2 = r1 * r1;
        const float r4 = r2 * r2;
        const float r8 = r4 * r4;
        dA[0] = r1;       dA[1] = r2;       dA[2] = r2 * r1;  dA[3] = r4;
        dA[4] = r4 * r1;  dA[5] = r4 * r2;  dA[6] = r4 * dA[2]; dA[7] = r8;
        dA[8]  = r8 * r1;   dA[9]  = r8 * r2;   dA[10] = r8 * dA[2]; dA[11] = r8 * r4;
        dA[12] = r8 * dA[4]; dA[13] = r8 * dA[5]; dA[14] = r8 * dA[6]; dA[15] = r8 * r8;
    } else {
        #pragma unroll
        for (int n = 0; n < NST; n++) dA[n] = __expf(dtv * Acoef[n]);
    }
}
__device__ __forceinline__ void load_bf162x8(const uint4* p0, const uint4* p1, bf162* v) {
    uint4 a = *p0, b = *p1;
    uint32_t* u = (uint32_t*)v;
    u[0] = a.x; u[1] = a.y; u[2] = a.z; u[3] = a.w;
    u[4] = b.x; u[5] = b.y; u[6] = b.z; u[7] = b.w;
}

// ---------------- fused weight conversion ----------------
#define N_WIN  (DDIM * 2 * EDIM)
#define N_WX   (EDIM * 64)
#define N_WDT  (RRANK * EDIM)
#define N_WOUT (EDIM * DDIM)
__global__ void wconv_kernel(const float* __restrict__ w_in,  bf16* __restrict__ o_in,
                             const float* __restrict__ w_x,   bf16* __restrict__ o_x,
                             const float* __restrict__ w_dt,  bf16* __restrict__ o_dt,
                             const float* __restrict__ w_out, bf16* __restrict__ o_out) {
    int i = (blockIdx.x * blockDim.x + threadIdx.x) * 4;
    const float* src; bf16* dst; int off;
    if (i < N_WIN)                      { src = w_in;  dst = o_in;  off = i; }
    else if (i < N_WIN + N_WX)          { src = w_x;   dst = o_x;   off = i - N_WIN; }
    else if (i < N_WIN + N_WX + N_WDT)  { src = w_dt;  dst = o_dt;  off = i - N_WIN - N_WX; }
    else if (i < N_WIN + N_WX + N_WDT + N_WOUT)
                                        { src = w_out; dst = o_out; off = i - N_WIN - N_WX - N_WDT; }
    else return;
    float4 v = *(const float4*)(src + off);
    bf16 o[4] = {__float2bfloat16(v.x), __float2bfloat16(v.y),
                 __float2bfloat16(v.z), __float2bfloat16(v.w)};
    *(uint64_t*)(dst + off) = *(uint64_t*)o;
}

// ---------------- RMSNorm -> bf16 ----------------
__global__ void rmsnorm_kernel(const float* __restrict__ x,
                               const float* __restrict__ w,
                               bf16* __restrict__ out) {
    int row = blockIdx.x;
    int tid = threadIdx.x;
    float4 v = ((const float4*)(x + (size_t)row * DDIM))[tid];
    float ss = v.x * v.x + v.y * v.y + v.z * v.z + v.w * v.w;
    #pragma unroll
    for (int o = 16; o > 0; o >>= 1) ss += __shfl_xor_sync(0xffffffffu, ss, o);
    __shared__ float sred[4];
    if ((tid & 31) == 0) sred[tid >> 5] = ss;
    __syncthreads();
    float tot = sred[0] + sred[1] + sred[2] + sred[3];
    float scale = rsqrtf(tot * (1.0f / DDIM) + 1e-6f);
    float4 wv = ((const float4*)w)[tid];
    bf16 o[4] = {__float2bfloat16(v.x * scale * wv.x),
                 __float2bfloat16(v.y * scale * wv.y),
                 __float2bfloat16(v.z * scale * wv.z),
                 __float2bfloat16(v.w * scale * wv.w)};
    *(uint64_t*)(out + (size_t)row * DDIM + tid * 4) = *(uint64_t*)o;
}

// ---------------- bf16 tensor-core GEMM, 3-stage cp.async pipeline ----------------
// EPI: 2 fp32 + resid | 5 bf16 C2 only | 6 bf16 C2 + compact bf16 C3 (cols>=32)
template <int BM, int BN, int WGM, int WGN, int EPI>
__global__ void __launch_bounds__(WGM * WGN * 32)
gemm_bf16(const bf16* __restrict__ A, int lda,
          const bf16* __restrict__ B, int ldb,
          float* __restrict__ C, int ldc,
          int M, int N, int K,
          const float* __restrict__ resid,
          bf16* __restrict__ C2,
          bf16* __restrict__ C3) {
    constexpr int BK = 32;
    constexpr int NTHR = WGM * WGN * 32;
    constexpr int WM = BM / WGM;
    constexpr int WN = BN / WGN;
    constexpr int MT = WM / 16;
    constexpr int NT = WN / 8;
    static_assert(NT % 2 == 0, "NT even");
    constexpr int LDAS = BK + 8;
    constexpr int LDBS = BN + 8;
    constexpr int SA_ELEM = BM * LDAS;
    constexpr int SB_ELEM = BK * LDBS;
    constexpr int STAGE = SA_ELEM + SB_ELEM;

    extern __shared__ __align__(16) bf16 smem[];

    const int tid = threadIdx.x;
    const int warp = tid >> 5, lane = tid & 31;
    const int wm = (warp % WGM) * WM;
    const int wn = (warp / WGM) * WN;
    const int rowBase = blockIdx.y * BM;
    const int colBase = blockIdx.x * BN;

    float acc[MT][NT][4];
    #pragma unroll
    for (int i = 0; i < MT; i++)
        #pragma unroll
        for (int j = 0; j < NT; j++)
            #pragma unroll
            for (int q = 0; q < 4; q++) acc[i][j][q] = 0.0f;

    constexpr int A_CHUNKS = BM * BK / 8;
    constexpr int B_CHUNKS = BK * BN / 8;

    auto load_tile = [&](int s, int k0) {
        bf16* As = smem + s * STAGE;
        bf16* Bs = As + SA_ELEM;
        #pragma unroll
        for (int c = tid; c < A_CHUNKS; c += NTHR) {
            int row = c / (BK / 8);
            int col = (c % (BK / 8)) * 8;
            cp_async16(&As[row * LDAS + col],
                       &A[(size_t)(rowBase + row) * lda + k0 + col]);
        }
        #pragma unroll
        for (int c = tid; c < B_CHUNKS; c += NTHR) {
            int row = c / (BN / 8);
            int col = (c % (BN / 8)) * 8;
            cp_async16(&Bs[row * LDBS + col],
                       &B[(size_t)(k0 + row) * ldb + colBase + col]);
        }
        cp_commit();
    };

    const int KT = K / BK;
    load_tile(0, 0);
    if (KT > 1) load_tile(1, BK);

    const int arow = lane & 15, acol = (lane >> 4) * 8;
    const int bq = lane >> 3, bl = lane & 7;
    const int bk = (bq & 1) * 8 + bl, bn = (bq >> 1) * 8;

    int sbuf = 0;
    for (int kt = 0; kt < KT; kt++) {
        if (kt + 2 < KT) cp_wait<1>(); else cp_wait<0>();
        __syncthreads();
        if (kt + 2 < KT) {
            int s2 = sbuf + 2; if (s2 >= 3) s2 -= 3;
            load_tile(s2, (kt + 2) * BK);
        }
        const bf16* As = smem + sbuf * STAGE;
        const bf16* Bs = As + SA_ELEM;

        #pragma unroll
        for (int ks = 0; ks < 2; ks++) {
            uint32_t a[MT][4];
            #pragma unroll
            for (int mt = 0; mt < MT; mt++)
                ldsm_x4(a[mt][0], a[mt][1], a[mt][2], a[mt][3],
                        smem_u32(&As[(wm + mt * 16 + arow) * LDAS + ks * 16 + acol]));
            uint32_t b[NT][2];
            #pragma unroll
            for (int nt2 = 0; nt2 < NT / 2; nt2++) {
                uint32_t r0, r1, r2, r3;
                ldsm_x4_t(r0, r1, r2, r3,
                          smem_u32(&Bs[(ks * 16 + bk) * LDBS + wn + nt2 * 16 + bn]));
                b[2 * nt2][0] = r0; b[2 * nt2][1] = r1;
                b[2 * nt2 + 1][0] = r2; b[2 * nt2 + 1][1] = r3;
            }
            #pragma unroll
            for (int mt = 0; mt < MT; mt++)
                #pragma unroll
                for (int nt = 0; nt < NT; nt++)
                    mma_bf16(acc[mt][nt][0], acc[mt][nt][1], acc[mt][nt][2], acc[mt][nt][3],
                             a[mt][0], a[mt][1], a[mt][2], a[mt][3],
                             b[nt][0], b[nt][1]);
        }
        if (++sbuf == 3) sbuf = 0;
    }

    #pragma unroll
    for (int mt = 0; mt < MT; mt++) {
        #pragma unroll
        for (int nt = 0; nt < NT; nt++) {
            int col = colBase + wn + nt * 8 + (lane & 3) * 2;
            #pragma unroll
            for (int h = 0; h < 2; h++) {
                int row = rowBase + wm + mt * 16 + (lane >> 2) + h * 8;
                float v0 = acc[mt][nt][2 * h + 0];
                float v1 = acc[mt][nt][2 * h + 1];
                if (EPI == 2) {
                    const float2 r = *(const float2*)&resid[(size_t)row * ldc + col];
                    v0 += r.x; v1 += r.y;
                    *(float2*)&C[(size_t)row * ldc + col] = make_float2(v0, v1);
                }
                if (EPI == 5 || EPI == 6) {
                    bf16 o[2] = {__float2bfloat16(v0), __float2bfloat16(v1)};
                    *(uint32_t*)&C2[(size_t)row * ldc + col] = *(uint32_t*)o;
                    if (EPI == 6 && col >= RRANK)
                        *(uint32_t*)&C3[(size_t)row * 32 + col - RRANK] = *(uint32_t*)o;
                }
            }
        }
    }
}
#define GEMM_BIG_SMEM  (3 * (128 * 40 + 32 * 136) * 2)   // 56832
#define GEMM_DBL_SMEM  (3 * (64 * 40 + 32 * 72) * 2)     // 29184

// ---------------- dedicated dt GEMM ----------------
__global__ void __launch_bounds__(256)
dtgemm_kernel(const bf16* __restrict__ A,
              const bf16* __restrict__ B,
              const float* __restrict__ bias,
              float* __restrict__ dtT) {
    __shared__ __align__(16) bf16 As[128][40];
    __shared__ __align__(16) bf16 Bs[32][136];
    __shared__ float sbuf[32][129];

    const int tid = threadIdx.x, warp = tid >> 5, lane = tid & 31;
    const int wm = (warp & 1) * 64;
    const int wn = (warp >> 1) * 32;
    const int rowBase = blockIdx.y * 128;
    const int colBase = blockIdx.x * 128;

    #pragma unroll
    for (int c = tid; c < 512; c += 256) {
        int r = c >> 2, q = (c & 3) * 8;
        cp_async16(&As[r][q], &A[(size_t)(rowBase + r) * 64 + q]);
    }
    #pragma unroll
    for (int c = tid; c < 512; c += 256) {
        int r = c >> 4, q = (c & 15) * 8;
        cp_async16(&Bs[r][q], &B[(size_t)r * EDIM + colBase + q]);
    }
    cp_commit(); cp_wait<0>(); __syncthreads();

    float acc[4][4][4];
    #pragma unroll
    for (int i = 0; i < 4; i++)
        #pragma unroll
        for (int j = 0; j < 4; j++)
            #pragma unroll
            for (int q = 0; q < 4; q++) acc[i][j][q] = 0.0f;

    const int arow = lane & 15, acol = (lane >> 4) * 8;
    const int bq = lane >> 3, bl = lane & 7;
    const int bk = (bq & 1) * 8 + bl, bn = (bq >> 1) * 8;

    #pragma unroll
    for (int ks = 0; ks < 2; ks++) {
        uint32_t a[4][4];
        #pragma unroll
        for (int mt = 0; mt < 4; mt++)
            ldsm_x4(a[mt][0], a[mt][1], a[mt][2], a[mt][3],
                    smem_u32(&As[wm + mt * 16 + arow][ks * 16 + acol]));
        uint32_t b[4][2];
        #pragma unroll
        for (int nt2 = 0; nt2 < 2; nt2++) {
            uint32_t r0, r1, r2, r3;
            ldsm_x4_t(r0, r1, r2, r3,
                      smem_u32(&Bs[ks * 16 + bk][wn + nt2 * 16 + bn]));
            b[2 * nt2][0] = r0; b[2 * nt2][1] = r1;
            b[2 * nt2 + 1][0] = r2; b[2 * nt2 + 1][1] = r3;
        }
        #pragma unroll
        for (int mt = 0; mt < 4; mt++)
            #pragma unroll
            for (int nt = 0; nt < 4; nt++)
                mma_bf16(acc[mt][nt][0], acc[mt][nt][1], acc[mt][nt][2], acc[mt][nt][3],
                         a[mt][0], a[mt][1], a[mt][2], a[mt][3],
                         b[nt][0], b[nt][1]);
    }

    const int bb = rowBase >> 11;
    const int tb = rowBase & 2047;
    #pragma unroll
    for (int cc = 0; cc < 4; cc++) {
        __syncthreads();
        if (wn == cc * 32) {
            #pragma unroll
            for (int mt = 0; mt < 4; mt++)
                #pragma unroll
                for (int nt = 0; nt < 4; nt++) {
                    int c = nt * 8 + (lane & 3) * 2;
                    int col = colBase + wn + c;
                    #pragma unroll
                    for (int h = 0; h < 2; h++) {
                        int r = wm + mt * 16 + (lane >> 2) + h * 8;
                        sbuf[c][r]     = softplus_f(acc[mt][nt][2 * h]     + bias[col]);
                        sbuf[c + 1][r] = softplus_f(acc[mt][nt][2 * h + 1] + bias[col + 1]);
                    }
                }
        }
        __syncthreads();
        for (int j = tid; j < 32 * 128; j += 256) {
            int c = j >> 7, r = j & 127;
            dtT[((size_t)bb * EDIM + colBase + cc * 32 + c) * LSEQ + tb + r] = sbuf[c][r];
        }
    }
}

// ---------------- fused conv+silu+transposes (64x64 tile, paired stores) ----------------
__global__ void __launch_bounds__(256)
conv_fused_kernel(const bf16* __restrict__ xzb,
                  const float* __restrict__ conv_w,
                  const float* __restrict__ conv_b,
                  bf16* __restrict__ xsb,
                  float* __restrict__ xsT,
                  bf16* __restrict__ zT) {
    __shared__ __align__(8) float xt[67][67];
    __shared__ __align__(8) float st[64][67];
    __shared__ __align__(4) bf16  zt[64][70];

    const int e0 = blockIdx.x * 64;
    const int t0 = blockIdx.y * 64;
    const int b  = blockIdx.z;
    const int tx = threadIdx.x & 31, ty = threadIdx.x >> 5;

    for (int i = ty; i < 67; i += 8) {
        int t = t0 - 3 + i;
        uint32_t pv = 0;
        if (t >= 0)
            pv = *(const uint32_t*)&xzb[((size_t)(b * LSEQ + t)) * (2 * EDIM) + e0 + 2 * tx];
        bf16 p[2]; *(uint32_t*)p = pv;
        xt[i][2 * tx]     = __bfloat162float(p[0]);
        xt[i][2 * tx + 1] = __bfloat162float(p[1]);
    }
    for (int i = ty; i < 64; i += 8) {
        uint32_t pv = *(const uint32_t*)&xzb[((size_t)(b * LSEQ + t0 + i)) * (2 * EDIM) + EDIM + e0 + 2 * tx];
        *(uint32_t*)&zt[i][2 * tx] = pv;
    }
    __syncthreads();

    const int ea = e0 + 2 * tx, ebx = ea + 1;
    const float w0a = conv_w[ea * 4 + 0], w1a = conv_w[ea * 4 + 1],
                w2a = conv_w[ea * 4 + 2], w3a = conv_w[ea * 4 + 3], bba = conv_b[ea];
    const float w0b = conv_w[ebx * 4 + 0], w1b = conv_w[ebx * 4 + 1],
                w2b = conv_w[ebx * 4 + 2], w3b = conv_w[ebx * 4 + 3], bbb = conv_b[ebx];

    for (int i = ty; i < 64; i += 8) {
        float a0 = bba + w0a * xt[i][2*tx] + w1a * xt[i+1][2*tx]
                       + w2a * xt[i+2][2*tx] + w3a * xt[i+3][2*tx];
        float a1 = bbb + w0b * xt[i][2*tx+1] + w1b * xt[i+1][2*tx+1]
                       + w2b * xt[i+2][2*tx+1] + w3b * xt[i+3][2*tx+1];
        float s0 = a0 / (1.0f + __expf(-a0));
        float s1 = a1 / (1.0f + __expf(-a1));
        st[i][2*tx] = s0; st[i][2*tx+1] = s1;
        bf16 o[2] = {__float2bfloat16(s0), __float2bfloat16(s1)};
        *(uint32_t*)&xsb[((size_t)(b * LSEQ + t0 + i)) * EDIM + e0 + 2 * tx] = *(uint32_t*)o;
    }
    __syncthreads();

    for (int i = ty; i < 64; i += 8) {
        float2 xv = make_float2(st[2 * tx][i], st[2 * tx + 1][i]);
        *(float2*)&xsT[((size_t)b * EDIM + e0 + i) * LSEQ + t0 + 2 * tx] = xv;
        bf16 zv[2] = {zt[2 * tx][i], zt[2 * tx + 1][i]};
        *(uint32_t*)&zT[((size_t)b * EDIM + e0 + i) * LSEQ + t0 + 2 * tx] = *(uint32_t*)zv;
    }
}

// ---------------- chunked parallel selective scan (16 warps/block, packed bf16x2) ----------------
#define CHUNK 64
#define BC_SMEM_BYTES 131072
#define NWARP_SCAN 16
#define YSTAGE_BYTES  (NWARP_SCAN * (LSEQ + 32) * 2)
#define SCAN_SMEM (BC_SMEM_BYTES + YSTAGE_BYTES)       // 197632

__device__ __forceinline__ const uint4* bc_addr(const char* bcs, int t, int c) {
    int slot = ((t & 1) * 4 + c) ^ ((t >> 6) & 7);
    return (const uint4*)(bcs + (t >> 1) * 128 + slot * 16);
}

__global__ void __launch_bounds__(NWARP_SCAN * 32)
scan_kernel(const float* __restrict__ dtT,
            const float* __restrict__ xsT,
            const bf16*  __restrict__ zT,
            const bf16*  __restrict__ bcb,
            const float* __restrict__ A_log,
            const float* __restrict__ D_skip,
            bf16* __restrict__ y) {
    extern __shared__ __align__(16) char dyn[];
    char* bcs = dyn;
    bf16 (*ystage)[LSEQ + 32] = (bf16 (*)[LSEQ + 32])(dyn + BC_SMEM_BYTES);

    const int b    = blockIdx.y;
    const int warp = threadIdx.x >> 5;
    const int lane = threadIdx.x & 31;
    const int e    = blockIdx.x * NWARP_SCAN + warp;

    // ---- stage B/C (shared by all warps) ----
    {
        const bf16* src = bcb + (size_t)b * LSEQ * 32;
        for (int k = threadIdx.x; k < 8192; k += NWARP_SCAN * 32) {
            int t = k >> 2, c = k & 3;
            int slot = ((t & 1) * 4 + c) ^ ((t >> 6) & 7);
            cp_async16(bcs + (t >> 1) * 128 + slot * 16, src + k * 8);
        }
        cp_commit(); cp_wait<0>();
    }
    __syncthreads();

    float Acoef[NST];
    bool structured = true;
    #pragma unroll
    for (int n = 0; n < NST; n++) {
        Acoef[n] = -__expf(A_log[e * NST + n]);
        structured &= fabsf(Acoef[n] + (float)(n + 1)) < 1e-4f * (float)(n + 1);
    }
    const float dsk = D_skip[e];

    const float* dtp = dtT + ((size_t)b * EDIM + e) * LSEQ;
    const float* xsp = xsT + ((size_t)b * EDIM + e) * LSEQ;
    const bf16*  zp  = zT  + ((size_t)b * EDIM + e) * LSEQ;

    const int t0 = lane * CHUNK;

    // ---- pass 1: per-chunk affine summary (P fp32, q packed bf16x2) ----
    float P[NST];
    bf162 q2[8];
    #pragma unroll
    for (int n = 0; n < NST; n++) P[n] = 1.0f;
    #pragma unroll
    for (int j = 0; j < 8; j++) q2[j] = __floats2bfloat162_rn(0.0f, 0.0f);

    for (int s4 = 0; s4 < CHUNK; s4 += 4) {
        float4 d4 = *(const float4*)&dtp[t0 + s4];
        float4 x4 = *(const float4*)&xsp[t0 + s4];
        float dv[4] = {d4.x, d4.y, d4.z, d4.w};
        float xv[4] = {x4.x, x4.y, x4.z, x4.w};
        #pragma unroll
        for (int u = 0; u < 4; u++) {
            const int t = t0 + s4 + u;
            bf162 Bv2[8];
            load_bf162x8(bc_addr(bcs, t, 0), bc_addr(bcs, t, 1), Bv2);
            float dA[NST];
            compute_dA(dv[u], Acoef, structured, dA);
            const bf162 dx2 = __float2bfloat162_rn(dv[u] * xv[u]);
            #pragma unroll
            for (int j = 0; j < 8; j++) {
                bf162 dA2 = __floats2bfloat162_rn(dA[2 * j], dA[2 * j + 1]);
                q2[j] = __hfma2(dA2, q2[j], __hmul2(dx2, Bv2[j]));
                P[2 * j]     *= dA[2 * j];
                P[2 * j + 1] *= dA[2 * j + 1];
            }
        }
    }

    // unpack q to fp32 for the cross-lane affine scan
    float q[NST];
    #pragma unroll
    for (int j = 0; j < 8; j++) {
        q[2 * j]     = __low2float(q2[j]);
        q[2 * j + 1] = __high2float(q2[j]);
    }

    // ---- warp inclusive scan of affine maps over lanes (fp32) ----
    #pragma unroll
    for (int d = 1; d < 32; d <<= 1) {
        #pragma unroll
        for (int n = 0; n < NST; n++) {
            float Pp = __shfl_up_sync(0xffffffffu, P[n], d);
            float qp = __shfl_up_sync(0xffffffffu, q[n], d);
            if (lane >= d) {
                q[n] = fmaf(P[n], qp, q[n]);
                P[n] *= Pp;
            }
        }
    }
    bf162 h2[8];
    #pragma unroll
    for (int n = 0; n < NST; n += 2) {
        float v0 = __shfl_up_sync(0xffffffffu, q[n], 1);
        float v1 = __shfl_up_sync(0xffffffffu, q[n + 1], 1);
        if (lane == 0) { v0 = 0.0f; v1 = 0.0f; }
        h2[n >> 1] = __floats2bfloat162_rn(v0, v1);
    }

    // ---- pass 2: replay with true h0, packed bf16x2 h/y ----
    for (int s8 = 0; s8 < CHUNK; s8 += 8) {
        float4 d4a = *(const float4*)&dtp[t0 + s8];
        float4 d4b = *(const float4*)&dtp[t0 + s8 + 4];
        float4 x4a = *(const float4*)&xsp[t0 + s8];
        float4 x4b = *(const float4*)&xsp[t0 + s8 + 4];
        uint4  zv8 = *(const uint4*)&zp[t0 + s8];
        float dv[8] = {d4a.x, d4a.y, d4a.z, d4a.w, d4b.x, d4b.y, d4b.z, d4b.w};
        float xv[8] = {x4a.x, x4a.y, x4a.z, x4a.w, x4b.x, x4b.y, x4b.z, x4b.w};
        float zv[8];
        unpack8(zv8, zv);
        #pragma unroll
        for (int u = 0; u < 8; u++) {
            const int t = t0 + s8 + u;
            bf162 Bv2[8], Cv2[8];
            load_bf162x8(bc_addr(bcs, t, 0), bc_addr(bcs, t, 1), Bv2);
            load_bf162x8(bc_addr(bcs, t, 2), bc_addr(bcs, t, 3), Cv2);
            float dA[NST];
            compute_dA(dv[u], Acoef, structured, dA);
            const bf162 dx2 = __float2bfloat162_rn(dv[u] * xv[u]);
            bf162 yac = __floats2bfloat162_rn(0.0f, 0.0f);
            #pragma unroll
            for (int j = 0; j < 8; j++) {
                bf162 dA2 = __floats2bfloat162_rn(dA[2 * j], dA[2 * j + 1]);
                h2[j] = __hfma2(dA2, h2[j], __hmul2(dx2, Bv2[j]));
                yac = __hfma2(h2[j], Cv2[j], yac);
            }
            const float yacc = __low2float(yac) + __high2float(yac);
            const float zz  = zv[u];
            const float sig = 1.0f / (1.0f + __expf(-zz));
            const float out = (yacc + xv[u] * dsk) * (zz * sig);
            ystage[warp][t + (t >> 6)] = __float2bfloat16(out);
        }
    }
    __syncthreads();

    // ---- coalesced store: y[b*L+t][e0..e0+15] as 2x uint4 ----
    const int e0 = blockIdx.x * NWARP_SCAN;
    for (int t = threadIdx.x; t < LSEQ; t += NWARP_SCAN * 32) {
        bf16 v[NWARP_SCAN];
        #pragma unroll
        for (int w = 0; w < NWARP_SCAN; w++) v[w] = ystage[w][t + (t >> 6)];
        *(uint4*)&y[((size_t)(b * LSEQ + t)) * EDIM + e0]     = ((uint4*)v)[0];
        *(uint4*)&y[((size_t)(b * LSEQ + t)) * EDIM + e0 + 8] = ((uint4*)v)[1];
    }
}

// ---------------- launcher ----------------
extern "C" void kernel_launch(void* const* d_in, const int* in_sizes, int n_in,
                              void* d_out, int out_size) {
    const float* hidden = (const float*)d_in[0];
    const float* norm_w = (const float*)d_in[1];
    const float* W_in   = (const float*)d_in[2];
    const float* conv_w = (const float*)d_in[3];
    const float* conv_b = (const float*)d_in[4];
    const float* W_x    = (const float*)d_in[5];
    const float* W_dt   = (const float*)d_in[6];
    const float* b_dt   = (const float*)d_in[7];
    const float* A_log  = (const float*)d_in[8];
    const float* D_skip = (const float*)d_in[9];
    const float* W_out  = (const float*)d_in[10];
    float* out = (float*)d_out;

    float *p_dtT, *p_xsT;
    bf16 *p_xzb, *p_zT, *p_nrmb, *p_xsb, *p_dblb, *p_bcb, *p_yb;
    bf16 *p_winb, *p_wxb, *p_wdtb, *p_woutb;
    cudaGetSymbolAddress((void**)&p_xzb,  g_xzb);
    cudaGetSymbolAddress((void**)&p_dtT,  g_dtT);
    cudaGetSymbolAddress((void**)&p_xsT,  g_xsT);
    cudaGetSymbolAddress((void**)&p_zT,   g_zT);
    cudaGetSymbolAddress((void**)&p_nrmb, g_nrmb);
    cudaGetSymbolAddress((void**)&p_xsb,  g_xsb);
    cudaGetSymbolAddress((void**)&p_dblb, g_dblb);
    cudaGetSymbolAddress((void**)&p_bcb,  g_bcb);
    cudaGetSymbolAddress((void**)&p_yb,   g_yb);
    cudaGetSymbolAddress((void**)&p_winb, g_winb);
    cudaGetSymbolAddress((void**)&p_wxb,  g_wxb);
    cudaGetSymbolAddress((void**)&p_wdtb, g_wdtb);
    cudaGetSymbolAddress((void**)&p_woutb, g_woutb);

    cudaFuncSetAttribute(scan_kernel, cudaFuncAttributeMaxDynamicSharedMemorySize, SCAN_SMEM);
    cudaFuncSetAttribute(gemm_bf16<128, 128, 2, 4, 5>,
                         cudaFuncAttributeMaxDynamicSharedMemorySize, GEMM_BIG_SMEM);
    cudaFuncSetAttribute(gemm_bf16<128, 128, 2, 4, 2>,
                         cudaFuncAttributeMaxDynamicSharedMemorySize, GEMM_BIG_SMEM);
    cudaFuncSetAttribute(gemm_bf16<64, 64, 4, 2, 6>,
                         cudaFuncAttributeMaxDynamicSharedMemorySize, GEMM_DBL_SMEM);

    // 0) fused weight conversion
    {
        int total = (N_WIN + N_WX + N_WDT + N_WOUT) / 4;
        wconv_kernel<<<(total + 255) / 256, 256>>>(W_in, p_winb, W_x, p_wxb,
                                                   W_dt, p_wdtb, W_out, p_woutb);
    }

    // 1) RMSNorm -> bf16
    rmsnorm_kernel<<<NTOK, 128>>>(hidden, norm_w, p_nrmb);

    // 2) xz = nrm @ W_in -> bf16 only
    gemm_bf16<128, 128, 2, 4, 5><<<dim3(2 * EDIM / 128, NTOK / 128), 256, GEMM_BIG_SMEM>>>(
        p_nrmb, DDIM, p_winb, 2 * EDIM, nullptr, 2 * EDIM,
        NTOK, 2 * EDIM, DDIM, nullptr, p_xzb, nullptr);

    // 3) fused conv + silu + transposes (64x64 tiles)
    conv_fused_kernel<<<dim3(EDIM / 64, LSEQ / 64, BSZ), 256>>>(
        p_xzb, conv_w, conv_b, p_xsb, p_xsT, p_zT);

    // 4) dbl = xs @ W_x -> bf16 full + bf16 compact BC
    gemm_bf16<64, 64, 4, 2, 6><<<dim3(1, NTOK / 64), 256, GEMM_DBL_SMEM>>>(
        p_xsb, EDIM, p_wxb, 64, nullptr, 64,
        NTOK, 64, EDIM, nullptr, p_dblb, p_bcb);

    // 5) dtT = softplus(dbl[:, :32] @ W_dt + b_dt), transposed write
    dtgemm_kernel<<<dim3(EDIM / 128, NTOK / 128), 256>>>(p_dblb, p_wdtb, b_dt, p_dtT);

    // 6) chunked parallel scan (16 warps/block, packed bf16x2) -> bf16 y
    scan_kernel<<<dim3(EDIM / NWARP_SCAN, BSZ), NWARP_SCAN * 32, SCAN_SMEM>>>(
        p_dtT, p_xsT, p_zT, p_bcb, A_log, D_skip, p_yb);

    // 7) out = y @ W_out + hidden -> fp32
    gemm_bf16<128, 128, 2, 4, 2><<<dim3(DDIM / 128, NTOK / 128), 256, GEMM_BIG_SMEM>>>(
        p_yb, EDIM, p_woutb, DDIM, out, DDIM,
        NTOK, DDIM, EDIM, hidden, nullptr, nullptr);
}

// round 14
// speedup vs baseline: 1.2423x; 1.0166x over previous
#include <cuda_runtime.h>
#include <cuda_bf16.h>
#include <cstdint>

using bf16 = __nv_bfloat16;
using bf162 = __nv_bfloat162;

// Problem constants
#define BSZ 4
#define LSEQ 2048
#define DDIM 512
#define EDIM 1024
#define NST 16
#define RRANK 32
#define NTOK (BSZ * LSEQ)          // 8192

// ---------------- scratch (device globals) ----------------
__device__ bf16  g_xzb[NTOK * 2 * EDIM];
__device__ float g_dtT[NTOK * EDIM];
__device__ float g_xsT[NTOK * EDIM];
__device__ bf16  g_zT [NTOK * EDIM];
__device__ bf16  g_nrmb[NTOK * DDIM];
__device__ bf16  g_xsb [NTOK * EDIM];
__device__ bf16  g_dblb[NTOK * 64];
__device__ bf16  g_bcb [NTOK * 32];
__device__ bf16  g_yb  [NTOK * EDIM];
__device__ bf16  g_winb [DDIM * 2 * EDIM];
__device__ bf16  g_wxb  [EDIM * 64];
__device__ bf16  g_wdtb [RRANK * EDIM];
__device__ bf16  g_woutb[EDIM * DDIM];

// ---------------- PTX helpers ----------------
__device__ __forceinline__ uint32_t smem_u32(const void* p) {
    return (uint32_t)__cvta_generic_to_shared(p);
}
__device__ __forceinline__ void cp_async16(void* s, const void* g) {
    asm volatile("cp.async.cg.shared.global [%0], [%1], 16;\n"
                 :: "r"(smem_u32(s)), "l"(g));
}
__device__ __forceinline__ void cp_commit() { asm volatile("cp.async.commit_group;\n"); }
template <int N> __device__ __forceinline__ void cp_wait() {
    asm volatile("cp.async.wait_group %0;\n" :: "n"(N));
}
__device__ __forceinline__ void ldsm_x4(uint32_t& r0, uint32_t& r1, uint32_t& r2, uint32_t& r3,
                                        uint32_t a) {
    asm volatile("ldmatrix.sync.aligned.m8n8.x4.shared.b16 {%0,%1,%2,%3}, [%4];\n"
                 : "=r"(r0), "=r"(r1), "=r"(r2), "=r"(r3) : "r"(a));
}
__device__ __forceinline__ void ldsm_x4_t(uint32_t& r0, uint32_t& r1, uint32_t& r2, uint32_t& r3,
                                          uint32_t a) {
    asm volatile("ldmatrix.sync.aligned.m8n8.x4.trans.shared.b16 {%0,%1,%2,%3}, [%4];\n"
                 : "=r"(r0), "=r"(r1), "=r"(r2), "=r"(r3) : "r"(a));
}
__device__ __forceinline__ void mma_bf16(float& d0, float& d1, float& d2, float& d3,
                                         uint32_t a0, uint32_t a1, uint32_t a2, uint32_t a3,
                                         uint32_t b0, uint32_t b1) {
    asm volatile("mma.sync.aligned.m16n8k16.row.col.f32.bf16.bf16.f32 "
                 "{%0,%1,%2,%3}, {%4,%5,%6,%7}, {%8,%9}, {%0,%1,%2,%3};\n"
                 : "+f"(d0), "+f"(d1), "+f"(d2), "+f"(d3)
                 : "r"(a0), "r"(a1), "r"(a2), "r"(a3), "r"(b0), "r"(b1));
}
__device__ __forceinline__ float softplus_f(float v) {
    return (v > 20.0f) ? v : log1pf(expf(v));
}
__device__ __forceinline__ void unpack8(uint4 v, float* f) {
    uint32_t u[4] = {v.x, v.y, v.z, v.w};
    #pragma unroll
    for (int j = 0; j < 4; j++) {
        f[2 * j]     = __uint_as_float(u[j] << 16);
        f[2 * j + 1] = __uint_as_float(u[j] & 0xffff0000u);
    }
}
// dA[n] = exp(dtv * Acoef[n]); fast path when Acoef[n] == -(n+1).
__device__ __forceinline__ void compute_dA(float dtv, const float* Acoef,
                                           bool structured, float* dA) {
    if (structured) {
        const float r1 = __expf(-dtv);
        const float r2 = r1 * r1;
        const float r4 = r2 * r2;
        const float r8 = r4 * r4;
        dA[0] = r1;       dA[1] = r2;       dA[2] = r2 * r1;  dA[3] = r4;
        dA[4] = r4 * r1;  dA[5] = r4 * r2;  dA[6] = r4 * dA[2]; dA[7] = r8;
        dA[8]  = r8 * r1;   dA[9]  = r8 * r2;   dA[10] = r8 * dA[2]; dA[11] = r8 * r4;
        dA[12] = r8 * dA[4]; dA[13] = r8 * dA[5]; dA[14] = r8 * dA[6]; dA[15] = r8 * r8;
    } else {
        #pragma unroll
        for (int n = 0; n < NST; n++) dA[n] = __expf(dtv * Acoef[n]);
    }
}
__device__ __forceinline__ void load_bf162x8(const uint4* p0, const uint4* p1, bf162* v) {
    uint4 a = *p0, b = *p1;
    uint32_t* u = (uint32_t*)v;
    u[0] = a.x; u[1] = a.y; u[2] = a.z; u[3] = a.w;
    u[4] = b.x; u[5] = b.y; u[6] = b.z; u[7] = b.w;
}

// ---------------- fused weight conversion ----------------
#define N_WIN  (DDIM * 2 * EDIM)
#define N_WX   (EDIM * 64)
#define N_WDT  (RRANK * EDIM)
#define N_WOUT (EDIM * DDIM)
__global__ void wconv_kernel(const float* __restrict__ w_in,  bf16* __restrict__ o_in,
                             const float* __restrict__ w_x,   bf16* __restrict__ o_x,
                             const float* __restrict__ w_dt,  bf16* __restrict__ o_dt,
                             const float* __restrict__ w_out, bf16* __restrict__ o_out) {
    int i = (blockIdx.x * blockDim.x + threadIdx.x) * 4;
    const float* src; bf16* dst; int off;
    if (i < N_WIN)                      { src = w_in;  dst = o_in;  off = i; }
    else if (i < N_WIN + N_WX)          { src = w_x;   dst = o_x;   off = i - N_WIN; }
    else if (i < N_WIN + N_WX + N_WDT)  { src = w_dt;  dst = o_dt;  off = i - N_WIN - N_WX; }
    else if (i < N_WIN + N_WX + N_WDT + N_WOUT)
                                        { src = w_out; dst = o_out; off = i - N_WIN - N_WX - N_WDT; }
    else return;
    float4 v = *(const float4*)(src + off);
    bf16 o[4] = {__float2bfloat16(v.x), __float2bfloat16(v.y),
                 __float2bfloat16(v.z), __float2bfloat16(v.w)};
    *(uint64_t*)(dst + off) = *(uint64_t*)o;
}

// ---------------- RMSNorm -> bf16 ----------------
__global__ void rmsnorm_kernel(const float* __restrict__ x,
                               const float* __restrict__ w,
                               bf16* __restrict__ out) {
    int row = blockIdx.x;
    int tid = threadIdx.x;
    float4 v = ((const float4*)(x + (size_t)row * DDIM))[tid];
    float ss = v.x * v.x + v.y * v.y + v.z * v.z + v.w * v.w;
    #pragma unroll
    for (int o = 16; o > 0; o >>= 1) ss += __shfl_xor_sync(0xffffffffu, ss, o);
    __shared__ float sred[4];
    if ((tid & 31) == 0) sred[tid >> 5] = ss;
    __syncthreads();
    float tot = sred[0] + sred[1] + sred[2] + sred[3];
    float scale = rsqrtf(tot * (1.0f / DDIM) + 1e-6f);
    float4 wv = ((const float4*)w)[tid];
    bf16 o[4] = {__float2bfloat16(v.x * scale * wv.x),
                 __float2bfloat16(v.y * scale * wv.y),
                 __float2bfloat16(v.z * scale * wv.z),
                 __float2bfloat16(v.w * scale * wv.w)};
    *(uint64_t*)(out + (size_t)row * DDIM + tid * 4) = *(uint64_t*)o;
}

// ---------------- bf16 tensor-core GEMM, 3-stage cp.async pipeline ----------------
// EPI: 2 fp32 + resid | 5 bf16 C2 only | 6 bf16 C2 + compact bf16 C3 (cols>=32)
template <int BM, int BN, int WGM, int WGN, int EPI>
__global__ void __launch_bounds__(WGM * WGN * 32)
gemm_bf16(const bf16* __restrict__ A, int lda,
          const bf16* __restrict__ B, int ldb,
          float* __restrict__ C, int ldc,
          int M, int N, int K,
          const float* __restrict__ resid,
          bf16* __restrict__ C2,
          bf16* __restrict__ C3) {
    constexpr int BK = 32;
    constexpr int NTHR = WGM * WGN * 32;
    constexpr int WM = BM / WGM;
    constexpr int WN = BN / WGN;
    constexpr int MT = WM / 16;
    constexpr int NT = WN / 8;
    static_assert(NT % 2 == 0, "NT even");
    constexpr int LDAS = BK + 8;
    constexpr int LDBS = BN + 8;
    constexpr int SA_ELEM = BM * LDAS;
    constexpr int SB_ELEM = BK * LDBS;
    constexpr int STAGE = SA_ELEM + SB_ELEM;

    extern __shared__ __align__(16) bf16 smem[];

    const int tid = threadIdx.x;
    const int warp = tid >> 5, lane = tid & 31;
    const int wm = (warp % WGM) * WM;
    const int wn = (warp / WGM) * WN;
    const int rowBase = blockIdx.y * BM;
    const int colBase = blockIdx.x * BN;

    float acc[MT][NT][4];
    #pragma unroll
    for (int i = 0; i < MT; i++)
        #pragma unroll
        for (int j = 0; j < NT; j++)
            #pragma unroll
            for (int q = 0; q < 4; q++) acc[i][j][q] = 0.0f;

    constexpr int A_CHUNKS = BM * BK / 8;
    constexpr int B_CHUNKS = BK * BN / 8;

    auto load_tile = [&](int s, int k0) {
        bf16* As = smem + s * STAGE;
        bf16* Bs = As + SA_ELEM;
        #pragma unroll
        for (int c = tid; c < A_CHUNKS; c += NTHR) {
            int row = c / (BK / 8);
            int col = (c % (BK / 8)) * 8;
            cp_async16(&As[row * LDAS + col],
                       &A[(size_t)(rowBase + row) * lda + k0 + col]);
        }
        #pragma unroll
        for (int c = tid; c < B_CHUNKS; c += NTHR) {
            int row = c / (BN / 8);
            int col = (c % (BN / 8)) * 8;
            cp_async16(&Bs[row * LDBS + col],
                       &B[(size_t)(k0 + row) * ldb + colBase + col]);
        }
        cp_commit();
    };

    const int KT = K / BK;
    load_tile(0, 0);
    if (KT > 1) load_tile(1, BK);

    const int arow = lane & 15, acol = (lane >> 4) * 8;
    const int bq = lane >> 3, bl = lane & 7;
    const int bk = (bq & 1) * 8 + bl, bn = (bq >> 1) * 8;

    int sbuf = 0;
    for (int kt = 0; kt < KT; kt++) {
        if (kt + 2 < KT) cp_wait<1>(); else cp_wait<0>();
        __syncthreads();
        if (kt + 2 < KT) {
            int s2 = sbuf + 2; if (s2 >= 3) s2 -= 3;
            load_tile(s2, (kt + 2) * BK);
        }
        const bf16* As = smem + sbuf * STAGE;
        const bf16* Bs = As + SA_ELEM;

        #pragma unroll
        for (int ks = 0; ks < 2; ks++) {
            uint32_t a[MT][4];
            #pragma unroll
            for (int mt = 0; mt < MT; mt++)
                ldsm_x4(a[mt][0], a[mt][1], a[mt][2], a[mt][3],
                        smem_u32(&As[(wm + mt * 16 + arow) * LDAS + ks * 16 + acol]));
            uint32_t b[NT][2];
            #pragma unroll
            for (int nt2 = 0; nt2 < NT / 2; nt2++) {
                uint32_t r0, r1, r2, r3;
                ldsm_x4_t(r0, r1, r2, r3,
                          smem_u32(&Bs[(ks * 16 + bk) * LDBS + wn + nt2 * 16 + bn]));
                b[2 * nt2][0] = r0; b[2 * nt2][1] = r1;
                b[2 * nt2 + 1][0] = r2; b[2 * nt2 + 1][1] = r3;
            }
            #pragma unroll
            for (int mt = 0; mt < MT; mt++)
                #pragma unroll
                for (int nt = 0; nt < NT; nt++)
                    mma_bf16(acc[mt][nt][0], acc[mt][nt][1], acc[mt][nt][2], acc[mt][nt][3],
                             a[mt][0], a[mt][1], a[mt][2], a[mt][3],
                             b[nt][0], b[nt][1]);
        }
        if (++sbuf == 3) sbuf = 0;
    }

    #pragma unroll
    for (int mt = 0; mt < MT; mt++) {
        #pragma unroll
        for (int nt = 0; nt < NT; nt++) {
            int col = colBase + wn + nt * 8 + (lane & 3) * 2;
            #pragma unroll
            for (int h = 0; h < 2; h++) {
                int row = rowBase + wm + mt * 16 + (lane >> 2) + h * 8;
                float v0 = acc[mt][nt][2 * h + 0];
                float v1 = acc[mt][nt][2 * h + 1];
                if (EPI == 2) {
                    const float2 r = *(const float2*)&resid[(size_t)row * ldc + col];
                    v0 += r.x; v1 += r.y;
                    *(float2*)&C[(size_t)row * ldc + col] = make_float2(v0, v1);
                }
                if (EPI == 5 || EPI == 6) {
                    bf16 o[2] = {__float2bfloat16(v0), __float2bfloat16(v1)};
                    *(uint32_t*)&C2[(size_t)row * ldc + col] = *(uint32_t*)o;
                    if (EPI == 6 && col >= RRANK)
                        *(uint32_t*)&C3[(size_t)row * 32 + col - RRANK] = *(uint32_t*)o;
                }
            }
        }
    }
}
#define GEMM_BIG_SMEM  (3 * (128 * 40 + 32 * 136) * 2)   // 56832
#define GEMM_DBL_SMEM  (3 * (64 * 40 + 32 * 72) * 2)     // 29184

// ---------------- dedicated dt GEMM ----------------
__global__ void __launch_bounds__(256)
dtgemm_kernel(const bf16* __restrict__ A,
              const bf16* __restrict__ B,
              const float* __restrict__ bias,
              float* __restrict__ dtT) {
    __shared__ __align__(16) bf16 As[128][40];
    __shared__ __align__(16) bf16 Bs[32][136];
    __shared__ float sbuf[32][129];

    const int tid = threadIdx.x, warp = tid >> 5, lane = tid & 31;
    const int wm = (warp & 1) * 64;
    const int wn = (warp >> 1) * 32;
    const int rowBase = blockIdx.y * 128;
    const int colBase = blockIdx.x * 128;

    #pragma unroll
    for (int c = tid; c < 512; c += 256) {
        int r = c >> 2, q = (c & 3) * 8;
        cp_async16(&As[r][q], &A[(size_t)(rowBase + r) * 64 + q]);
    }
    #pragma unroll
    for (int c = tid; c < 512; c += 256) {
        int r = c >> 4, q = (c & 15) * 8;
        cp_async16(&Bs[r][q], &B[(size_t)r * EDIM + colBase + q]);
    }
    cp_commit(); cp_wait<0>(); __syncthreads();

    float acc[4][4][4];
    #pragma unroll
    for (int i = 0; i < 4; i++)
        #pragma unroll
        for (int j = 0; j < 4; j++)
            #pragma unroll
            for (int q = 0; q < 4; q++) acc[i][j][q] = 0.0f;

    const int arow = lane & 15, acol = (lane >> 4) * 8;
    const int bq = lane >> 3, bl = lane & 7;
    const int bk = (bq & 1) * 8 + bl, bn = (bq >> 1) * 8;

    #pragma unroll
    for (int ks = 0; ks < 2; ks++) {
        uint32_t a[4][4];
        #pragma unroll
        for (int mt = 0; mt < 4; mt++)
            ldsm_x4(a[mt][0], a[mt][1], a[mt][2], a[mt][3],
                    smem_u32(&As[wm + mt * 16 + arow][ks * 16 + acol]));
        uint32_t b[4][2];
        #pragma unroll
        for (int nt2 = 0; nt2 < 2; nt2++) {
            uint32_t r0, r1, r2, r3;
            ldsm_x4_t(r0, r1, r2, r3,
                      smem_u32(&Bs[ks * 16 + bk][wn + nt2 * 16 + bn]));
            b[2 * nt2][0] = r0; b[2 * nt2][1] = r1;
            b[2 * nt2 + 1][0] = r2; b[2 * nt2 + 1][1] = r3;
        }
        #pragma unroll
        for (int mt = 0; mt < 4; mt++)
            #pragma unroll
            for (int nt = 0; nt < 4; nt++)
                mma_bf16(acc[mt][nt][0], acc[mt][nt][1], acc[mt][nt][2], acc[mt][nt][3],
                         a[mt][0], a[mt][1], a[mt][2], a[mt][3],
                         b[nt][0], b[nt][1]);
    }

    const int bb = rowBase >> 11;
    const int tb = rowBase & 2047;
    #pragma unroll
    for (int cc = 0; cc < 4; cc++) {
        __syncthreads();
        if (wn == cc * 32) {
            #pragma unroll
            for (int mt = 0; mt < 4; mt++)
                #pragma unroll
                for (int nt = 0; nt < 4; nt++) {
                    int c = nt * 8 + (lane & 3) * 2;
                    int col = colBase + wn + c;
                    #pragma unroll
                    for (int h = 0; h < 2; h++) {
                        int r = wm + mt * 16 + (lane >> 2) + h * 8;
                        sbuf[c][r]     = softplus_f(acc[mt][nt][2 * h]     + bias[col]);
                        sbuf[c + 1][r] = softplus_f(acc[mt][nt][2 * h + 1] + bias[col + 1]);
                    }
                }
        }
        __syncthreads();
        for (int j = tid; j < 32 * 128; j += 256) {
            int c = j >> 7, r = j & 127;
            dtT[((size_t)bb * EDIM + colBase + cc * 32 + c) * LSEQ + tb + r] = sbuf[c][r];
        }
    }
}

// ---------------- fused conv+silu+transposes (R12 version: 32x64 tile, float2 smem) ----------------
__global__ void __launch_bounds__(256)
conv_fused_kernel(const bf16* __restrict__ xzb,
                  const float* __restrict__ conv_w,
                  const float* __restrict__ conv_b,
                  bf16* __restrict__ xsb,
                  float* __restrict__ xsT,
                  bf16* __restrict__ zT) {
    __shared__ __align__(8) float xt[35][66];
    __shared__ __align__(8) float st[32][66];
    __shared__ bf16  zt[32][66];

    const int e0 = blockIdx.x * 64;
    const int t0 = blockIdx.y * 32;
    const int b  = blockIdx.z;
    const int tx = threadIdx.x & 31, ty = threadIdx.x >> 5;

    for (int i = ty; i < 35; i += 8) {
        int t = t0 - 3 + i;
        uint32_t pv = 0;
        if (t >= 0)
            pv = *(const uint32_t*)&xzb[((size_t)(b * LSEQ + t)) * (2 * EDIM) + e0 + 2 * tx];
        bf16 p[2]; *(uint32_t*)p = pv;
        *(float2*)&xt[i][2 * tx] = make_float2(__bfloat162float(p[0]), __bfloat162float(p[1]));
    }
    for (int i = ty; i < 32; i += 8) {
        uint32_t pv = *(const uint32_t*)&xzb[((size_t)(b * LSEQ + t0 + i)) * (2 * EDIM) + EDIM + e0 + 2 * tx];
        *(uint32_t*)&zt[i][2 * tx] = pv;
    }
    __syncthreads();

    const int ea = e0 + 2 * tx, ebx = ea + 1;
    const float w0a = conv_w[ea * 4 + 0], w1a = conv_w[ea * 4 + 1],
                w2a = conv_w[ea * 4 + 2], w3a = conv_w[ea * 4 + 3], bba = conv_b[ea];
    const float w0b = conv_w[ebx * 4 + 0], w1b = conv_w[ebx * 4 + 1],
                w2b = conv_w[ebx * 4 + 2], w3b = conv_w[ebx * 4 + 3], bbb = conv_b[ebx];

    for (int i = ty; i < 32; i += 8) {
        float2 v0 = *(const float2*)&xt[i][2 * tx];
        float2 v1 = *(const float2*)&xt[i + 1][2 * tx];
        float2 v2 = *(const float2*)&xt[i + 2][2 * tx];
        float2 v3 = *(const float2*)&xt[i + 3][2 * tx];
        float a0 = bba + w0a * v0.x + w1a * v1.x + w2a * v2.x + w3a * v3.x;
        float a1 = bbb + w0b * v0.y + w1b * v1.y + w2b * v2.y + w3b * v3.y;
        float s0 = a0 / (1.0f + __expf(-a0));
        float s1 = a1 / (1.0f + __expf(-a1));
        *(float2*)&st[i][2 * tx] = make_float2(s0, s1);
        bf16 o[2] = {__float2bfloat16(s0), __float2bfloat16(s1)};
        *(uint32_t*)&xsb[((size_t)(b * LSEQ + t0 + i)) * EDIM + e0 + 2 * tx] = *(uint32_t*)o;
    }
    __syncthreads();

    for (int i = ty; i < 64; i += 8) {
        xsT[((size_t)b * EDIM + e0 + i) * LSEQ + t0 + tx] = st[tx][i];
        zT [((size_t)b * EDIM + e0 + i) * LSEQ + t0 + tx] = zt[tx][i];
    }
}

// ---------------- chunked parallel selective scan (16 warps/block, packed bf16x2) ----------------
#define CHUNK 64
#define BC_SMEM_BYTES 131072
#define NWARP_SCAN 16
#define YSTAGE_BYTES  (NWARP_SCAN * (LSEQ + 32) * 2)
#define SCAN_SMEM (BC_SMEM_BYTES + YSTAGE_BYTES)       // 197632

__device__ __forceinline__ const uint4* bc_addr(const char* bcs, int t, int c) {
    int slot = ((t & 1) * 4 + c) ^ ((t >> 6) & 7);
    return (const uint4*)(bcs + (t >> 1) * 128 + slot * 16);
}

__global__ void __launch_bounds__(NWARP_SCAN * 32)
scan_kernel(const float* __restrict__ dtT,
            const float* __restrict__ xsT,
            const bf16*  __restrict__ zT,
            const bf16*  __restrict__ bcb,
            const float* __restrict__ A_log,
            const float* __restrict__ D_skip,
            bf16* __restrict__ y) {
    extern __shared__ __align__(16) char dyn[];
    char* bcs = dyn;
    bf16 (*ystage)[LSEQ + 32] = (bf16 (*)[LSEQ + 32])(dyn + BC_SMEM_BYTES);

    const int b    = blockIdx.y;
    const int warp = threadIdx.x >> 5;
    const int lane = threadIdx.x & 31;
    const int e    = blockIdx.x * NWARP_SCAN + warp;

    // ---- stage B/C (shared by all warps) ----
    {
        const bf16* src = bcb + (size_t)b * LSEQ * 32;
        for (int k = threadIdx.x; k < 8192; k += NWARP_SCAN * 32) {
            int t = k >> 2, c = k & 3;
            int slot = ((t & 1) * 4 + c) ^ ((t >> 6) & 7);
            cp_async16(bcs + (t >> 1) * 128 + slot * 16, src + k * 8);
        }
        cp_commit(); cp_wait<0>();
    }
    __syncthreads();

    float Acoef[NST];
    bool structured = true;
    #pragma unroll
    for (int n = 0; n < NST; n++) {
        Acoef[n] = -__expf(A_log[e * NST + n]);
        structured &= fabsf(Acoef[n] + (float)(n + 1)) < 1e-4f * (float)(n + 1);
    }
    const float dsk = D_skip[e];

    const float* dtp = dtT + ((size_t)b * EDIM + e) * LSEQ;
    const float* xsp = xsT + ((size_t)b * EDIM + e) * LSEQ;
    const bf16*  zp  = zT  + ((size_t)b * EDIM + e) * LSEQ;

    const int t0 = lane * CHUNK;

    // ---- pass 1: per-chunk affine summary (P fp32, q packed bf16x2) ----
    float P[NST];
    bf162 q2[8];
    #pragma unroll
    for (int n = 0; n < NST; n++) P[n] = 1.0f;
    #pragma unroll
    for (int j = 0; j < 8; j++) q2[j] = __floats2bfloat162_rn(0.0f, 0.0f);

    for (int s4 = 0; s4 < CHUNK; s4 += 4) {
        float4 d4 = *(const float4*)&dtp[t0 + s4];
        float4 x4 = *(const float4*)&xsp[t0 + s4];
        float dv[4] = {d4.x, d4.y, d4.z, d4.w};
        float xv[4] = {x4.x, x4.y, x4.z, x4.w};
        #pragma unroll
        for (int u = 0; u < 4; u++) {
            const int t = t0 + s4 + u;
            bf162 Bv2[8];
            load_bf162x8(bc_addr(bcs, t, 0), bc_addr(bcs, t, 1), Bv2);
            float dA[NST];
            compute_dA(dv[u], Acoef, structured, dA);
            const bf162 dx2 = __float2bfloat162_rn(dv[u] * xv[u]);
            #pragma unroll
            for (int j = 0; j < 8; j++) {
                bf162 dA2 = __floats2bfloat162_rn(dA[2 * j], dA[2 * j + 1]);
                q2[j] = __hfma2(dA2, q2[j], __hmul2(dx2, Bv2[j]));
                P[2 * j]     *= dA[2 * j];
                P[2 * j + 1] *= dA[2 * j + 1];
            }
        }
    }

    // unpack q to fp32 for the cross-lane affine scan
    float q[NST];
    #pragma unroll
    for (int j = 0; j < 8; j++) {
        q[2 * j]     = __low2float(q2[j]);
        q[2 * j + 1] = __high2float(q2[j]);
    }

    // ---- warp inclusive scan of affine maps over lanes (fp32) ----
    #pragma unroll
    for (int d = 1; d < 32; d <<= 1) {
        #pragma unroll
        for (int n = 0; n < NST; n++) {
            float Pp = __shfl_up_sync(0xffffffffu, P[n], d);
            float qp = __shfl_up_sync(0xffffffffu, q[n], d);
            if (lane >= d) {
                q[n] = fmaf(P[n], qp, q[n]);
                P[n] *= Pp;
            }
        }
    }
    bf162 h2[8];
    #pragma unroll
    for (int n = 0; n < NST; n += 2) {
        float v0 = __shfl_up_sync(0xffffffffu, q[n], 1);
        float v1 = __shfl_up_sync(0xffffffffu, q[n + 1], 1);
        if (lane == 0) { v0 = 0.0f; v1 = 0.0f; }
        h2[n >> 1] = __floats2bfloat162_rn(v0, v1);
    }

    // ---- pass 2: replay with true h0, packed bf16x2 h/y ----
    for (int s8 = 0; s8 < CHUNK; s8 += 8) {
        float4 d4a = *(const float4*)&dtp[t0 + s8];
        float4 d4b = *(const float4*)&dtp[t0 + s8 + 4];
        float4 x4a = *(const float4*)&xsp[t0 + s8];
        float4 x4b = *(const float4*)&xsp[t0 + s8 + 4];
        uint4  zv8 = *(const uint4*)&zp[t0 + s8];
        float dv[8] = {d4a.x, d4a.y, d4a.z, d4a.w, d4b.x, d4b.y, d4b.z, d4b.w};
        float xv[8] = {x4a.x, x4a.y, x4a.z, x4a.w, x4b.x, x4b.y, x4b.z, x4b.w};
        float zv[8];
        unpack8(zv8, zv);
        #pragma unroll
        for (int u = 0; u < 8; u++) {
            const int t = t0 + s8 + u;
            bf162 Bv2[8], Cv2[8];
            load_bf162x8(bc_addr(bcs, t, 0), bc_addr(bcs, t, 1), Bv2);
            load_bf162x8(bc_addr(bcs, t, 2), bc_addr(bcs, t, 3), Cv2);
            float dA[NST];
            compute_dA(dv[u], Acoef, structured, dA);
            const bf162 dx2 = __float2bfloat162_rn(dv[u] * xv[u]);
            bf162 yac = __floats2bfloat162_rn(0.0f, 0.0f);
            #pragma unroll
            for (int j = 0; j < 8; j++) {
                bf162 dA2 = __floats2bfloat162_rn(dA[2 * j], dA[2 * j + 1]);
                h2[j] = __hfma2(dA2, h2[j], __hmul2(dx2, Bv2[j]));
                yac = __hfma2(h2[j], Cv2[j], yac);
            }
            const float yacc = __low2float(yac) + __high2float(yac);
            const float zz  = zv[u];
            const float sig = 1.0f / (1.0f + __expf(-zz));
            const float out = (yacc + xv[u] * dsk) * (zz * sig);
            ystage[warp][t + (t >> 6)] = __float2bfloat16(out);
        }
    }
    __syncthreads();

    // ---- coalesced store: y[b*L+t][e0..e0+15] as 2x uint4 ----
    const int e0 = blockIdx.x * NWARP_SCAN;
    for (int t = threadIdx.x; t < LSEQ; t += NWARP_SCAN * 32) {
        bf16 v[NWARP_SCAN];
        #pragma unroll
        for (int w = 0; w < NWARP_SCAN; w++) v[w] = ystage[w][t + (t >> 6)];
        *(uint4*)&y[((size_t)(b * LSEQ + t)) * EDIM + e0]     = ((uint4*)v)[0];
        *(uint4*)&y[((size_t)(b * LSEQ + t)) * EDIM + e0 + 8] = ((uint4*)v)[1];
    }
}

// ---------------- launcher ----------------
extern "C" void kernel_launch(void* const* d_in, const int* in_sizes, int n_in,
                              void* d_out, int out_size) {
    const float* hidden = (const float*)d_in[0];
    const float* norm_w = (const float*)d_in[1];
    const float* W_in   = (const float*)d_in[2];
    const float* conv_w = (const float*)d_in[3];
    const float* conv_b = (const float*)d_in[4];
    const float* W_x    = (const float*)d_in[5];
    const float* W_dt   = (const float*)d_in[6];
    const float* b_dt   = (const float*)d_in[7];
    const float* A_log  = (const float*)d_in[8];
    const float* D_skip = (const float*)d_in[9];
    const float* W_out  = (const float*)d_in[10];
    float* out = (float*)d_out;

    float *p_dtT, *p_xsT;
    bf16 *p_xzb, *p_zT, *p_nrmb, *p_xsb, *p_dblb, *p_bcb, *p_yb;
    bf16 *p_winb, *p_wxb, *p_wdtb, *p_woutb;
    cudaGetSymbolAddress((void**)&p_xzb,  g_xzb);
    cudaGetSymbolAddress((void**)&p_dtT,  g_dtT);
    cudaGetSymbolAddress((void**)&p_xsT,  g_xsT);
    cudaGetSymbolAddress((void**)&p_zT,   g_zT);
    cudaGetSymbolAddress((void**)&p_nrmb, g_nrmb);
    cudaGetSymbolAddress((void**)&p_xsb,  g_xsb);
    cudaGetSymbolAddress((void**)&p_dblb, g_dblb);
    cudaGetSymbolAddress((void**)&p_bcb,  g_bcb);
    cudaGetSymbolAddress((void**)&p_yb,   g_yb);
    cudaGetSymbolAddress((void**)&p_winb, g_winb);
    cudaGetSymbolAddress((void**)&p_wxb,  g_wxb);
    cudaGetSymbolAddress((void**)&p_wdtb, g_wdtb);
    cudaGetSymbolAddress((void**)&p_woutb, g_woutb);

    cudaFuncSetAttribute(scan_kernel, cudaFuncAttributeMaxDynamicSharedMemorySize, SCAN_SMEM);
    cudaFuncSetAttribute(gemm_bf16<128, 128, 2, 4, 5>,
                         cudaFuncAttributeMaxDynamicSharedMemorySize, GEMM_BIG_SMEM);
    cudaFuncSetAttribute(gemm_bf16<128, 128, 2, 4, 2>,
                         cudaFuncAttributeMaxDynamicSharedMemorySize, GEMM_BIG_SMEM);
    cudaFuncSetAttribute(gemm_bf16<64, 64, 4, 2, 6>,
                         cudaFuncAttributeMaxDynamicSharedMemorySize, GEMM_DBL_SMEM);

    // 0) fused weight conversion
    {
        int total = (N_WIN + N_WX + N_WDT + N_WOUT) / 4;
        wconv_kernel<<<(total + 255) / 256, 256>>>(W_in, p_winb, W_x, p_wxb,
                                                   W_dt, p_wdtb, W_out, p_woutb);
    }

    // 1) RMSNorm -> bf16
    rmsnorm_kernel<<<NTOK, 128>>>(hidden, norm_w, p_nrmb);

    // 2) xz = nrm @ W_in -> bf16 only
    gemm_bf16<128, 128, 2, 4, 5><<<dim3(2 * EDIM / 128, NTOK / 128), 256, GEMM_BIG_SMEM>>>(
        p_nrmb, DDIM, p_winb, 2 * EDIM, nullptr, 2 * EDIM,
        NTOK, 2 * EDIM, DDIM, nullptr, p_xzb, nullptr);

    // 3) fused conv + silu + transposes (32x64 tiles)
    conv_fused_kernel<<<dim3(EDIM / 64, LSEQ / 32, BSZ), 256>>>(
        p_xzb, conv_w, conv_b, p_xsb, p_xsT, p_zT);

    // 4) dbl = xs @ W_x -> bf16 full + bf16 compact BC
    gemm_bf16<64, 64, 4, 2, 6><<<dim3(1, NTOK / 64), 256, GEMM_DBL_SMEM>>>(
        p_xsb, EDIM, p_wxb, 64, nullptr, 64,
        NTOK, 64, EDIM, nullptr, p_dblb, p_bcb);

    // 5) dtT = softplus(dbl[:, :32] @ W_dt + b_dt), transposed write
    dtgemm_kernel<<<dim3(EDIM / 128, NTOK / 128), 256>>>(p_dblb, p_wdtb, b_dt, p_dtT);

    // 6) chunked parallel scan (16 warps/block, packed bf16x2) -> bf16 y
    scan_kernel<<<dim3(EDIM / NWARP_SCAN, BSZ), NWARP_SCAN * 32, SCAN_SMEM>>>(
        p_dtT, p_xsT, p_zT, p_bcb, A_log, D_skip, p_yb);

    // 7) out = y @ W_out + hidden -> fp32
    gemm_bf16<128, 128, 2, 4, 2><<<dim3(DDIM / 128, NTOK / 128), 256, GEMM_BIG_SMEM>>>(
        p_yb, EDIM, p_woutb, DDIM, out, DDIM,
        NTOK, DDIM, EDIM, hidden, nullptr, nullptr);
}

// round 15
// speedup vs baseline: 1.2788x; 1.0294x over previous
#include <cuda_runtime.h>
#include <cuda_bf16.h>
#include <cstdint>

using bf16 = __nv_bfloat16;
using bf162 = __nv_bfloat162;

// Problem constants
#define BSZ 4
#define LSEQ 2048
#define DDIM 512
#define EDIM 1024
#define NST 16
#define RRANK 32
#define NTOK (BSZ * LSEQ)          // 8192

// ---------------- scratch (device globals) ----------------
__device__ bf16  g_xzb[NTOK * 2 * EDIM];
__device__ float g_dtT[NTOK * EDIM];
__device__ float g_xsT[NTOK * EDIM];
__device__ bf16  g_zT [NTOK * EDIM];
__device__ bf16  g_nrmb[NTOK * DDIM];
__device__ bf16  g_xsb [NTOK * EDIM];
__device__ bf16  g_dblb[NTOK * 64];
__device__ bf16  g_bcb [NTOK * 32];
__device__ bf16  g_yb  [NTOK * EDIM];
__device__ bf16  g_winb [DDIM * 2 * EDIM];
__device__ bf16  g_wxb  [EDIM * 64];
__device__ bf16  g_wdtb [RRANK * EDIM];
__device__ bf16  g_woutb[EDIM * DDIM];

// ---------------- PTX helpers ----------------
__device__ __forceinline__ uint32_t smem_u32(const void* p) {
    return (uint32_t)__cvta_generic_to_shared(p);
}
__device__ __forceinline__ void cp_async16(void* s, const void* g) {
    asm volatile("cp.async.cg.shared.global [%0], [%1], 16;\n"
                 :: "r"(smem_u32(s)), "l"(g));
}
__device__ __forceinline__ void cp_commit() { asm volatile("cp.async.commit_group;\n"); }
template <int N> __device__ __forceinline__ void cp_wait() {
    asm volatile("cp.async.wait_group %0;\n" :: "n"(N));
}
__device__ __forceinline__ void ldsm_x4(uint32_t& r0, uint32_t& r1, uint32_t& r2, uint32_t& r3,
                                        uint32_t a) {
    asm volatile("ldmatrix.sync.aligned.m8n8.x4.shared.b16 {%0,%1,%2,%3}, [%4];\n"
                 : "=r"(r0), "=r"(r1), "=r"(r2), "=r"(r3) : "r"(a));
}
__device__ __forceinline__ void ldsm_x4_t(uint32_t& r0, uint32_t& r1, uint32_t& r2, uint32_t& r3,
                                          uint32_t a) {
    asm volatile("ldmatrix.sync.aligned.m8n8.x4.trans.shared.b16 {%0,%1,%2,%3}, [%4];\n"
                 : "=r"(r0), "=r"(r1), "=r"(r2), "=r"(r3) : "r"(a));
}
__device__ __forceinline__ void mma_bf16(float& d0, float& d1, float& d2, float& d3,
                                         uint32_t a0, uint32_t a1, uint32_t a2, uint32_t a3,
                                         uint32_t b0, uint32_t b1) {
    asm volatile("mma.sync.aligned.m16n8k16.row.col.f32.bf16.bf16.f32 "
                 "{%0,%1,%2,%3}, {%4,%5,%6,%7}, {%8,%9}, {%0,%1,%2,%3};\n"
                 : "+f"(d0), "+f"(d1), "+f"(d2), "+f"(d3)
                 : "r"(a0), "r"(a1), "r"(a2), "r"(a3), "r"(b0), "r"(b1));
}
__device__ __forceinline__ float softplus_f(float v) {
    return (v > 20.0f) ? v : log1pf(expf(v));
}
__device__ __forceinline__ void unpack8(uint4 v, float* f) {
    uint32_t u[4] = {v.x, v.y, v.z, v.w};
    #pragma unroll
    for (int j = 0; j < 4; j++) {
        f[2 * j]     = __uint_as_float(u[j] << 16);
        f[2 * j + 1] = __uint_as_float(u[j] & 0xffff0000u);
    }
}
// dA[n] = exp(dtv * Acoef[n]); fast path when Acoef[n] == -(n+1).
__device__ __forceinline__ void compute_dA(float dtv, const float* Acoef,
                                           bool structured, float* dA) {
    if (structured) {
        const float r1 = __expf(-dtv);
        const float r2 = r1 * r1;
        const float r4 = r2 * r2;
        const float r8 = r4 * r4;
        dA[0] = r1;       dA[1] = r2;       dA[2] = r2 * r1;  dA[3] = r4;
        dA[4] = r4 * r1;  dA[5] = r4 * r2;  dA[6] = r4 * dA[2]; dA[7] = r8;
        dA[8]  = r8 * r1;   dA[9]  = r8 * r2;   dA[10] = r8 * dA[2]; dA[11] = r8 * r4;
        dA[12] = r8 * dA[4]; dA[13] = r8 * dA[5]; dA[14] = r8 * dA[6]; dA[15] = r8 * r8;
    } else {
        #pragma unroll
        for (int n = 0; n < NST; n++) dA[n] = __expf(dtv * Acoef[n]);
    }
}
__device__ __forceinline__ void load_bf162x8(const uint4* p0, const uint4* p1, bf162* v) {
    uint4 a = *p0, b = *p1;
    uint32_t* u = (uint32_t*)v;
    u[0] = a.x; u[1] = a.y; u[2] = a.z; u[3] = a.w;
    u[4] = b.x; u[5] = b.y; u[6] = b.z; u[7] = b.w;
}

// ---------------- fused weight conversion ----------------
#define N_WIN  (DDIM * 2 * EDIM)
#define N_WX   (EDIM * 64)
#define N_WDT  (RRANK * EDIM)
#define N_WOUT (EDIM * DDIM)
__global__ void wconv_kernel(const float* __restrict__ w_in,  bf16* __restrict__ o_in,
                             const float* __restrict__ w_x,   bf16* __restrict__ o_x,
                             const float* __restrict__ w_dt,  bf16* __restrict__ o_dt,
                             const float* __restrict__ w_out, bf16* __restrict__ o_out) {
    int i = (blockIdx.x * blockDim.x + threadIdx.x) * 4;
    const float* src; bf16* dst; int off;
    if (i < N_WIN)                      { src = w_in;  dst = o_in;  off = i; }
    else if (i < N_WIN + N_WX)          { src = w_x;   dst = o_x;   off = i - N_WIN; }
    else if (i < N_WIN + N_WX + N_WDT)  { src = w_dt;  dst = o_dt;  off = i - N_WIN - N_WX; }
    else if (i < N_WIN + N_WX + N_WDT + N_WOUT)
                                        { src = w_out; dst = o_out; off = i - N_WIN - N_WX - N_WDT; }
    else return;
    float4 v = *(const float4*)(src + off);
    bf16 o[4] = {__float2bfloat16(v.x), __float2bfloat16(v.y),
                 __float2bfloat16(v.z), __float2bfloat16(v.w)};
    *(uint64_t*)(dst + off) = *(uint64_t*)o;
}

// ---------------- RMSNorm -> bf16 ----------------
__global__ void rmsnorm_kernel(const float* __restrict__ x,
                               const float* __restrict__ w,
                               bf16* __restrict__ out) {
    int row = blockIdx.x;
    int tid = threadIdx.x;
    float4 v = ((const float4*)(x + (size_t)row * DDIM))[tid];
    float ss = v.x * v.x + v.y * v.y + v.z * v.z + v.w * v.w;
    #pragma unroll
    for (int o = 16; o > 0; o >>= 1) ss += __shfl_xor_sync(0xffffffffu, ss, o);
    __shared__ float sred[4];
    if ((tid & 31) == 0) sred[tid >> 5] = ss;
    __syncthreads();
    float tot = sred[0] + sred[1] + sred[2] + sred[3];
    float scale = rsqrtf(tot * (1.0f / DDIM) + 1e-6f);
    float4 wv = ((const float4*)w)[tid];
    bf16 o[4] = {__float2bfloat16(v.x * scale * wv.x),
                 __float2bfloat16(v.y * scale * wv.y),
                 __float2bfloat16(v.z * scale * wv.z),
                 __float2bfloat16(v.w * scale * wv.w)};
    *(uint64_t*)(out + (size_t)row * DDIM + tid * 4) = *(uint64_t*)o;
}

// ---------------- bf16 tensor-core GEMM, BK=64, 3-stage cp.async pipeline ----------------
// EPI: 2 fp32 + resid | 5 bf16 C2 only | 6 bf16 C2 + compact bf16 C3 (cols>=32)
template <int BM, int BN, int WGM, int WGN, int EPI>
__global__ void __launch_bounds__(WGM * WGN * 32)
gemm_bf16(const bf16* __restrict__ A, int lda,
          const bf16* __restrict__ B, int ldb,
          float* __restrict__ C, int ldc,
          int M, int N, int K,
          const float* __restrict__ resid,
          bf16* __restrict__ C2,
          bf16* __restrict__ C3) {
    constexpr int BK = 64;
    constexpr int NTHR = WGM * WGN * 32;
    constexpr int WM = BM / WGM;
    constexpr int WN = BN / WGN;
    constexpr int MT = WM / 16;
    constexpr int NT = WN / 8;
    static_assert(NT % 2 == 0, "NT even");
    constexpr int LDAS = BK + 8;
    constexpr int LDBS = BN + 8;
    constexpr int SA_ELEM = BM * LDAS;
    constexpr int SB_ELEM = BK * LDBS;
    constexpr int STAGE = SA_ELEM + SB_ELEM;

    extern __shared__ __align__(16) bf16 smem[];

    const int tid = threadIdx.x;
    const int warp = tid >> 5, lane = tid & 31;
    const int wm = (warp % WGM) * WM;
    const int wn = (warp / WGM) * WN;
    const int rowBase = blockIdx.y * BM;
    const int colBase = blockIdx.x * BN;

    float acc[MT][NT][4];
    #pragma unroll
    for (int i = 0; i < MT; i++)
        #pragma unroll
        for (int j = 0; j < NT; j++)
            #pragma unroll
            for (int q = 0; q < 4; q++) acc[i][j][q] = 0.0f;

    constexpr int A_CHUNKS = BM * BK / 8;
    constexpr int B_CHUNKS = BK * BN / 8;

    auto load_tile = [&](int s, int k0) {
        bf16* As = smem + s * STAGE;
        bf16* Bs = As + SA_ELEM;
        #pragma unroll
        for (int c = tid; c < A_CHUNKS; c += NTHR) {
            int row = c / (BK / 8);
            int col = (c % (BK / 8)) * 8;
            cp_async16(&As[row * LDAS + col],
                       &A[(size_t)(rowBase + row) * lda + k0 + col]);
        }
        #pragma unroll
        for (int c = tid; c < B_CHUNKS; c += NTHR) {
            int row = c / (BN / 8);
            int col = (c % (BN / 8)) * 8;
            cp_async16(&Bs[row * LDBS + col],
                       &B[(size_t)(k0 + row) * ldb + colBase + col]);
        }
        cp_commit();
    };

    const int KT = K / BK;
    load_tile(0, 0);
    if (KT > 1) load_tile(1, BK);

    const int arow = lane & 15, acol = (lane >> 4) * 8;
    const int bq = lane >> 3, bl = lane & 7;
    const int bk = (bq & 1) * 8 + bl, bn = (bq >> 1) * 8;

    int sbuf = 0;
    for (int kt = 0; kt < KT; kt++) {
        if (kt + 2 < KT) cp_wait<1>(); else cp_wait<0>();
        __syncthreads();
        if (kt + 2 < KT) {
            int s2 = sbuf + 2; if (s2 >= 3) s2 -= 3;
            load_tile(s2, (kt + 2) * BK);
        }
        const bf16* As = smem + sbuf * STAGE;
        const bf16* Bs = As + SA_ELEM;

        #pragma unroll
        for (int ks = 0; ks < 4; ks++) {
            uint32_t a[MT][4];
            #pragma unroll
            for (int mt = 0; mt < MT; mt++)
                ldsm_x4(a[mt][0], a[mt][1], a[mt][2], a[mt][3],
                        smem_u32(&As[(wm + mt * 16 + arow) * LDAS + ks * 16 + acol]));
            uint32_t b[NT][2];
            #pragma unroll
            for (int nt2 = 0; nt2 < NT / 2; nt2++) {
                uint32_t r0, r1, r2, r3;
                ldsm_x4_t(r0, r1, r2, r3,
                          smem_u32(&Bs[(ks * 16 + bk) * LDBS + wn + nt2 * 16 + bn]));
                b[2 * nt2][0] = r0; b[2 * nt2][1] = r1;
                b[2 * nt2 + 1][0] = r2; b[2 * nt2 + 1][1] = r3;
            }
            #pragma unroll
            for (int mt = 0; mt < MT; mt++)
                #pragma unroll
                for (int nt = 0; nt < NT; nt++)
                    mma_bf16(acc[mt][nt][0], acc[mt][nt][1], acc[mt][nt][2], acc[mt][nt][3],
                             a[mt][0], a[mt][1], a[mt][2], a[mt][3],
                             b[nt][0], b[nt][1]);
        }
        if (++sbuf == 3) sbuf = 0;
    }

    #pragma unroll
    for (int mt = 0; mt < MT; mt++) {
        #pragma unroll
        for (int nt = 0; nt < NT; nt++) {
            int col = colBase + wn + nt * 8 + (lane & 3) * 2;
            #pragma unroll
            for (int h = 0; h < 2; h++) {
                int row = rowBase + wm + mt * 16 + (lane >> 2) + h * 8;
                float v0 = acc[mt][nt][2 * h + 0];
                float v1 = acc[mt][nt][2 * h + 1];
                if (EPI == 2) {
                    const float2 r = *(const float2*)&resid[(size_t)row * ldc + col];
                    v0 += r.x; v1 += r.y;
                    *(float2*)&C[(size_t)row * ldc + col] = make_float2(v0, v1);
                }
                if (EPI == 5 || EPI == 6) {
                    bf16 o[2] = {__float2bfloat16(v0), __float2bfloat16(v1)};
                    *(uint32_t*)&C2[(size_t)row * ldc + col] = *(uint32_t*)o;
                    if (EPI == 6 && col >= RRANK)
                        *(uint32_t*)&C3[(size_t)row * 32 + col - RRANK] = *(uint32_t*)o;
                }
            }
        }
    }
}
#define GEMM_BIG_SMEM  (3 * (128 * 72 + 64 * 136) * 2)   // 107520
#define GEMM_DBL_SMEM  (3 * (64 * 72 + 64 * 72) * 2)     // 55296

// ---------------- dedicated dt GEMM ----------------
__global__ void __launch_bounds__(256)
dtgemm_kernel(const bf16* __restrict__ A,
              const bf16* __restrict__ B,
              const float* __restrict__ bias,
              float* __restrict__ dtT) {
    __shared__ __align__(16) bf16 As[128][40];
    __shared__ __align__(16) bf16 Bs[32][136];
    __shared__ float sbuf[32][129];

    const int tid = threadIdx.x, warp = tid >> 5, lane = tid & 31;
    const int wm = (warp & 1) * 64;
    const int wn = (warp >> 1) * 32;
    const int rowBase = blockIdx.y * 128;
    const int colBase = blockIdx.x * 128;

    #pragma unroll
    for (int c = tid; c < 512; c += 256) {
        int r = c >> 2, q = (c & 3) * 8;
        cp_async16(&As[r][q], &A[(size_t)(rowBase + r) * 64 + q]);
    }
    #pragma unroll
    for (int c = tid; c < 512; c += 256) {
        int r = c >> 4, q = (c & 15) * 8;
        cp_async16(&Bs[r][q], &B[(size_t)r * EDIM + colBase + q]);
    }
    cp_commit(); cp_wait<0>(); __syncthreads();

    float acc[4][4][4];
    #pragma unroll
    for (int i = 0; i < 4; i++)
        #pragma unroll
        for (int j = 0; j < 4; j++)
            #pragma unroll
            for (int q = 0; q < 4; q++) acc[i][j][q] = 0.0f;

    const int arow = lane & 15, acol = (lane >> 4) * 8;
    const int bq = lane >> 3, bl = lane & 7;
    const int bk = (bq & 1) * 8 + bl, bn = (bq >> 1) * 8;

    #pragma unroll
    for (int ks = 0; ks < 2; ks++) {
        uint32_t a[4][4];
        #pragma unroll
        for (int mt = 0; mt < 4; mt++)
            ldsm_x4(a[mt][0], a[mt][1], a[mt][2], a[mt][3],
                    smem_u32(&As[wm + mt * 16 + arow][ks * 16 + acol]));
        uint32_t b[4][2];
        #pragma unroll
        for (int nt2 = 0; nt2 < 2; nt2++) {
            uint32_t r0, r1, r2, r3;
            ldsm_x4_t(r0, r1, r2, r3,
                      smem_u32(&Bs[ks * 16 + bk][wn + nt2 * 16 + bn]));
            b[2 * nt2][0] = r0; b[2 * nt2][1] = r1;
            b[2 * nt2 + 1][0] = r2; b[2 * nt2 + 1][1] = r3;
        }
        #pragma unroll
        for (int mt = 0; mt < 4; mt++)
            #pragma unroll
            for (int nt = 0; nt < 4; nt++)
                mma_bf16(acc[mt][nt][0], acc[mt][nt][1], acc[mt][nt][2], acc[mt][nt][3],
                         a[mt][0], a[mt][1], a[mt][2], a[mt][3],
                         b[nt][0], b[nt][1]);
    }

    const int bb = rowBase >> 11;
    const int tb = rowBase & 2047;
    #pragma unroll
    for (int cc = 0; cc < 4; cc++) {
        __syncthreads();
        if (wn == cc * 32) {
            #pragma unroll
            for (int mt = 0; mt < 4; mt++)
                #pragma unroll
                for (int nt = 0; nt < 4; nt++) {
                    int c = nt * 8 + (lane & 3) * 2;
                    int col = colBase + wn + c;
                    #pragma unroll
                    for (int h = 0; h < 2; h++) {
                        int r = wm + mt * 16 + (lane >> 2) + h * 8;
                        sbuf[c][r]     = softplus_f(acc[mt][nt][2 * h]     + bias[col]);
                        sbuf[c + 1][r] = softplus_f(acc[mt][nt][2 * h + 1] + bias[col + 1]);
                    }
                }
        }
        __syncthreads();
        for (int j = tid; j < 32 * 128; j += 256) {
            int c = j >> 7, r = j & 127;
            dtT[((size_t)bb * EDIM + colBase + cc * 32 + c) * LSEQ + tb + r] = sbuf[c][r];
        }
    }
}

// ---------------- fused conv+silu+transposes (32x64 tile, float2 smem) ----------------
__global__ void __launch_bounds__(256)
conv_fused_kernel(const bf16* __restrict__ xzb,
                  const float* __restrict__ conv_w,
                  const float* __restrict__ conv_b,
                  bf16* __restrict__ xsb,
                  float* __restrict__ xsT,
                  bf16* __restrict__ zT) {
    __shared__ __align__(8) float xt[35][66];
    __shared__ __align__(8) float st[32][66];
    __shared__ bf16  zt[32][66];

    const int e0 = blockIdx.x * 64;
    const int t0 = blockIdx.y * 32;
    const int b  = blockIdx.z;
    const int tx = threadIdx.x & 31, ty = threadIdx.x >> 5;

    for (int i = ty; i < 35; i += 8) {
        int t = t0 - 3 + i;
        uint32_t pv = 0;
        if (t >= 0)
            pv = *(const uint32_t*)&xzb[((size_t)(b * LSEQ + t)) * (2 * EDIM) + e0 + 2 * tx];
        bf16 p[2]; *(uint32_t*)p = pv;
        *(float2*)&xt[i][2 * tx] = make_float2(__bfloat162float(p[0]), __bfloat162float(p[1]));
    }
    for (int i = ty; i < 32; i += 8) {
        uint32_t pv = *(const uint32_t*)&xzb[((size_t)(b * LSEQ + t0 + i)) * (2 * EDIM) + EDIM + e0 + 2 * tx];
        *(uint32_t*)&zt[i][2 * tx] = pv;
    }
    __syncthreads();

    const int ea = e0 + 2 * tx, ebx = ea + 1;
    const float w0a = conv_w[ea * 4 + 0], w1a = conv_w[ea * 4 + 1],
                w2a = conv_w[ea * 4 + 2], w3a = conv_w[ea * 4 + 3], bba = conv_b[ea];
    const float w0b = conv_w[ebx * 4 + 0], w1b = conv_w[ebx * 4 + 1],
                w2b = conv_w[ebx * 4 + 2], w3b = conv_w[ebx * 4 + 3], bbb = conv_b[ebx];

    for (int i = ty; i < 32; i += 8) {
        float2 v0 = *(const float2*)&xt[i][2 * tx];
        float2 v1 = *(const float2*)&xt[i + 1][2 * tx];
        float2 v2 = *(const float2*)&xt[i + 2][2 * tx];
        float2 v3 = *(const float2*)&xt[i + 3][2 * tx];
        float a0 = bba + w0a * v0.x + w1a * v1.x + w2a * v2.x + w3a * v3.x;
        float a1 = bbb + w0b * v0.y + w1b * v1.y + w2b * v2.y + w3b * v3.y;
        float s0 = a0 / (1.0f + __expf(-a0));
        float s1 = a1 / (1.0f + __expf(-a1));
        *(float2*)&st[i][2 * tx] = make_float2(s0, s1);
        bf16 o[2] = {__float2bfloat16(s0), __float2bfloat16(s1)};
        *(uint32_t*)&xsb[((size_t)(b * LSEQ + t0 + i)) * EDIM + e0 + 2 * tx] = *(uint32_t*)o;
    }
    __syncthreads();

    for (int i = ty; i < 64; i += 8) {
        xsT[((size_t)b * EDIM + e0 + i) * LSEQ + t0 + tx] = st[tx][i];
        zT [((size_t)b * EDIM + e0 + i) * LSEQ + t0 + tx] = zt[tx][i];
    }
}

// ---------------- chunked parallel selective scan (16 warps/block, packed bf16x2) ----------------
#define CHUNK 64
#define BC_SMEM_BYTES 131072
#define NWARP_SCAN 16
#define YSTAGE_BYTES  (NWARP_SCAN * (LSEQ + 32) * 2)
#define SCAN_SMEM (BC_SMEM_BYTES + YSTAGE_BYTES)       // 197632

__device__ __forceinline__ const uint4* bc_addr(const char* bcs, int t, int c) {
    int slot = ((t & 1) * 4 + c) ^ ((t >> 6) & 7);
    return (const uint4*)(bcs + (t >> 1) * 128 + slot * 16);
}

__global__ void __launch_bounds__(NWARP_SCAN * 32)
scan_kernel(const float* __restrict__ dtT,
            const float* __restrict__ xsT,
            const bf16*  __restrict__ zT,
            const bf16*  __restrict__ bcb,
            const float* __restrict__ A_log,
            const float* __restrict__ D_skip,
            bf16* __restrict__ y) {
    extern __shared__ __align__(16) char dyn[];
    char* bcs = dyn;
    bf16 (*ystage)[LSEQ + 32] = (bf16 (*)[LSEQ + 32])(dyn + BC_SMEM_BYTES);

    const int b    = blockIdx.y;
    const int warp = threadIdx.x >> 5;
    const int lane = threadIdx.x & 31;
    const int e    = blockIdx.x * NWARP_SCAN + warp;

    {
        const bf16* src = bcb + (size_t)b * LSEQ * 32;
        for (int k = threadIdx.x; k < 8192; k += NWARP_SCAN * 32) {
            int t = k >> 2, c = k & 3;
            int slot = ((t & 1) * 4 + c) ^ ((t >> 6) & 7);
            cp_async16(bcs + (t >> 1) * 128 + slot * 16, src + k * 8);
        }
        cp_commit(); cp_wait<0>();
    }
    __syncthreads();

    float Acoef[NST];
    bool structured = true;
    #pragma unroll
    for (int n = 0; n < NST; n++) {
        Acoef[n] = -__expf(A_log[e * NST + n]);
        structured &= fabsf(Acoef[n] + (float)(n + 1)) < 1e-4f * (float)(n + 1);
    }
    const float dsk = D_skip[e];

    const float* dtp = dtT + ((size_t)b * EDIM + e) * LSEQ;
    const float* xsp = xsT + ((size_t)b * EDIM + e) * LSEQ;
    const bf16*  zp  = zT  + ((size_t)b * EDIM + e) * LSEQ;

    const int t0 = lane * CHUNK;

    float P[NST];
    bf162 q2[8];
    #pragma unroll
    for (int n = 0; n < NST; n++) P[n] = 1.0f;
    #pragma unroll
    for (int j = 0; j < 8; j++) q2[j] = __floats2bfloat162_rn(0.0f, 0.0f);

    for (int s4 = 0; s4 < CHUNK; s4 += 4) {
        float4 d4 = *(const float4*)&dtp[t0 + s4];
        float4 x4 = *(const float4*)&xsp[t0 + s4];
        float dv[4] = {d4.x, d4.y, d4.z, d4.w};
        float xv[4] = {x4.x, x4.y, x4.z, x4.w};
        #pragma unroll
        for (int u = 0; u < 4; u++) {
            const int t = t0 + s4 + u;
            bf162 Bv2[8];
            load_bf162x8(bc_addr(bcs, t, 0), bc_addr(bcs, t, 1), Bv2);
            float dA[NST];
            compute_dA(dv[u], Acoef, structured, dA);
            const bf162 dx2 = __float2bfloat162_rn(dv[u] * xv[u]);
            #pragma unroll
            for (int j = 0; j < 8; j++) {
                bf162 dA2 = __floats2bfloat162_rn(dA[2 * j], dA[2 * j + 1]);
                q2[j] = __hfma2(dA2, q2[j], __hmul2(dx2, Bv2[j]));
                P[2 * j]     *= dA[2 * j];
                P[2 * j + 1] *= dA[2 * j + 1];
            }
        }
    }

    float q[NST];
    #pragma unroll
    for (int j = 0; j < 8; j++) {
        q[2 * j]     = __low2float(q2[j]);
        q[2 * j + 1] = __high2float(q2[j]);
    }

    #pragma unroll
    for (int d = 1; d < 32; d <<= 1) {
        #pragma unroll
        for (int n = 0; n < NST; n++) {
            float Pp = __shfl_up_sync(0xffffffffu, P[n], d);
            float qp = __shfl_up_sync(0xffffffffu, q[n], d);
            if (lane >= d) {
                q[n] = fmaf(P[n], qp, q[n]);
                P[n] *= Pp;
            }
        }
    }
    bf162 h2[8];
    #pragma unroll
    for (int n = 0; n < NST; n += 2) {
        float v0 = __shfl_up_sync(0xffffffffu, q[n], 1);
        float v1 = __shfl_up_sync(0xffffffffu, q[n + 1], 1);
        if (lane == 0) { v0 = 0.0f; v1 = 0.0f; }
        h2[n >> 1] = __floats2bfloat162_rn(v0, v1);
    }

    for (int s8 = 0; s8 < CHUNK; s8 += 8) {
        float4 d4a = *(const float4*)&dtp[t0 + s8];
        float4 d4b = *(const float4*)&dtp[t0 + s8 + 4];
        float4 x4a = *(const float4*)&xsp[t0 + s8];
        float4 x4b = *(const float4*)&xsp[t0 + s8 + 4];
        uint4  zv8 = *(const uint4*)&zp[t0 + s8];
        float dv[8] = {d4a.x, d4a.y, d4a.z, d4a.w, d4b.x, d4b.y, d4b.z, d4b.w};
        float xv[8] = {x4a.x, x4a.y, x4a.z, x4a.w, x4b.x, x4b.y, x4b.z, x4b.w};
        float zv[8];
        unpack8(zv8, zv);
        #pragma unroll
        for (int u = 0; u < 8; u++) {
            const int t = t0 + s8 + u;
            bf162 Bv2[8], Cv2[8];
            load_bf162x8(bc_addr(bcs, t, 0), bc_addr(bcs, t, 1), Bv2);
            load_bf162x8(bc_addr(bcs, t, 2), bc_addr(bcs, t, 3), Cv2);
            float dA[NST];
            compute_dA(dv[u], Acoef, structured, dA);
            const bf162 dx2 = __float2bfloat162_rn(dv[u] * xv[u]);
            bf162 yac = __floats2bfloat162_rn(0.0f, 0.0f);
            #pragma unroll
            for (int j = 0; j < 8; j++) {
                bf162 dA2 = __floats2bfloat162_rn(dA[2 * j], dA[2 * j + 1]);
                h2[j] = __hfma2(dA2, h2[j], __hmul2(dx2, Bv2[j]));
                yac = __hfma2(h2[j], Cv2[j], yac);
            }
            const float yacc = __low2float(yac) + __high2float(yac);
            const float zz  = zv[u];
            const float sig = 1.0f / (1.0f + __expf(-zz));
            const float out = (yacc + xv[u] * dsk) * (zz * sig);
            ystage[warp][t + (t >> 6)] = __float2bfloat16(out);
        }
    }
    __syncthreads();

    const int e0 = blockIdx.x * NWARP_SCAN;
    for (int t = threadIdx.x; t < LSEQ; t += NWARP_SCAN * 32) {
        bf16 v[NWARP_SCAN];
        #pragma unroll
        for (int w = 0; w < NWARP_SCAN; w++) v[w] = ystage[w][t + (t >> 6)];
        *(uint4*)&y[((size_t)(b * LSEQ + t)) * EDIM + e0]     = ((uint4*)v)[0];
        *(uint4*)&y[((size_t)(b * LSEQ + t)) * EDIM + e0 + 8] = ((uint4*)v)[1];
    }
}

// ---------------- launcher ----------------
extern "C" void kernel_launch(void* const* d_in, const int* in_sizes, int n_in,
                              void* d_out, int out_size) {
    const float* hidden = (const float*)d_in[0];
    const float* norm_w = (const float*)d_in[1];
    const float* W_in   = (const float*)d_in[2];
    const float* conv_w = (const float*)d_in[3];
    const float* conv_b = (const float*)d_in[4];
    const float* W_x    = (const float*)d_in[5];
    const float* W_dt   = (const float*)d_in[6];
    const float* b_dt   = (const float*)d_in[7];
    const float* A_log  = (const float*)d_in[8];
    const float* D_skip = (const float*)d_in[9];
    const float* W_out  = (const float*)d_in[10];
    float* out = (float*)d_out;

    float *p_dtT, *p_xsT;
    bf16 *p_xzb, *p_zT, *p_nrmb, *p_xsb, *p_dblb, *p_bcb, *p_yb;
    bf16 *p_winb, *p_wxb, *p_wdtb, *p_woutb;
    cudaGetSymbolAddress((void**)&p_xzb,  g_xzb);
    cudaGetSymbolAddress((void**)&p_dtT,  g_dtT);
    cudaGetSymbolAddress((void**)&p_xsT,  g_xsT);
    cudaGetSymbolAddress((void**)&p_zT,   g_zT);
    cudaGetSymbolAddress((void**)&p_nrmb, g_nrmb);
    cudaGetSymbolAddress((void**)&p_xsb,  g_xsb);
    cudaGetSymbolAddress((void**)&p_dblb, g_dblb);
    cudaGetSymbolAddress((void**)&p_bcb,  g_bcb);
    cudaGetSymbolAddress((void**)&p_yb,   g_yb);
    cudaGetSymbolAddress((void**)&p_winb, g_winb);
    cudaGetSymbolAddress((void**)&p_wxb,  g_wxb);
    cudaGetSymbolAddress((void**)&p_wdtb, g_wdtb);
    cudaGetSymbolAddress((void**)&p_woutb, g_woutb);

    cudaFuncSetAttribute(scan_kernel, cudaFuncAttributeMaxDynamicSharedMemorySize, SCAN_SMEM);
    cudaFuncSetAttribute(gemm_bf16<128, 128, 2, 4, 5>,
                         cudaFuncAttributeMaxDynamicSharedMemorySize, GEMM_BIG_SMEM);
    cudaFuncSetAttribute(gemm_bf16<128, 128, 2, 4, 2>,
                         cudaFuncAttributeMaxDynamicSharedMemorySize, GEMM_BIG_SMEM);
    cudaFuncSetAttribute(gemm_bf16<64, 64, 4, 2, 6>,
                         cudaFuncAttributeMaxDynamicSharedMemorySize, GEMM_DBL_SMEM);

    // 0) fused weight conversion
    {
        int total = (N_WIN + N_WX + N_WDT + N_WOUT) / 4;
        wconv_kernel<<<(total + 255) / 256, 256>>>(W_in, p_winb, W_x, p_wxb,
                                                   W_dt, p_wdtb, W_out, p_woutb);
    }

    // 1) RMSNorm -> bf16
    rmsnorm_kernel<<<NTOK, 128>>>(hidden, norm_w, p_nrmb);

    // 2) xz = nrm @ W_in -> bf16 only
    gemm_bf16<128, 128, 2, 4, 5><<<dim3(2 * EDIM / 128, NTOK / 128), 256, GEMM_BIG_SMEM>>>(
        p_nrmb, DDIM, p_winb, 2 * EDIM, nullptr, 2 * EDIM,
        NTOK, 2 * EDIM, DDIM, nullptr, p_xzb, nullptr);

    // 3) fused conv + silu + transposes
    conv_fused_kernel<<<dim3(EDIM / 64, LSEQ / 32, BSZ), 256>>>(
        p_xzb, conv_w, conv_b, p_xsb, p_xsT, p_zT);

    // 4) dbl = xs @ W_x -> bf16 full + bf16 compact BC
    gemm_bf16<64, 64, 4, 2, 6><<<dim3(1, NTOK / 64), 256, GEMM_DBL_SMEM>>>(
        p_xsb, EDIM, p_wxb, 64, nullptr, 64,
        NTOK, 64, EDIM, nullptr, p_dblb, p_bcb);

    // 5) dtT = softplus(dbl[:, :32] @ W_dt + b_dt), transposed write
    dtgemm_kernel<<<dim3(EDIM / 128, NTOK / 128), 256>>>(p_dblb, p_wdtb, b_dt, p_dtT);

    // 6) chunked parallel scan (16 warps/block, packed bf16x2) -> bf16 y
    scan_kernel<<<dim3(EDIM / NWARP_SCAN, BSZ), NWARP_SCAN * 32, SCAN_SMEM>>>(
        p_dtT, p_xsT, p_zT, p_bcb, A_log, D_skip, p_yb);

    // 7) out = y @ W_out + hidden -> fp32
    gemm_bf16<128, 128, 2, 4, 2><<<dim3(DDIM / 128, NTOK / 128), 256, GEMM_BIG_SMEM>>>(
        p_yb, EDIM, p_woutb, DDIM, out, DDIM,
        NTOK, DDIM, EDIM, hidden, nullptr, nullptr);
}

// round 16
// speedup vs baseline: 1.3085x; 1.0233x over previous
#include <cuda_runtime.h>
#include <cuda_bf16.h>
#include <cstdint>

using bf16 = __nv_bfloat16;
using bf162 = __nv_bfloat162;

// Problem constants
#define BSZ 4
#define LSEQ 2048
#define DDIM 512
#define EDIM 1024
#define NST 16
#define RRANK 32
#define NTOK (BSZ * LSEQ)          // 8192

// ---------------- scratch (device globals) ----------------
__device__ bf16  g_xzb[NTOK * 2 * EDIM];
__device__ bf16  g_dtT[NTOK * EDIM];        // [b][e][t] bf16
__device__ bf16  g_xsT[NTOK * EDIM];        // [b][e][t] bf16
__device__ bf16  g_zT [NTOK * EDIM];
__device__ bf16  g_nrmb[NTOK * DDIM];
__device__ bf16  g_xsb [NTOK * EDIM];
__device__ bf16  g_dblb[NTOK * 64];
__device__ bf16  g_bcb [NTOK * 32];
__device__ bf16  g_yb  [NTOK * EDIM];
__device__ bf16  g_winb [DDIM * 2 * EDIM];
__device__ bf16  g_wxb  [EDIM * 64];
__device__ bf16  g_wdtb [RRANK * EDIM];
__device__ bf16  g_woutb[EDIM * DDIM];

// ---------------- PTX helpers ----------------
__device__ __forceinline__ uint32_t smem_u32(const void* p) {
    return (uint32_t)__cvta_generic_to_shared(p);
}
__device__ __forceinline__ void cp_async16(void* s, const void* g) {
    asm volatile("cp.async.cg.shared.global [%0], [%1], 16;\n"
                 :: "r"(smem_u32(s)), "l"(g));
}
__device__ __forceinline__ void cp_commit() { asm volatile("cp.async.commit_group;\n"); }
template <int N> __device__ __forceinline__ void cp_wait() {
    asm volatile("cp.async.wait_group %0;\n" :: "n"(N));
}
__device__ __forceinline__ void ldsm_x4(uint32_t& r0, uint32_t& r1, uint32_t& r2, uint32_t& r3,
                                        uint32_t a) {
    asm volatile("ldmatrix.sync.aligned.m8n8.x4.shared.b16 {%0,%1,%2,%3}, [%4];\n"
                 : "=r"(r0), "=r"(r1), "=r"(r2), "=r"(r3) : "r"(a));
}
__device__ __forceinline__ void ldsm_x4_t(uint32_t& r0, uint32_t& r1, uint32_t& r2, uint32_t& r3,
                                          uint32_t a) {
    asm volatile("ldmatrix.sync.aligned.m8n8.x4.trans.shared.b16 {%0,%1,%2,%3}, [%4];\n"
                 : "=r"(r0), "=r"(r1), "=r"(r2), "=r"(r3) : "r"(a));
}
__device__ __forceinline__ void mma_bf16(float& d0, float& d1, float& d2, float& d3,
                                         uint32_t a0, uint32_t a1, uint32_t a2, uint32_t a3,
                                         uint32_t b0, uint32_t b1) {
    asm volatile("mma.sync.aligned.m16n8k16.row.col.f32.bf16.bf16.f32 "
                 "{%0,%1,%2,%3}, {%4,%5,%6,%7}, {%8,%9}, {%0,%1,%2,%3};\n"
                 : "+f"(d0), "+f"(d1), "+f"(d2), "+f"(d3)
                 : "r"(a0), "r"(a1), "r"(a2), "r"(a3), "r"(b0), "r"(b1));
}
__device__ __forceinline__ float softplus_f(float v) {
    return (v > 20.0f) ? v : log1pf(expf(v));
}
__device__ __forceinline__ void unpack8(uint4 v, float* f) {
    uint32_t u[4] = {v.x, v.y, v.z, v.w};
    #pragma unroll
    for (int j = 0; j < 4; j++) {
        f[2 * j]     = __uint_as_float(u[j] << 16);
        f[2 * j + 1] = __uint_as_float(u[j] & 0xffff0000u);
    }
}
__device__ __forceinline__ void unpack4(uint2 v, float* f) {
    uint32_t u[2] = {v.x, v.y};
    #pragma unroll
    for (int j = 0; j < 2; j++) {
        f[2 * j]     = __uint_as_float(u[j] << 16);
        f[2 * j + 1] = __uint_as_float(u[j] & 0xffff0000u);
    }
}
// dA[n] = exp(dtv * Acoef[n]); fast path when Acoef[n] == -(n+1).
__device__ __forceinline__ void compute_dA(float dtv, const float* Acoef,
                                           bool structured, float* dA) {
    if (structured) {
        const float r1 = __expf(-dtv);
        const float r2 = r1 * r1;
        const float r4 = r2 * r2;
        const float r8 = r4 * r4;
        dA[0] = r1;       dA[1] = r2;       dA[2] = r2 * r1;  dA[3] = r4;
        dA[4] = r4 * r1;  dA[5] = r4 * r2;  dA[6] = r4 * dA[2]; dA[7] = r8;
        dA[8]  = r8 * r1;   dA[9]  = r8 * r2;   dA[10] = r8 * dA[2]; dA[11] = r8 * r4;
        dA[12] = r8 * dA[4]; dA[13] = r8 * dA[5]; dA[14] = r8 * dA[6]; dA[15] = r8 * r8;
    } else {
        #pragma unroll
        for (int n = 0; n < NST; n++) dA[n] = __expf(dtv * Acoef[n]);
    }
}
__device__ __forceinline__ void load_bf162x8(const uint4* p0, const uint4* p1, bf162* v) {
    uint4 a = *p0, b = *p1;
    uint32_t* u = (uint32_t*)v;
    u[0] = a.x; u[1] = a.y; u[2] = a.z; u[3] = a.w;
    u[4] = b.x; u[5] = b.y; u[6] = b.z; u[7] = b.w;
}

// ---------------- fused weight conversion ----------------
#define N_WIN  (DDIM * 2 * EDIM)
#define N_WX   (EDIM * 64)
#define N_WDT  (RRANK * EDIM)
#define N_WOUT (EDIM * DDIM)
__global__ void wconv_kernel(const float* __restrict__ w_in,  bf16* __restrict__ o_in,
                             const float* __restrict__ w_x,   bf16* __restrict__ o_x,
                             const float* __restrict__ w_dt,  bf16* __restrict__ o_dt,
                             const float* __restrict__ w_out, bf16* __restrict__ o_out) {
    int i = (blockIdx.x * blockDim.x + threadIdx.x) * 4;
    const float* src; bf16* dst; int off;
    if (i < N_WIN)                      { src = w_in;  dst = o_in;  off = i; }
    else if (i < N_WIN + N_WX)          { src = w_x;   dst = o_x;   off = i - N_WIN; }
    else if (i < N_WIN + N_WX + N_WDT)  { src = w_dt;  dst = o_dt;  off = i - N_WIN - N_WX; }
    else if (i < N_WIN + N_WX + N_WDT + N_WOUT)
                                        { src = w_out; dst = o_out; off = i - N_WIN - N_WX - N_WDT; }
    else return;
    float4 v = *(const float4*)(src + off);
    bf16 o[4] = {__float2bfloat16(v.x), __float2bfloat16(v.y),
                 __float2bfloat16(v.z), __float2bfloat16(v.w)};
    *(uint64_t*)(dst + off) = *(uint64_t*)o;
}

// ---------------- RMSNorm -> bf16 ----------------
__global__ void rmsnorm_kernel(const float* __restrict__ x,
                               const float* __restrict__ w,
                               bf16* __restrict__ out) {
    int row = blockIdx.x;
    int tid = threadIdx.x;
    float4 v = ((const float4*)(x + (size_t)row * DDIM))[tid];
    float ss = v.x * v.x + v.y * v.y + v.z * v.z + v.w * v.w;
    #pragma unroll
    for (int o = 16; o > 0; o >>= 1) ss += __shfl_xor_sync(0xffffffffu, ss, o);
    __shared__ float sred[4];
    if ((tid & 31) == 0) sred[tid >> 5] = ss;
    __syncthreads();
    float tot = sred[0] + sred[1] + sred[2] + sred[3];
    float scale = rsqrtf(tot * (1.0f / DDIM) + 1e-6f);
    float4 wv = ((const float4*)w)[tid];
    bf16 o[4] = {__float2bfloat16(v.x * scale * wv.x),
                 __float2bfloat16(v.y * scale * wv.y),
                 __float2bfloat16(v.z * scale * wv.z),
                 __float2bfloat16(v.w * scale * wv.w)};
    *(uint64_t*)(out + (size_t)row * DDIM + tid * 4) = *(uint64_t*)o;
}

// ---------------- bf16 tensor-core GEMM, BK=64, 3-stage cp.async pipeline ----------------
// EPI: 2 fp32 + resid | 5 bf16 C2 only | 6 bf16 C2 + compact bf16 C3 (cols>=32)
template <int BM, int BN, int WGM, int WGN, int EPI>
__global__ void __launch_bounds__(WGM * WGN * 32)
gemm_bf16(const bf16* __restrict__ A, int lda,
          const bf16* __restrict__ B, int ldb,
          float* __restrict__ C, int ldc,
          int M, int N, int K,
          const float* __restrict__ resid,
          bf16* __restrict__ C2,
          bf16* __restrict__ C3) {
    constexpr int BK = 64;
    constexpr int NTHR = WGM * WGN * 32;
    constexpr int WM = BM / WGM;
    constexpr int WN = BN / WGN;
    constexpr int MT = WM / 16;
    constexpr int NT = WN / 8;
    static_assert(NT % 2 == 0, "NT even");
    constexpr int LDAS = BK + 8;
    constexpr int LDBS = BN + 8;
    constexpr int SA_ELEM = BM * LDAS;
    constexpr int SB_ELEM = BK * LDBS;
    constexpr int STAGE = SA_ELEM + SB_ELEM;

    extern __shared__ __align__(16) bf16 smem[];

    const int tid = threadIdx.x;
    const int warp = tid >> 5, lane = tid & 31;
    const int wm = (warp % WGM) * WM;
    const int wn = (warp / WGM) * WN;
    const int rowBase = blockIdx.y * BM;
    const int colBase = blockIdx.x * BN;

    float acc[MT][NT][4];
    #pragma unroll
    for (int i = 0; i < MT; i++)
        #pragma unroll
        for (int j = 0; j < NT; j++)
            #pragma unroll
            for (int q = 0; q < 4; q++) acc[i][j][q] = 0.0f;

    constexpr int A_CHUNKS = BM * BK / 8;
    constexpr int B_CHUNKS = BK * BN / 8;

    auto load_tile = [&](int s, int k0) {
        bf16* As = smem + s * STAGE;
        bf16* Bs = As + SA_ELEM;
        #pragma unroll
        for (int c = tid; c < A_CHUNKS; c += NTHR) {
            int row = c / (BK / 8);
            int col = (c % (BK / 8)) * 8;
            cp_async16(&As[row * LDAS + col],
                       &A[(size_t)(rowBase + row) * lda + k0 + col]);
        }
        #pragma unroll
        for (int c = tid; c < B_CHUNKS; c += NTHR) {
            int row = c / (BN / 8);
            int col = (c % (BN / 8)) * 8;
            cp_async16(&Bs[row * LDBS + col],
                       &B[(size_t)(k0 + row) * ldb + colBase + col]);
        }
        cp_commit();
    };

    const int KT = K / BK;
    load_tile(0, 0);
    if (KT > 1) load_tile(1, BK);

    const int arow = lane & 15, acol = (lane >> 4) * 8;
    const int bq = lane >> 3, bl = lane & 7;
    const int bk = (bq & 1) * 8 + bl, bn = (bq >> 1) * 8;

    int sbuf = 0;
    for (int kt = 0; kt < KT; kt++) {
        if (kt + 2 < KT) cp_wait<1>(); else cp_wait<0>();
        __syncthreads();
        if (kt + 2 < KT) {
            int s2 = sbuf + 2; if (s2 >= 3) s2 -= 3;
            load_tile(s2, (kt + 2) * BK);
        }
        const bf16* As = smem + sbuf * STAGE;
        const bf16* Bs = As + SA_ELEM;

        #pragma unroll
        for (int ks = 0; ks < 4; ks++) {
            uint32_t a[MT][4];
            #pragma unroll
            for (int mt = 0; mt < MT; mt++)
                ldsm_x4(a[mt][0], a[mt][1], a[mt][2], a[mt][3],
                        smem_u32(&As[(wm + mt * 16 + arow) * LDAS + ks * 16 + acol]));
            uint32_t b[NT][2];
            #pragma unroll
            for (int nt2 = 0; nt2 < NT / 2; nt2++) {
                uint32_t r0, r1, r2, r3;
                ldsm_x4_t(r0, r1, r2, r3,
                          smem_u32(&Bs[(ks * 16 + bk) * LDBS + wn + nt2 * 16 + bn]));
                b[2 * nt2][0] = r0; b[2 * nt2][1] = r1;
                b[2 * nt2 + 1][0] = r2; b[2 * nt2 + 1][1] = r3;
            }
            #pragma unroll
            for (int mt = 0; mt < MT; mt++)
                #pragma unroll
                for (int nt = 0; nt < NT; nt++)
                    mma_bf16(acc[mt][nt][0], acc[mt][nt][1], acc[mt][nt][2], acc[mt][nt][3],
                             a[mt][0], a[mt][1], a[mt][2], a[mt][3],
                             b[nt][0], b[nt][1]);
        }
        if (++sbuf == 3) sbuf = 0;
    }

    #pragma unroll
    for (int mt = 0; mt < MT; mt++) {
        #pragma unroll
        for (int nt = 0; nt < NT; nt++) {
            int col = colBase + wn + nt * 8 + (lane & 3) * 2;
            #pragma unroll
            for (int h = 0; h < 2; h++) {
                int row = rowBase + wm + mt * 16 + (lane >> 2) + h * 8;
                float v0 = acc[mt][nt][2 * h + 0];
                float v1 = acc[mt][nt][2 * h + 1];
                if (EPI == 2) {
                    const float2 r = *(const float2*)&resid[(size_t)row * ldc + col];
                    v0 += r.x; v1 += r.y;
                    *(float2*)&C[(size_t)row * ldc + col] = make_float2(v0, v1);
                }
                if (EPI == 5 || EPI == 6) {
                    bf16 o[2] = {__float2bfloat16(v0), __float2bfloat16(v1)};
                    *(uint32_t*)&C2[(size_t)row * ldc + col] = *(uint32_t*)o;
                    if (EPI == 6 && col >= RRANK)
                        *(uint32_t*)&C3[(size_t)row * 32 + col - RRANK] = *(uint32_t*)o;
                }
            }
        }
    }
}
#define GEMM_BIG_SMEM  (3 * (128 * 72 + 64 * 136) * 2)   // 107520
#define GEMM_DBL_SMEM  (3 * (64 * 72 + 64 * 72) * 2)     // 55296

// ---------------- dedicated dt GEMM (bf16 transposed out) ----------------
__global__ void __launch_bounds__(256)
dtgemm_kernel(const bf16* __restrict__ A,
              const bf16* __restrict__ B,
              const float* __restrict__ bias,
              bf16* __restrict__ dtT) {
    __shared__ __align__(16) bf16 As[128][40];
    __shared__ __align__(16) bf16 Bs[32][136];
    __shared__ float sbuf[32][129];

    const int tid = threadIdx.x, warp = tid >> 5, lane = tid & 31;
    const int wm = (warp & 1) * 64;
    const int wn = (warp >> 1) * 32;
    const int rowBase = blockIdx.y * 128;
    const int colBase = blockIdx.x * 128;

    #pragma unroll
    for (int c = tid; c < 512; c += 256) {
        int r = c >> 2, q = (c & 3) * 8;
        cp_async16(&As[r][q], &A[(size_t)(rowBase + r) * 64 + q]);
    }
    #pragma unroll
    for (int c = tid; c < 512; c += 256) {
        int r = c >> 4, q = (c & 15) * 8;
        cp_async16(&Bs[r][q], &B[(size_t)r * EDIM + colBase + q]);
    }
    cp_commit(); cp_wait<0>(); __syncthreads();

    float acc[4][4][4];
    #pragma unroll
    for (int i = 0; i < 4; i++)
        #pragma unroll
        for (int j = 0; j < 4; j++)
            #pragma unroll
            for (int q = 0; q < 4; q++) acc[i][j][q] = 0.0f;

    const int arow = lane & 15, acol = (lane >> 4) * 8;
    const int bq = lane >> 3, bl = lane & 7;
    const int bk = (bq & 1) * 8 + bl, bn = (bq >> 1) * 8;

    #pragma unroll
    for (int ks = 0; ks < 2; ks++) {
        uint32_t a[4][4];
        #pragma unroll
        for (int mt = 0; mt < 4; mt++)
            ldsm_x4(a[mt][0], a[mt][1], a[mt][2], a[mt][3],
                    smem_u32(&As[wm + mt * 16 + arow][ks * 16 + acol]));
        uint32_t b[4][2];
        #pragma unroll
        for (int nt2 = 0; nt2 < 2; nt2++) {
            uint32_t r0, r1, r2, r3;
            ldsm_x4_t(r0, r1, r2, r3,
                      smem_u32(&Bs[ks * 16 + bk][wn + nt2 * 16 + bn]));
            b[2 * nt2][0] = r0; b[2 * nt2][1] = r1;
            b[2 * nt2 + 1][0] = r2; b[2 * nt2 + 1][1] = r3;
        }
        #pragma unroll
        for (int mt = 0; mt < 4; mt++)
            #pragma unroll
            for (int nt = 0; nt < 4; nt++)
                mma_bf16(acc[mt][nt][0], acc[mt][nt][1], acc[mt][nt][2], acc[mt][nt][3],
                         a[mt][0], a[mt][1], a[mt][2], a[mt][3],
                         b[nt][0], b[nt][1]);
    }

    const int bb = rowBase >> 11;
    const int tb = rowBase & 2047;
    #pragma unroll
    for (int cc = 0; cc < 4; cc++) {
        __syncthreads();
        if (wn == cc * 32) {
            #pragma unroll
            for (int mt = 0; mt < 4; mt++)
                #pragma unroll
                for (int nt = 0; nt < 4; nt++) {
                    int c = nt * 8 + (lane & 3) * 2;
                    int col = colBase + wn + c;
                    #pragma unroll
                    for (int h = 0; h < 2; h++) {
                        int r = wm + mt * 16 + (lane >> 2) + h * 8;
                        sbuf[c][r]     = softplus_f(acc[mt][nt][2 * h]     + bias[col]);
                        sbuf[c + 1][r] = softplus_f(acc[mt][nt][2 * h + 1] + bias[col + 1]);
                    }
                }
        }
        __syncthreads();
        // paired bf16 store: thread j -> dtT[e=colBase+cc*32+c][tb + 2r..2r+1]
        for (int j = tid; j < 32 * 64; j += 256) {
            int c = j >> 6, r = (j & 63) * 2;
            bf16 o[2] = {__float2bfloat16(sbuf[c][r]), __float2bfloat16(sbuf[c][r + 1])};
            *(uint32_t*)&dtT[((size_t)bb * EDIM + colBase + cc * 32 + c) * LSEQ + tb + r]
                = *(uint32_t*)o;
        }
    }
}

// ---------------- fused conv+silu+transposes (32x64 tile, bf16 xsT/zT out) ----------------
__global__ void __launch_bounds__(256)
conv_fused_kernel(const bf16* __restrict__ xzb,
                  const float* __restrict__ conv_w,
                  const float* __restrict__ conv_b,
                  bf16* __restrict__ xsb,
                  bf16* __restrict__ xsT,
                  bf16* __restrict__ zT) {
    __shared__ __align__(8) float xt[35][66];
    __shared__ __align__(8) float st[32][66];
    __shared__ bf16  zt[32][66];

    const int e0 = blockIdx.x * 64;
    const int t0 = blockIdx.y * 32;
    const int b  = blockIdx.z;
    const int tx = threadIdx.x & 31, ty = threadIdx.x >> 5;

    for (int i = ty; i < 35; i += 8) {
        int t = t0 - 3 + i;
        uint32_t pv = 0;
        if (t >= 0)
            pv = *(const uint32_t*)&xzb[((size_t)(b * LSEQ + t)) * (2 * EDIM) + e0 + 2 * tx];
        bf16 p[2]; *(uint32_t*)p = pv;
        *(float2*)&xt[i][2 * tx] = make_float2(__bfloat162float(p[0]), __bfloat162float(p[1]));
    }
    for (int i = ty; i < 32; i += 8) {
        uint32_t pv = *(const uint32_t*)&xzb[((size_t)(b * LSEQ + t0 + i)) * (2 * EDIM) + EDIM + e0 + 2 * tx];
        *(uint32_t*)&zt[i][2 * tx] = pv;
    }
    __syncthreads();

    const int ea = e0 + 2 * tx, ebx = ea + 1;
    const float w0a = conv_w[ea * 4 + 0], w1a = conv_w[ea * 4 + 1],
                w2a = conv_w[ea * 4 + 2], w3a = conv_w[ea * 4 + 3], bba = conv_b[ea];
    const float w0b = conv_w[ebx * 4 + 0], w1b = conv_w[ebx * 4 + 1],
                w2b = conv_w[ebx * 4 + 2], w3b = conv_w[ebx * 4 + 3], bbb = conv_b[ebx];

    for (int i = ty; i < 32; i += 8) {
        float2 v0 = *(const float2*)&xt[i][2 * tx];
        float2 v1 = *(const float2*)&xt[i + 1][2 * tx];
        float2 v2 = *(const float2*)&xt[i + 2][2 * tx];
        float2 v3 = *(const float2*)&xt[i + 3][2 * tx];
        float a0 = bba + w0a * v0.x + w1a * v1.x + w2a * v2.x + w3a * v3.x;
        float a1 = bbb + w0b * v0.y + w1b * v1.y + w2b * v2.y + w3b * v3.y;
        float s0 = a0 / (1.0f + __expf(-a0));
        float s1 = a1 / (1.0f + __expf(-a1));
        *(float2*)&st[i][2 * tx] = make_float2(s0, s1);
        bf16 o[2] = {__float2bfloat16(s0), __float2bfloat16(s1)};
        *(uint32_t*)&xsb[((size_t)(b * LSEQ + t0 + i)) * EDIM + e0 + 2 * tx] = *(uint32_t*)o;
    }
    __syncthreads();

    for (int i = ty; i < 64; i += 8) {
        xsT[((size_t)b * EDIM + e0 + i) * LSEQ + t0 + tx] = __float2bfloat16(st[tx][i]);
        zT [((size_t)b * EDIM + e0 + i) * LSEQ + t0 + tx] = zt[tx][i];
    }
}

// ---------------- chunked parallel selective scan (16 warps/block, packed bf16x2) ----------------
#define CHUNK 64
#define BC_SMEM_BYTES 131072
#define NWARP_SCAN 16
#define YSTAGE_BYTES  (NWARP_SCAN * (LSEQ + 32) * 2)
#define SCAN_SMEM (BC_SMEM_BYTES + YSTAGE_BYTES)       // 197632

__device__ __forceinline__ const uint4* bc_addr(const char* bcs, int t, int c) {
    int slot = ((t & 1) * 4 + c) ^ ((t >> 6) & 7);
    return (const uint4*)(bcs + (t >> 1) * 128 + slot * 16);
}

__global__ void __launch_bounds__(NWARP_SCAN * 32)
scan_kernel(const bf16* __restrict__ dtT,
            const bf16* __restrict__ xsT,
            const bf16* __restrict__ zT,
            const bf16* __restrict__ bcb,
            const float* __restrict__ A_log,
            const float* __restrict__ D_skip,
            bf16* __restrict__ y) {
    extern __shared__ __align__(16) char dyn[];
    char* bcs = dyn;
    bf16 (*ystage)[LSEQ + 32] = (bf16 (*)[LSEQ + 32])(dyn + BC_SMEM_BYTES);

    const int b    = blockIdx.y;
    const int warp = threadIdx.x >> 5;
    const int lane = threadIdx.x & 31;
    const int e    = blockIdx.x * NWARP_SCAN + warp;

    {
        const bf16* src = bcb + (size_t)b * LSEQ * 32;
        for (int k = threadIdx.x; k < 8192; k += NWARP_SCAN * 32) {
            int t = k >> 2, c = k & 3;
            int slot = ((t & 1) * 4 + c) ^ ((t >> 6) & 7);
            cp_async16(bcs + (t >> 1) * 128 + slot * 16, src + k * 8);
        }
        cp_commit(); cp_wait<0>();
    }
    __syncthreads();

    float Acoef[NST];
    bool structured = true;
    #pragma unroll
    for (int n = 0; n < NST; n++) {
        Acoef[n] = -__expf(A_log[e * NST + n]);
        structured &= fabsf(Acoef[n] + (float)(n + 1)) < 1e-4f * (float)(n + 1);
    }
    const float dsk = D_skip[e];

    const bf16* dtp = dtT + ((size_t)b * EDIM + e) * LSEQ;
    const bf16* xsp = xsT + ((size_t)b * EDIM + e) * LSEQ;
    const bf16* zp  = zT  + ((size_t)b * EDIM + e) * LSEQ;

    const int t0 = lane * CHUNK;

    float P[NST];
    bf162 q2[8];
    #pragma unroll
    for (int n = 0; n < NST; n++) P[n] = 1.0f;
    #pragma unroll
    for (int j = 0; j < 8; j++) q2[j] = __floats2bfloat162_rn(0.0f, 0.0f);

    for (int s4 = 0; s4 < CHUNK; s4 += 4) {
        uint2 d4 = *(const uint2*)&dtp[t0 + s4];
        uint2 x4 = *(const uint2*)&xsp[t0 + s4];
        float dv[4], xv[4];
        unpack4(d4, dv);
        unpack4(x4, xv);
        #pragma unroll
        for (int u = 0; u < 4; u++) {
            const int t = t0 + s4 + u;
            bf162 Bv2[8];
            load_bf162x8(bc_addr(bcs, t, 0), bc_addr(bcs, t, 1), Bv2);
            float dA[NST];
            compute_dA(dv[u], Acoef, structured, dA);
            const bf162 dx2 = __float2bfloat162_rn(dv[u] * xv[u]);
            #pragma unroll
            for (int j = 0; j < 8; j++) {
                bf162 dA2 = __floats2bfloat162_rn(dA[2 * j], dA[2 * j + 1]);
                q2[j] = __hfma2(dA2, q2[j], __hmul2(dx2, Bv2[j]));
                P[2 * j]     *= dA[2 * j];
                P[2 * j + 1] *= dA[2 * j + 1];
            }
        }
    }

    float q[NST];
    #pragma unroll
    for (int j = 0; j < 8; j++) {
        q[2 * j]     = __low2float(q2[j]);
        q[2 * j + 1] = __high2float(q2[j]);
    }

    #pragma unroll
    for (int d = 1; d < 32; d <<= 1) {
        #pragma unroll
        for (int n = 0; n < NST; n++) {
            float Pp = __shfl_up_sync(0xffffffffu, P[n], d);
            float qp = __shfl_up_sync(0xffffffffu, q[n], d);
            if (lane >= d) {
                q[n] = fmaf(P[n], qp, q[n]);
                P[n] *= Pp;
            }
        }
    }
    bf162 h2[8];
    #pragma unroll
    for (int n = 0; n < NST; n += 2) {
        float v0 = __shfl_up_sync(0xffffffffu, q[n], 1);
        float v1 = __shfl_up_sync(0xffffffffu, q[n + 1], 1);
        if (lane == 0) { v0 = 0.0f; v1 = 0.0f; }
        h2[n >> 1] = __floats2bfloat162_rn(v0, v1);
    }

    for (int s8 = 0; s8 < CHUNK; s8 += 8) {
        uint4 d8 = *(const uint4*)&dtp[t0 + s8];
        uint4 x8 = *(const uint4*)&xsp[t0 + s8];
        uint4 z8 = *(const uint4*)&zp[t0 + s8];
        float dv[8], xv[8], zv[8];
        unpack8(d8, dv);
        unpack8(x8, xv);
        unpack8(z8, zv);
        #pragma unroll
        for (int u = 0; u < 8; u++) {
            const int t = t0 + s8 + u;
            bf162 Bv2[8], Cv2[8];
            load_bf162x8(bc_addr(bcs, t, 0), bc_addr(bcs, t, 1), Bv2);
            load_bf162x8(bc_addr(bcs, t, 2), bc_addr(bcs, t, 3), Cv2);
            float dA[NST];
            compute_dA(dv[u], Acoef, structured, dA);
            const bf162 dx2 = __float2bfloat162_rn(dv[u] * xv[u]);
            bf162 yac = __floats2bfloat162_rn(0.0f, 0.0f);
            #pragma unroll
            for (int j = 0; j < 8; j++) {
                bf162 dA2 = __floats2bfloat162_rn(dA[2 * j], dA[2 * j + 1]);
                h2[j] = __hfma2(dA2, h2[j], __hmul2(dx2, Bv2[j]));
                yac = __hfma2(h2[j], Cv2[j], yac);
            }
            const float yacc = __low2float(yac) + __high2float(yac);
            const float zz  = zv[u];
            const float sig = 1.0f / (1.0f + __expf(-zz));
            const float out = (yacc + xv[u] * dsk) * (zz * sig);
            ystage[warp][t + (t >> 6)] = __float2bfloat16(out);
        }
    }
    __syncthreads();

    const int e0 = blockIdx.x * NWARP_SCAN;
    for (int t = threadIdx.x; t < LSEQ; t += NWARP_SCAN * 32) {
        bf16 v[NWARP_SCAN];
        #pragma unroll
        for (int w = 0; w < NWARP_SCAN; w++) v[w] = ystage[w][t + (t >> 6)];
        *(uint4*)&y[((size_t)(b * LSEQ + t)) * EDIM + e0]     = ((uint4*)v)[0];
        *(uint4*)&y[((size_t)(b * LSEQ + t)) * EDIM + e0 + 8] = ((uint4*)v)[1];
    }
}

// ---------------- launcher ----------------
extern "C" void kernel_launch(void* const* d_in, const int* in_sizes, int n_in,
                              void* d_out, int out_size) {
    const float* hidden = (const float*)d_in[0];
    const float* norm_w = (const float*)d_in[1];
    const float* W_in   = (const float*)d_in[2];
    const float* conv_w = (const float*)d_in[3];
    const float* conv_b = (const float*)d_in[4];
    const float* W_x    = (const float*)d_in[5];
    const float* W_dt   = (const float*)d_in[6];
    const float* b_dt   = (const float*)d_in[7];
    const float* A_log  = (const float*)d_in[8];
    const float* D_skip = (const float*)d_in[9];
    const float* W_out  = (const float*)d_in[10];
    float* out = (float*)d_out;

    bf16 *p_xzb, *p_dtT, *p_xsT, *p_zT, *p_nrmb, *p_xsb, *p_dblb, *p_bcb, *p_yb;
    bf16 *p_winb, *p_wxb, *p_wdtb, *p_woutb;
    cudaGetSymbolAddress((void**)&p_xzb,  g_xzb);
    cudaGetSymbolAddress((void**)&p_dtT,  g_dtT);
    cudaGetSymbolAddress((void**)&p_xsT,  g_xsT);
    cudaGetSymbolAddress((void**)&p_zT,   g_zT);
    cudaGetSymbolAddress((void**)&p_nrmb, g_nrmb);
    cudaGetSymbolAddress((void**)&p_xsb,  g_xsb);
    cudaGetSymbolAddress((void**)&p_dblb, g_dblb);
    cudaGetSymbolAddress((void**)&p_bcb,  g_bcb);
    cudaGetSymbolAddress((void**)&p_yb,   g_yb);
    cudaGetSymbolAddress((void**)&p_winb, g_winb);
    cudaGetSymbolAddress((void**)&p_wxb,  g_wxb);
    cudaGetSymbolAddress((void**)&p_wdtb, g_wdtb);
    cudaGetSymbolAddress((void**)&p_woutb, g_woutb);

    cudaFuncSetAttribute(scan_kernel, cudaFuncAttributeMaxDynamicSharedMemorySize, SCAN_SMEM);
    cudaFuncSetAttribute(gemm_bf16<128, 128, 2, 4, 5>,
                         cudaFuncAttributeMaxDynamicSharedMemorySize, GEMM_BIG_SMEM);
    cudaFuncSetAttribute(gemm_bf16<128, 128, 2, 4, 2>,
                         cudaFuncAttributeMaxDynamicSharedMemorySize, GEMM_BIG_SMEM);
    cudaFuncSetAttribute(gemm_bf16<64, 64, 4, 2, 6>,
                         cudaFuncAttributeMaxDynamicSharedMemorySize, GEMM_DBL_SMEM);

    // 0) fused weight conversion
    {
        int total = (N_WIN + N_WX + N_WDT + N_WOUT) / 4;
        wconv_kernel<<<(total + 255) / 256, 256>>>(W_in, p_winb, W_x, p_wxb,
                                                   W_dt, p_wdtb, W_out, p_woutb);
    }

    // 1) RMSNorm -> bf16
    rmsnorm_kernel<<<NTOK, 128>>>(hidden, norm_w, p_nrmb);

    // 2) xz = nrm @ W_in -> bf16 only
    gemm_bf16<128, 128, 2, 4, 5><<<dim3(2 * EDIM / 128, NTOK / 128), 256, GEMM_BIG_SMEM>>>(
        p_nrmb, DDIM, p_winb, 2 * EDIM, nullptr, 2 * EDIM,
        NTOK, 2 * EDIM, DDIM, nullptr, p_xzb, nullptr);

    // 3) fused conv + silu + transposes (bf16 xsT)
    conv_fused_kernel<<<dim3(EDIM / 64, LSEQ / 32, BSZ), 256>>>(
        p_xzb, conv_w, conv_b, p_xsb, p_xsT, p_zT);

    // 4) dbl = xs @ W_x -> bf16 full + bf16 compact BC
    gemm_bf16<64, 64, 4, 2, 6><<<dim3(1, NTOK / 64), 256, GEMM_DBL_SMEM>>>(
        p_xsb, EDIM, p_wxb, 64, nullptr, 64,
        NTOK, 64, EDIM, nullptr, p_dblb, p_bcb);

    // 5) dtT = softplus(dbl[:, :32] @ W_dt + b_dt) -> bf16 transposed
    dtgemm_kernel<<<dim3(EDIM / 128, NTOK / 128), 256>>>(p_dblb, p_wdtb, b_dt, p_dtT);

    // 6) chunked parallel scan (16 warps/block, all-bf16 inputs) -> bf16 y
    scan_kernel<<<dim3(EDIM / NWARP_SCAN, BSZ), NWARP_SCAN * 32, SCAN_SMEM>>>(
        p_dtT, p_xsT, p_zT, p_bcb, A_log, D_skip, p_yb);

    // 7) out = y @ W_out + hidden -> fp32
    gemm_bf16<128, 128, 2, 4, 2><<<dim3(DDIM / 128, NTOK / 128), 256, GEMM_BIG_SMEM>>>(
        p_yb, EDIM, p_woutb, DDIM, out, DDIM,
        NTOK, DDIM, EDIM, hidden, nullptr, nullptr);
}